// round 3
// baseline (speedup 1.0000x reference)
#include <cuda_runtime.h>
#include <math.h>

#define DIMC 1024
#define TT   4096
#define BBAT 2
#define HH   8
#define DHH  128
#define BHC  16
#define TOK  8192
#define NHSH 4
#define NBKT 64
#define NCHK 256
#define FFD  4096

// ------------------------- scratch (device globals, no allocs) -------------
__device__ float g_x1[TOK * DIMC];
__device__ float g_x2[TOK * DIMC];
__device__ float g_xn[TOK * DIMC];
__device__ float g_qk[TOK * DIMC];
__device__ float g_v[TOK * DIMC];
__device__ float g_attn[TOK * DIMC];
__device__ float g_ff[TOK * FFD];
__device__ float g_so[BHC * NHSH * TT * DHH];
__device__ float g_slog[BHC * NHSH * TT];
__device__ int g_st[BHC * NHSH * TT];
__device__ int g_undo[BHC * NHSH * TT];
__device__ unsigned char g_bucket[BHC * NHSH * TT];

// ------------------------- init: x1 = x2 = x ------------------------------
__global__ void init_xx(const float* __restrict__ x) {
    int i = blockIdx.x * blockDim.x + threadIdx.x;
    float4 v = ((const float4*)x)[i];
    ((float4*)g_x1)[i] = v;
    ((float4*)g_x2)[i] = v;
}

// ------------------------- layernorm --------------------------------------
__global__ void ln_kernel(const float* __restrict__ in, const float* __restrict__ g,
                          const float* __restrict__ b, float* __restrict__ out) {
    int row = blockIdx.x;
    int tid = threadIdx.x;
    const float* p = in + (size_t)row * DIMC;
    float v[4];
    float s = 0.f, sq = 0.f;
#pragma unroll
    for (int j = 0; j < 4; j++) {
        float x = p[tid + j * 256];
        v[j] = x;
        s += x;
        sq += x * x;
    }
#pragma unroll
    for (int o = 16; o; o >>= 1) {
        s += __shfl_xor_sync(~0u, s, o);
        sq += __shfl_xor_sync(~0u, sq, o);
    }
    __shared__ float rs[8], rq[8];
    if ((tid & 31) == 0) { rs[tid >> 5] = s; rq[tid >> 5] = sq; }
    __syncthreads();
    float S = 0.f, Q = 0.f;
#pragma unroll
    for (int w = 0; w < 8; w++) { S += rs[w]; Q += rq[w]; }
    float mean = S * (1.0f / DIMC);
    float var = Q * (1.0f / DIMC) - mean * mean;
    float inv = rsqrtf(var + 1e-5f);
#pragma unroll
    for (int j = 0; j < 4; j++) {
        int c = tid + j * 256;
        out[(size_t)row * DIMC + c] = (v[j] - mean) * inv * g[c] + b[c];
    }
}

// ------------------------- SGEMM 128x128x16, 8x8 per thread ---------------
// FLAGS: 1 = +bias[col], 2 = +res[row,col], 4 = exact gelu (after bias, before res)
template <int FLAGS>
__global__ void __launch_bounds__(256) sgemm(const float* __restrict__ A,
                                             const float* __restrict__ Bm,
                                             float* C,
                                             const float* __restrict__ bias,
                                             const float* res, int N, int K) {
    __shared__ float As[16 * 128];
    __shared__ float Bs[16 * 128];
    int tid = threadIdx.x;
    int bx = blockIdx.x, by = blockIdx.y;
    int ttx = tid & 15, tty = tid >> 4;
    float acc[8][8];
#pragma unroll
    for (int i = 0; i < 8; i++)
#pragma unroll
        for (int j = 0; j < 8; j++) acc[i][j] = 0.f;

    const float* Ab = A + (size_t)(by * 128) * K;
    const float* Bb = Bm + bx * 128;
    int nk = K >> 4;
    for (int kt = 0; kt < nk; kt++) {
#pragma unroll
        for (int l = 0; l < 2; l++) {
            int idx = tid + l * 256;
            int row = idx >> 2, c4 = idx & 3;
            float4 a = *(const float4*)(Ab + (size_t)row * K + kt * 16 + c4 * 4);
            As[(c4 * 4 + 0) * 128 + row] = a.x;
            As[(c4 * 4 + 1) * 128 + row] = a.y;
            As[(c4 * 4 + 2) * 128 + row] = a.z;
            As[(c4 * 4 + 3) * 128 + row] = a.w;
            int r2 = idx >> 5, cc = idx & 31;
            float4 bv = *(const float4*)(Bb + (size_t)(kt * 16 + r2) * N + cc * 4);
            *(float4*)(Bs + r2 * 128 + cc * 4) = bv;
        }
        __syncthreads();
#pragma unroll
        for (int k = 0; k < 16; k++) {
            float af[8], bf[8];
            *(float4*)af = *(float4*)(As + k * 128 + tty * 8);
            *(float4*)(af + 4) = *(float4*)(As + k * 128 + tty * 8 + 4);
            *(float4*)bf = *(float4*)(Bs + k * 128 + ttx * 8);
            *(float4*)(bf + 4) = *(float4*)(Bs + k * 128 + ttx * 8 + 4);
#pragma unroll
            for (int i = 0; i < 8; i++)
#pragma unroll
                for (int j = 0; j < 8; j++) acc[i][j] = fmaf(af[i], bf[j], acc[i][j]);
        }
        __syncthreads();
    }
#pragma unroll
    for (int i = 0; i < 8; i++) {
        int gr = by * 128 + tty * 8 + i;
#pragma unroll
        for (int j = 0; j < 8; j++) {
            int gc = bx * 128 + ttx * 8 + j;
            float vv = acc[i][j];
            if (FLAGS & 1) vv += bias[gc];
            if (FLAGS & 4) vv = 0.5f * vv * (1.0f + erff(vv * 0.70710678118654752f));
            if (FLAGS & 2) vv += res[(size_t)gr * N + gc];
            C[(size_t)gr * N + gc] = vv;
        }
    }
}

// ------------------------- LSH hashing ------------------------------------
__global__ void hash_kernel(const float* __restrict__ qk, const float* __restrict__ rot,
                            unsigned char* __restrict__ bucket) {
    __shared__ float srow[8][128];
    int warp = threadIdx.x >> 5, lane = threadIdx.x & 31;
    int rid = blockIdx.x * 8 + warp;  // bh*T + t
    int bh = rid >> 12, t = rid & 4095;
    int b = bh >> 3, h = bh & 7;
    const float* qp = qk + ((size_t)(b * TT + t)) * DIMC + h * DHH;
#pragma unroll
    for (int j = 0; j < 4; j++) srow[warp][lane + j * 32] = qp[lane + j * 32];
    __syncwarp();
#pragma unroll
    for (int hh = 0; hh < 4; hh++) {
        float acc = 0.f;
#pragma unroll 8
        for (int f = 0; f < 128; f++)
            acc = fmaf(srow[warp][f], rot[f * 128 + hh * 32 + lane], acc);
        float val = fmaxf(acc, -acc);
        int idx = (acc >= -acc) ? lane : 32 + lane;  // first-max tie rule
#pragma unroll
        for (int o = 16; o; o >>= 1) {
            float ov = __shfl_down_sync(~0u, val, o);
            int oi = __shfl_down_sync(~0u, idx, o);
            if (ov > val || (ov == val && oi < idx)) { val = ov; idx = oi; }
        }
        if (lane == 0) bucket[((size_t)bh * 4 + hh) * TT + t] = (unsigned char)idx;
    }
}

// ------------------------- stable counting sort per (bh, hash) ------------
__global__ void sort_kernel(const unsigned char* __restrict__ bucket,
                            int* __restrict__ st, int* __restrict__ undo) {
    __shared__ unsigned char sb[4096];
    __shared__ unsigned short hist[64 * 257];
    __shared__ int base[65];
    __shared__ int tot[64];
    int blk = blockIdx.x;  // bh*4 + r
    int tid = threadIdx.x;
    const unsigned char* bp = bucket + (size_t)blk * TT;
    for (int i = tid; i < 4096; i += 256) sb[i] = bp[i];
    for (int i = tid; i < 64 * 257; i += 256) hist[i] = 0;
    __syncthreads();
#pragma unroll
    for (int j = 0; j < 16; j++) {
        int t = tid * 16 + j;
        int b = sb[t];
        hist[b * 257 + tid]++;
    }
    __syncthreads();
    if (tid < 64) {
        unsigned int run = 0;
        int b = tid;
        for (int th = 0; th < 256; th++) {
            unsigned short tmp = hist[b * 257 + th];
            hist[b * 257 + th] = (unsigned short)run;
            run += tmp;
        }
        tot[b] = (int)run;
    }
    __syncthreads();
    if (tid == 0) {
        base[0] = 0;
        for (int b = 0; b < 64; b++) base[b + 1] = base[b] + tot[b];
    }
    __syncthreads();
#pragma unroll
    for (int j = 0; j < 16; j++) {
        int t = tid * 16 + j;
        int b = sb[t];
        int pos = base[b] + hist[b * 257 + tid];
        hist[b * 257 + tid]++;
        st[(size_t)blk * TT + pos] = t;
        undo[(size_t)blk * TT + t] = pos;
    }
}

// ------------------------- chunked LSH attention ---------------------------
// one block per (bh, chunk): 64 queries x 128 keys (chunk + prev chunk)
#define ATTN_SMEM ((128 * 133 + 64 * 132 + 128) * 4 + 128 * 4)
__global__ void __launch_bounds__(256) attn_kernel(const float* __restrict__ qk,
                                                   const float* __restrict__ v,
                                                   const int* __restrict__ st,
                                                   float* __restrict__ so,
                                                   float* __restrict__ slog) {
    extern __shared__ float sm[];
    float* s_k = sm;                    // 128 x 133 raw key/query rows
    float* s_p = s_k + 128 * 133;       // 64 x 132 dots -> probs
    float* s_rn = s_p + 64 * 132;       // 128 inverse norms
    int* s_pk = (int*)(s_rn + 128);     // 128 positions (first 64 = queries)
    int tid = threadIdx.x;
    int bh = blockIdx.x >> 8;
    int c = blockIdx.x & 255;
    int prev = (c + 255) & 255;
    int b = bh >> 3, h = bh & 7;
    const int* stb = st + (size_t)bh * (NHSH * TT);
    if (tid < 64) s_pk[tid] = stb[c * 64 + tid];
    else if (tid < 128) s_pk[tid] = stb[prev * 64 + (tid - 64)];
    __syncthreads();
#pragma unroll
    for (int rep = 0; rep < 16; rep++) {
        int idx = tid + rep * 256;
        int j = idx >> 5, d4 = idx & 31;
        const float* kp = qk + ((size_t)(b * TT + s_pk[j])) * DIMC + h * DHH + d4 * 4;
        float4 kv = *(const float4*)kp;
        float* dst = s_k + j * 133 + d4 * 4;
        dst[0] = kv.x; dst[1] = kv.y; dst[2] = kv.z; dst[3] = kv.w;
    }
    __syncthreads();
    if (tid < 128) {
        float sq = 0.f;
#pragma unroll 8
        for (int d = 0; d < 128; d++) {
            float x = s_k[tid * 133 + d];
            sq += x * x;
        }
        float nrm = sqrtf(sq);
        s_rn[tid] = 1.0f / fmaxf(nrm, 1e-12f);
    }
    __syncthreads();
    int lane = tid & 31, w = tid >> 5;
    const float SC = 0.08838834764831845f;  // 1/sqrt(128)
    // dots: each warp owns 8 query rows, processed in pairs
    for (int p2 = 0; p2 < 4; p2++) {
        int i0 = w * 8 + p2 * 2;
        float acc0[4] = {0, 0, 0, 0}, acc1[4] = {0, 0, 0, 0};
        const float* k0 = s_k + i0 * 133;
        const float* k1 = s_k + (i0 + 1) * 133;
        for (int d = 0; d < 128; d++) {
            float q0 = k0[d], q1 = k1[d];
#pragma unroll
            for (int cc = 0; cc < 4; cc++) {
                float kv = s_k[(lane + 32 * cc) * 133 + d];
                acc0[cc] = fmaf(q0, kv, acc0[cc]);
                acc1[cc] = fmaf(q1, kv, acc1[cc]);
            }
        }
        int pq0 = s_pk[i0], pq1 = s_pk[i0 + 1];
#pragma unroll
        for (int cc = 0; cc < 4; cc++) {
            int j = lane + 32 * cc;
            float rn = s_rn[j];
            int pkj = s_pk[j];
            s_p[i0 * 132 + j] = (pq0 == pkj) ? -5e4f : acc0[cc] * rn * SC;
            s_p[(i0 + 1) * 132 + j] = (pq1 == pkj) ? -5e4f : acc1[cc] * rn * SC;
        }
    }
    __syncthreads();
    // softmax per query row; store lse
    for (int rr = 0; rr < 8; rr++) {
        int i = w * 8 + rr;
        float vv[4];
#pragma unroll
        for (int cc = 0; cc < 4; cc++) vv[cc] = s_p[i * 132 + lane + 32 * cc];
        float m = fmaxf(fmaxf(vv[0], vv[1]), fmaxf(vv[2], vv[3]));
#pragma unroll
        for (int o = 16; o; o >>= 1) m = fmaxf(m, __shfl_xor_sync(~0u, m, o));
        float sum = 0.f;
#pragma unroll
        for (int cc = 0; cc < 4; cc++) {
            vv[cc] = expf(vv[cc] - m);
            sum += vv[cc];
        }
#pragma unroll
        for (int o = 16; o; o >>= 1) sum += __shfl_xor_sync(~0u, sum, o);
        float lse = m + logf(sum);
        float isum = 1.0f / sum;
#pragma unroll
        for (int cc = 0; cc < 4; cc++) s_p[i * 132 + lane + 32 * cc] = vv[cc] * isum;
        if (lane == 0) slog[(size_t)bh * (NHSH * TT) + c * 64 + i] = lse;
    }
    __syncthreads();
    // PV: thread (w, lane) owns queries w+8*ii, dims lane+32*dd
    float acc[8][4];
#pragma unroll
    for (int ii = 0; ii < 8; ii++)
#pragma unroll
        for (int dd = 0; dd < 4; dd++) acc[ii][dd] = 0.f;
    for (int j = 0; j < 128; j++) {
        const float* vp = v + ((size_t)(b * TT + s_pk[j])) * DIMC + h * DHH;
        float v0 = vp[lane], v1 = vp[lane + 32], v2 = vp[lane + 64], v3 = vp[lane + 96];
#pragma unroll
        for (int ii = 0; ii < 8; ii++) {
            float pij = s_p[(w + 8 * ii) * 132 + j];
            acc[ii][0] = fmaf(pij, v0, acc[ii][0]);
            acc[ii][1] = fmaf(pij, v1, acc[ii][1]);
            acc[ii][2] = fmaf(pij, v2, acc[ii][2]);
            acc[ii][3] = fmaf(pij, v3, acc[ii][3]);
        }
    }
#pragma unroll
    for (int ii = 0; ii < 8; ii++) {
        size_t base = ((size_t)bh * (NHSH * TT) + c * 64 + w + 8 * ii) * 128;
        so[base + lane] = acc[ii][0];
        so[base + lane + 32] = acc[ii][1];
        so[base + lane + 64] = acc[ii][2];
        so[base + lane + 96] = acc[ii][3];
    }
}

// ------------------------- combine hash rounds ----------------------------
__global__ void combine_kernel(const float* __restrict__ so, const float* __restrict__ slog,
                               const int* __restrict__ undo, float* __restrict__ attn) {
    int warp = threadIdx.x >> 5, lane = threadIdx.x & 31;
    int rid = blockIdx.x * 8 + warp;  // bh*T + t
    int bh = rid >> 12, t = rid & 4095;
    int b = bh >> 3, h = bh & 7;
    int u[4];
    float lg[4];
#pragma unroll
    for (int r = 0; r < 4; r++) {
        u[r] = undo[((size_t)bh * 4 + r) * TT + t];
        lg[r] = slog[(size_t)bh * (NHSH * TT) + r * TT + u[r]];
    }
    float m = fmaxf(fmaxf(lg[0], lg[1]), fmaxf(lg[2], lg[3]));
    float e[4];
    float s = 0.f;
#pragma unroll
    for (int r = 0; r < 4; r++) {
        e[r] = expf(lg[r] - m);
        s += e[r];
    }
    float is = 1.0f / s;
    float a0 = 0, a1 = 0, a2 = 0, a3 = 0;
#pragma unroll
    for (int r = 0; r < 4; r++) {
        const float* op = so + ((size_t)bh * (NHSH * TT) + r * TT + u[r]) * 128;
        float pr = e[r] * is;
        a0 = fmaf(pr, op[lane], a0);
        a1 = fmaf(pr, op[lane + 32], a1);
        a2 = fmaf(pr, op[lane + 64], a2);
        a3 = fmaf(pr, op[lane + 96], a3);
    }
    float* dst = attn + ((size_t)(b * TT + t)) * DIMC + h * DHH;
    dst[lane] = a0;
    dst[lane + 32] = a1;
    dst[lane + 64] = a2;
    dst[lane + 96] = a3;
}

// ------------------------- final y1 + y2 ----------------------------------
__global__ void add_out(float* __restrict__ out) {
    int i = blockIdx.x * blockDim.x + threadIdx.x;
    float4 a = ((float4*)g_x1)[i];
    float4 b = ((float4*)g_x2)[i];
    float4 o;
    o.x = a.x + b.x; o.y = a.y + b.y; o.z = a.z + b.z; o.w = a.w + b.w;
    ((float4*)out)[i] = o;
}

// ------------------------- launch -----------------------------------------
extern "C" void kernel_launch(void* const* d_in, const int* in_sizes, int n_in,
                              void* d_out, int out_size) {
    const float* x = (const float*)d_in[0];
    const float* ln1g = (const float*)d_in[1];
    const float* ln1b = (const float*)d_in[2];
    const float* Wqk = (const float*)d_in[3];
    const float* Wv = (const float*)d_in[4];
    const float* Wo = (const float*)d_in[5];
    const float* bo = (const float*)d_in[6];
    const float* ln2g = (const float*)d_in[7];
    const float* ln2b = (const float*)d_in[8];
    const float* W1 = (const float*)d_in[9];
    const float* b1 = (const float*)d_in[10];
    const float* W2 = (const float*)d_in[11];
    const float* b2 = (const float*)d_in[12];
    const float* rot = (const float*)d_in[13];

    float *px1, *px2, *pxn, *pqk, *pv, *pattn, *pff, *pso, *pslog;
    int *pst, *pundo;
    unsigned char* pbkt;
    cudaGetSymbolAddress((void**)&px1, g_x1);
    cudaGetSymbolAddress((void**)&px2, g_x2);
    cudaGetSymbolAddress((void**)&pxn, g_xn);
    cudaGetSymbolAddress((void**)&pqk, g_qk);
    cudaGetSymbolAddress((void**)&pv, g_v);
    cudaGetSymbolAddress((void**)&pattn, g_attn);
    cudaGetSymbolAddress((void**)&pff, g_ff);
    cudaGetSymbolAddress((void**)&pso, g_so);
    cudaGetSymbolAddress((void**)&pslog, g_slog);
    cudaGetSymbolAddress((void**)&pst, g_st);
    cudaGetSymbolAddress((void**)&pundo, g_undo);
    cudaGetSymbolAddress((void**)&pbkt, g_bucket);

    cudaFuncSetAttribute(attn_kernel, cudaFuncAttributeMaxDynamicSharedMemorySize, ATTN_SMEM);

    init_xx<<<TOK * DIMC / 4 / 256, 256>>>(x);

    for (int L = 0; L < 2; L++) {
        const float* wqk = Wqk + (size_t)L * DIMC * DIMC;
        const float* wv = Wv + (size_t)L * DIMC * DIMC;
        const float* wo = Wo + (size_t)L * DIMC * DIMC;
        const float* w1 = W1 + (size_t)L * DIMC * FFD;
        const float* w2 = W2 + (size_t)L * FFD * DIMC;
        const float* rl = rot + (size_t)L * DHH * NHSH * (NBKT / 2);

        ln_kernel<<<TOK, 256>>>(px2, ln1g + L * DIMC, ln1b + L * DIMC, pxn);
        sgemm<0><<<dim3(8, 64), 256>>>(pxn, wqk, pqk, nullptr, nullptr, 1024, 1024);
        sgemm<0><<<dim3(8, 64), 256>>>(pxn, wv, pv, nullptr, nullptr, 1024, 1024);
        hash_kernel<<<TOK, 256>>>(pqk, rl, pbkt);
        sort_kernel<<<64, 256>>>(pbkt, pst, pundo);
        attn_kernel<<<BHC * NCHK, 256, ATTN_SMEM>>>(pqk, pv, pst, pso, pslog);
        combine_kernel<<<TOK, 256>>>(pso, pslog, pundo, pattn);
        sgemm<3><<<dim3(8, 64), 256>>>(pattn, wo, px1, bo + L * DIMC, px1, 1024, 1024);
        ln_kernel<<<TOK, 256>>>(px1, ln2g + L * DIMC, ln2b + L * DIMC, pxn);
        sgemm<5><<<dim3(32, 64), 256>>>(pxn, w1, pff, b1 + L * FFD, nullptr, 4096, 1024);
        sgemm<3><<<dim3(8, 64), 256>>>(pff, w2, px2, b2 + L * DIMC, px2, 1024, 4096);
    }

    add_out<<<TOK * DIMC / 4 / 256, 256>>>((float*)d_out);
}

// round 7
// speedup vs baseline: 1.9369x; 1.9369x over previous
#include <cuda_runtime.h>
#include <cuda_bf16.h>
#include <math.h>
#include <stdint.h>

#define DIMC 1024
#define TT   4096
#define BBAT 2
#define HH   8
#define DHH  128
#define BHC  16
#define TOK  8192
#define NHSH 4
#define NBKT 64
#define NCHK 256
#define FFD  4096

// ------------------------- scratch (device globals, no allocs) -------------
__device__ float g_x1[TOK * DIMC];
__device__ float g_x2[TOK * DIMC];
__device__ float g_xn[TOK * DIMC];
__device__ float g_qk[TOK * DIMC];
__device__ float g_v[TOK * DIMC];
__device__ float g_attn[TOK * DIMC];
__device__ float g_ff[TOK * FFD];
__device__ float g_so[BHC * NHSH * TT * DHH];
__device__ float g_slog[BHC * NHSH * TT];
__device__ int g_st[BHC * NHSH * TT];
__device__ int g_undo[BHC * NHSH * TT];
__device__ unsigned char g_bucket[BHC * NHSH * TT];
// split-bf16 operand buffers (uint4 for 16B alignment)
__device__ uint4 g_A3[(size_t)TOK * 3 * FFD * 2 / 16];
__device__ uint4 g_B3[(size_t)FFD * 3 * DIMC * 2 / 16];

// ------------------------- helpers ----------------------------------------
__device__ __forceinline__ uint32_t smem_u32(const void* p) {
    uint32_t a;
    asm("{ .reg .u64 t; cvta.to.shared.u64 t, %1; cvt.u32.u64 %0, t; }" : "=r"(a) : "l"(p));
    return a;
}
__device__ __forceinline__ uint32_t swz128(uint32_t off) { return off ^ ((off >> 3) & 0x70); }

__device__ __forceinline__ void cp_async16(uint32_t so, const void* g) {
    asm volatile("cp.async.cg.shared.global [%0], [%1], 16;" :: "r"(so), "l"(g));
}
__device__ __forceinline__ void ldm_x4(uint32_t& r0, uint32_t& r1, uint32_t& r2, uint32_t& r3,
                                       uint32_t a) {
    asm volatile("ldmatrix.sync.aligned.m8n8.x4.shared.b16 {%0,%1,%2,%3}, [%4];"
                 : "=r"(r0), "=r"(r1), "=r"(r2), "=r"(r3) : "r"(a));
}
__device__ __forceinline__ void mma16816(float* c, uint32_t a0, uint32_t a1, uint32_t a2,
                                         uint32_t a3, uint32_t b0, uint32_t b1) {
    asm volatile(
        "mma.sync.aligned.m16n8k16.row.col.f32.bf16.bf16.f32 "
        "{%0,%1,%2,%3}, {%4,%5,%6,%7}, {%8,%9}, {%0,%1,%2,%3};"
        : "+f"(c[0]), "+f"(c[1]), "+f"(c[2]), "+f"(c[3])
        : "r"(a0), "r"(a1), "r"(a2), "r"(a3), "r"(b0), "r"(b1));
}

// ------------------------- init: x1 = x2 = x ------------------------------
__global__ void init_xx(const float* __restrict__ x) {
    int i = blockIdx.x * blockDim.x + threadIdx.x;
    float4 v = ((const float4*)x)[i];
    ((float4*)g_x1)[i] = v;
    ((float4*)g_x2)[i] = v;
}

// ------------------------- layernorm --------------------------------------
__global__ void ln_kernel(const float* __restrict__ in, const float* __restrict__ g,
                          const float* __restrict__ b, float* __restrict__ out) {
    int row = blockIdx.x;
    int tid = threadIdx.x;
    const float* p = in + (size_t)row * DIMC;
    float v[4];
    float s = 0.f, sq = 0.f;
#pragma unroll
    for (int j = 0; j < 4; j++) {
        float x = p[tid + j * 256];
        v[j] = x;
        s += x;
        sq += x * x;
    }
#pragma unroll
    for (int o = 16; o; o >>= 1) {
        s += __shfl_xor_sync(~0u, s, o);
        sq += __shfl_xor_sync(~0u, sq, o);
    }
    __shared__ float rs[8], rq[8];
    if ((tid & 31) == 0) { rs[tid >> 5] = s; rq[tid >> 5] = sq; }
    __syncthreads();
    float S = 0.f, Q = 0.f;
#pragma unroll
    for (int w = 0; w < 8; w++) { S += rs[w]; Q += rq[w]; }
    float mean = S * (1.0f / DIMC);
    float var = Q * (1.0f / DIMC) - mean * mean;
    float inv = rsqrtf(var + 1e-5f);
#pragma unroll
    for (int j = 0; j < 4; j++) {
        int c = tid + j * 256;
        out[(size_t)row * DIMC + c] = (v[j] - mean) * inv * g[c] + b[c];
    }
}

// ------------------------- split-bf16 conversions --------------------------
// A' [M, 3K]: [hi | hi | lo]
__global__ void convA_kernel(const float* __restrict__ X, __nv_bfloat16* __restrict__ A3, int K) {
    int lin = blockIdx.x * blockDim.x + threadIdx.x;
    int kq = K >> 2;
    int m = lin / kq;
    int k4 = (lin - m * kq) * 4;
    float4 x = *(const float4*)(X + (size_t)m * K + k4);
    size_t rb = (size_t)m * 3 * K;
    float xs[4] = {x.x, x.y, x.z, x.w};
#pragma unroll
    for (int j = 0; j < 4; j++) {
        __nv_bfloat16 h = __float2bfloat16(xs[j]);
        __nv_bfloat16 l = __float2bfloat16(xs[j] - __bfloat162float(h));
        A3[rb + k4 + j] = h;
        A3[rb + K + k4 + j] = h;
        A3[rb + 2 * K + k4 + j] = l;
    }
}

// B'^T [N, 3K] from W [K, N]: [hi | lo | hi]
__global__ void convB_kernel(const float* __restrict__ W, __nv_bfloat16* __restrict__ B3,
                             int K, int N) {
    __shared__ float s[32][33];
    int tx = threadIdx.x & 31, ty = threadIdx.x >> 5;
    int n0 = blockIdx.x * 32, k0 = blockIdx.y * 32;
#pragma unroll
    for (int j = 0; j < 4; j++)
        s[ty + 8 * j][tx] = W[(size_t)(k0 + ty + 8 * j) * N + n0 + tx];
    __syncthreads();
#pragma unroll
    for (int j = 0; j < 4; j++) {
        int r = ty + 8 * j;
        int n = n0 + r;
        int k = k0 + tx;
        float x = s[tx][r];
        __nv_bfloat16 h = __float2bfloat16(x);
        __nv_bfloat16 l = __float2bfloat16(x - __bfloat162float(h));
        size_t rb = (size_t)n * 3 * K;
        B3[rb + k] = h;
        B3[rb + K + k] = l;
        B3[rb + 2 * K + k] = h;
    }
}

// ------------------------- HMMA bf16 GEMM (mma.sync) -----------------------
// C[M,N] fp32 = A'[M,K3] x B'[N,K3]^T. Tile 128x128, BK=64, 3-stage cp.async.
// Warp layout 2x4 (each warp 64x32). FLAGS: 1=+bias, 2=+res, 4=exact gelu.
#define TG_STAGE 32768
#define TG_DSMEM (3 * TG_STAGE)

template <int FLAGS>
__global__ void __launch_bounds__(256) tgemm(const __nv_bfloat16* __restrict__ A,
                                             const __nv_bfloat16* __restrict__ B,
                                             float* __restrict__ C,
                                             const float* __restrict__ bias,
                                             const float* __restrict__ res,
                                             int N, int K3) {
    extern __shared__ char sm_[];
    int tid = threadIdx.x, lane = tid & 31, wid = tid >> 5;
    int wm = wid >> 2, wn = wid & 3;
    int bx = blockIdx.x, by = blockIdx.y;
    const char* Ag = (const char*)(A + (size_t)(by * 128) * K3);
    const char* Bg = (const char*)(B + (size_t)(bx * 128) * K3);
    size_t rs = (size_t)K3 * 2;
    int nk = K3 >> 6;
    uint32_t sbase = smem_u32(sm_);

    auto load_stage = [&](int kc, int s) {
        uint32_t sb = sbase + s * TG_STAGE;
#pragma unroll
        for (int j = 0; j < 8; j++) {
            int idx = tid + j * 256;       // 0..2047
            int half = idx >> 10;          // 0:A 1:B
            int r = (idx >> 3) & 127, seg = idx & 7;
            const char* g = (half ? Bg : Ag) + (size_t)r * rs + (size_t)kc * 128 + seg * 16;
            cp_async16(sb + half * 16384 + swz128(r * 128 + seg * 16), g);
        }
        asm volatile("cp.async.commit_group;");
    };

    float acc[4][4][4];
#pragma unroll
    for (int a = 0; a < 4; a++)
#pragma unroll
        for (int b = 0; b < 4; b++)
#pragma unroll
            for (int c = 0; c < 4; c++) acc[a][b][c] = 0.f;

    load_stage(0, 0);
    load_stage(1, 1);

    int mat = lane >> 3, rin = lane & 7;
    for (int i = 0; i < nk; i++) {
        __syncthreads();  // all warps done computing stage (i+2)%3 (iter i-1)
        if (i + 2 < nk) load_stage(i + 2, (i + 2) % 3);
        if (i + 2 < nk)       asm volatile("cp.async.wait_group 2;");
        else if (i + 1 < nk)  asm volatile("cp.async.wait_group 1;");
        else                  asm volatile("cp.async.wait_group 0;");
        __syncthreads();

        uint32_t sa = sbase + (i % 3) * TG_STAGE;
        uint32_t sb = sa + 16384;
#pragma unroll
        for (int ks = 0; ks < 4; ks++) {
            uint32_t af[4][4], bf[4][2];
#pragma unroll
            for (int mt = 0; mt < 4; mt++) {
                int row = wm * 64 + mt * 16 + (mat & 1) * 8 + rin;
                int kb = 2 * ks + (mat >> 1);
                ldm_x4(af[mt][0], af[mt][1], af[mt][2], af[mt][3],
                       sa + swz128(row * 128 + kb * 16));
            }
#pragma unroll
            for (int g = 0; g < 2; g++) {
                int nt = 2 * g + (mat >> 1);
                int n = wn * 32 + nt * 8 + rin;
                int kb = 2 * ks + (mat & 1);
                uint32_t b0, b1, b2, b3;
                ldm_x4(b0, b1, b2, b3, sb + swz128(n * 128 + kb * 16));
                bf[2 * g][0] = b0; bf[2 * g][1] = b1;
                bf[2 * g + 1][0] = b2; bf[2 * g + 1][1] = b3;
            }
#pragma unroll
            for (int mt = 0; mt < 4; mt++)
#pragma unroll
                for (int nt = 0; nt < 4; nt++)
                    mma16816(acc[mt][nt], af[mt][0], af[mt][1], af[mt][2], af[mt][3],
                             bf[nt][0], bf[nt][1]);
        }
    }

    // epilogue: direct float2 stores
#pragma unroll
    for (int mt = 0; mt < 4; mt++) {
        int gr0 = by * 128 + wm * 64 + mt * 16 + (lane >> 2);
#pragma unroll
        for (int nt = 0; nt < 4; nt++) {
            int gc = bx * 128 + wn * 32 + nt * 8 + (lane & 3) * 2;
            float v0 = acc[mt][nt][0], v1 = acc[mt][nt][1];
            float v2 = acc[mt][nt][2], v3 = acc[mt][nt][3];
            if (FLAGS & 1) {
                float b0 = bias[gc], b1 = bias[gc + 1];
                v0 += b0; v1 += b1; v2 += b0; v3 += b1;
            }
            if (FLAGS & 4) {
                v0 = 0.5f * v0 * (1.0f + erff(v0 * 0.70710678118654752f));
                v1 = 0.5f * v1 * (1.0f + erff(v1 * 0.70710678118654752f));
                v2 = 0.5f * v2 * (1.0f + erff(v2 * 0.70710678118654752f));
                v3 = 0.5f * v3 * (1.0f + erff(v3 * 0.70710678118654752f));
            }
            if (FLAGS & 2) {
                const float* r0p = res + (size_t)gr0 * N + gc;
                const float* r1p = res + (size_t)(gr0 + 8) * N + gc;
                v0 += r0p[0]; v1 += r0p[1]; v2 += r1p[0]; v3 += r1p[1];
            }
            float2 o0 = {v0, v1}, o1 = {v2, v3};
            *(float2*)(C + (size_t)gr0 * N + gc) = o0;
            *(float2*)(C + (size_t)(gr0 + 8) * N + gc) = o1;
        }
    }
}

// ------------------------- LSH hashing ------------------------------------
__global__ void hash_kernel(const float* __restrict__ qk, const float* __restrict__ rot,
                            unsigned char* __restrict__ bucket) {
    __shared__ float srow[8][128];
    int warp = threadIdx.x >> 5, lane = threadIdx.x & 31;
    int rid = blockIdx.x * 8 + warp;
    int bh = rid >> 12, t = rid & 4095;
    int b = bh >> 3, h = bh & 7;
    const float* qp = qk + ((size_t)(b * TT + t)) * DIMC + h * DHH;
#pragma unroll
    for (int j = 0; j < 4; j++) srow[warp][lane + j * 32] = qp[lane + j * 32];
    __syncwarp();
#pragma unroll
    for (int hh = 0; hh < 4; hh++) {
        float acc = 0.f;
#pragma unroll 8
        for (int f = 0; f < 128; f++)
            acc = fmaf(srow[warp][f], rot[f * 128 + hh * 32 + lane], acc);
        float val = fmaxf(acc, -acc);
        int idx = (acc >= -acc) ? lane : 32 + lane;
#pragma unroll
        for (int o = 16; o; o >>= 1) {
            float ov = __shfl_down_sync(~0u, val, o);
            int oi = __shfl_down_sync(~0u, idx, o);
            if (ov > val || (ov == val && oi < idx)) { val = ov; idx = oi; }
        }
        if (lane == 0) bucket[((size_t)bh * 4 + hh) * TT + t] = (unsigned char)idx;
    }
}

// ------------------------- stable counting sort per (bh, hash) ------------
__global__ void sort_kernel(const unsigned char* __restrict__ bucket,
                            int* __restrict__ st, int* __restrict__ undo) {
    __shared__ unsigned char sb[4096];
    __shared__ unsigned short hist[64 * 257];
    __shared__ int base[65];
    __shared__ int tot[64];
    int blk = blockIdx.x;
    int tid = threadIdx.x;
    const unsigned char* bp = bucket + (size_t)blk * TT;
    for (int i = tid; i < 4096; i += 256) sb[i] = bp[i];
    for (int i = tid; i < 64 * 257; i += 256) hist[i] = 0;
    __syncthreads();
#pragma unroll
    for (int j = 0; j < 16; j++) {
        int t = tid * 16 + j;
        int b = sb[t];
        hist[b * 257 + tid]++;
    }
    __syncthreads();
    if (tid < 64) {
        unsigned int run = 0;
        int b = tid;
        for (int th = 0; th < 256; th++) {
            unsigned short tmp = hist[b * 257 + th];
            hist[b * 257 + th] = (unsigned short)run;
            run += tmp;
        }
        tot[b] = (int)run;
    }
    __syncthreads();
    if (tid == 0) {
        base[0] = 0;
        for (int b = 0; b < 64; b++) base[b + 1] = base[b] + tot[b];
    }
    __syncthreads();
#pragma unroll
    for (int j = 0; j < 16; j++) {
        int t = tid * 16 + j;
        int b = sb[t];
        int pos = base[b] + hist[b * 257 + tid];
        hist[b * 257 + tid]++;
        st[(size_t)blk * TT + pos] = t;
        undo[(size_t)blk * TT + t] = pos;
    }
}

// ------------------------- chunked LSH attention ---------------------------
#define ATTN_SMEM ((128 * 133 + 64 * 132 + 128) * 4 + 128 * 4)
__global__ void __launch_bounds__(256) attn_kernel(const float* __restrict__ qk,
                                                   const float* __restrict__ v,
                                                   const int* __restrict__ st,
                                                   float* __restrict__ so,
                                                   float* __restrict__ slog) {
    extern __shared__ float sm[];
    float* s_k = sm;
    float* s_p = s_k + 128 * 133;
    float* s_rn = s_p + 64 * 132;
    int* s_pk = (int*)(s_rn + 128);
    int tid = threadIdx.x;
    int bh = blockIdx.x >> 8;
    int c = blockIdx.x & 255;
    int prev = (c + 255) & 255;
    int b = bh >> 3, h = bh & 7;
    const int* stb = st + (size_t)bh * (NHSH * TT);
    if (tid < 64) s_pk[tid] = stb[c * 64 + tid];
    else if (tid < 128) s_pk[tid] = stb[prev * 64 + (tid - 64)];
    __syncthreads();
#pragma unroll
    for (int rep = 0; rep < 16; rep++) {
        int idx = tid + rep * 256;
        int j = idx >> 5, d4 = idx & 31;
        const float* kp = qk + ((size_t)(b * TT + s_pk[j])) * DIMC + h * DHH + d4 * 4;
        float4 kv = *(const float4*)kp;
        float* dst = s_k + j * 133 + d4 * 4;
        dst[0] = kv.x; dst[1] = kv.y; dst[2] = kv.z; dst[3] = kv.w;
    }
    __syncthreads();
    if (tid < 128) {
        float sq = 0.f;
#pragma unroll 8
        for (int d = 0; d < 128; d++) {
            float x = s_k[tid * 133 + d];
            sq += x * x;
        }
        float nrm = sqrtf(sq);
        s_rn[tid] = 1.0f / fmaxf(nrm, 1e-12f);
    }
    __syncthreads();
    int lane = tid & 31, w = tid >> 5;
    const float SC = 0.08838834764831845f;
    for (int p2 = 0; p2 < 4; p2++) {
        int i0 = w * 8 + p2 * 2;
        float acc0[4] = {0, 0, 0, 0}, acc1[4] = {0, 0, 0, 0};
        const float* k0 = s_k + i0 * 133;
        const float* k1 = s_k + (i0 + 1) * 133;
        for (int d = 0; d < 128; d++) {
            float q0 = k0[d], q1 = k1[d];
#pragma unroll
            for (int cc = 0; cc < 4; cc++) {
                float kv = s_k[(lane + 32 * cc) * 133 + d];
                acc0[cc] = fmaf(q0, kv, acc0[cc]);
                acc1[cc] = fmaf(q1, kv, acc1[cc]);
            }
        }
        int pq0 = s_pk[i0], pq1 = s_pk[i0 + 1];
#pragma unroll
        for (int cc = 0; cc < 4; cc++) {
            int j = lane + 32 * cc;
            float rn = s_rn[j];
            int pkj = s_pk[j];
            s_p[i0 * 132 + j] = (pq0 == pkj) ? -5e4f : acc0[cc] * rn * SC;
            s_p[(i0 + 1) * 132 + j] = (pq1 == pkj) ? -5e4f : acc1[cc] * rn * SC;
        }
    }
    __syncthreads();
    for (int rr = 0; rr < 8; rr++) {
        int i = w * 8 + rr;
        float vv[4];
#pragma unroll
        for (int cc = 0; cc < 4; cc++) vv[cc] = s_p[i * 132 + lane + 32 * cc];
        float m = fmaxf(fmaxf(vv[0], vv[1]), fmaxf(vv[2], vv[3]));
#pragma unroll
        for (int o = 16; o; o >>= 1) m = fmaxf(m, __shfl_xor_sync(~0u, m, o));
        float sum = 0.f;
#pragma unroll
        for (int cc = 0; cc < 4; cc++) {
            vv[cc] = expf(vv[cc] - m);
            sum += vv[cc];
        }
#pragma unroll
        for (int o = 16; o; o >>= 1) sum += __shfl_xor_sync(~0u, sum, o);
        float lse = m + logf(sum);
        float isum = 1.0f / sum;
#pragma unroll
        for (int cc = 0; cc < 4; cc++) s_p[i * 132 + lane + 32 * cc] = vv[cc] * isum;
        if (lane == 0) slog[(size_t)bh * (NHSH * TT) + c * 64 + i] = lse;
    }
    __syncthreads();
    float acc[8][4];
#pragma unroll
    for (int ii = 0; ii < 8; ii++)
#pragma unroll
        for (int dd = 0; dd < 4; dd++) acc[ii][dd] = 0.f;
    for (int j = 0; j < 128; j++) {
        const float* vp = v + ((size_t)(b * TT + s_pk[j])) * DIMC + h * DHH;
        float v0 = vp[lane], v1 = vp[lane + 32], v2 = vp[lane + 64], v3 = vp[lane + 96];
#pragma unroll
        for (int ii = 0; ii < 8; ii++) {
            float pij = s_p[(w + 8 * ii) * 132 + j];
            acc[ii][0] = fmaf(pij, v0, acc[ii][0]);
            acc[ii][1] = fmaf(pij, v1, acc[ii][1]);
            acc[ii][2] = fmaf(pij, v2, acc[ii][2]);
            acc[ii][3] = fmaf(pij, v3, acc[ii][3]);
        }
    }
#pragma unroll
    for (int ii = 0; ii < 8; ii++) {
        size_t base = ((size_t)bh * (NHSH * TT) + c * 64 + w + 8 * ii) * 128;
        so[base + lane] = acc[ii][0];
        so[base + lane + 32] = acc[ii][1];
        so[base + lane + 64] = acc[ii][2];
        so[base + lane + 96] = acc[ii][3];
    }
}

// ------------------------- combine hash rounds ----------------------------
__global__ void combine_kernel(const float* __restrict__ so, const float* __restrict__ slog,
                               const int* __restrict__ undo, float* __restrict__ attn) {
    int warp = threadIdx.x >> 5, lane = threadIdx.x & 31;
    int rid = blockIdx.x * 8 + warp;
    int bh = rid >> 12, t = rid & 4095;
    int b = bh >> 3, h = bh & 7;
    int u[4];
    float lg[4];
#pragma unroll
    for (int r = 0; r < 4; r++) {
        u[r] = undo[((size_t)bh * 4 + r) * TT + t];
        lg[r] = slog[(size_t)bh * (NHSH * TT) + r * TT + u[r]];
    }
    float m = fmaxf(fmaxf(lg[0], lg[1]), fmaxf(lg[2], lg[3]));
    float e[4];
    float s = 0.f;
#pragma unroll
    for (int r = 0; r < 4; r++) {
        e[r] = expf(lg[r] - m);
        s += e[r];
    }
    float is = 1.0f / s;
    float a0 = 0, a1 = 0, a2 = 0, a3 = 0;
#pragma unroll
    for (int r = 0; r < 4; r++) {
        const float* op = so + ((size_t)bh * (NHSH * TT) + r * TT + u[r]) * 128;
        float pr = e[r] * is;
        a0 = fmaf(pr, op[lane], a0);
        a1 = fmaf(pr, op[lane + 32], a1);
        a2 = fmaf(pr, op[lane + 64], a2);
        a3 = fmaf(pr, op[lane + 96], a3);
    }
    float* dst = attn + ((size_t)(b * TT + t)) * DIMC + h * DHH;
    dst[lane] = a0;
    dst[lane + 32] = a1;
    dst[lane + 64] = a2;
    dst[lane + 96] = a3;
}

// ------------------------- final y1 + y2 ----------------------------------
__global__ void add_out(float* __restrict__ out) {
    int i = blockIdx.x * blockDim.x + threadIdx.x;
    float4 a = ((float4*)g_x1)[i];
    float4 b = ((float4*)g_x2)[i];
    float4 o;
    o.x = a.x + b.x; o.y = a.y + b.y; o.z = a.z + b.z; o.w = a.w + b.w;
    ((float4*)out)[i] = o;
}

// ------------------------- launch -----------------------------------------
extern "C" void kernel_launch(void* const* d_in, const int* in_sizes, int n_in,
                              void* d_out, int out_size) {
    const float* x = (const float*)d_in[0];
    const float* ln1g = (const float*)d_in[1];
    const float* ln1b = (const float*)d_in[2];
    const float* Wqk = (const float*)d_in[3];
    const float* Wv = (const float*)d_in[4];
    const float* Wo = (const float*)d_in[5];
    const float* bo = (const float*)d_in[6];
    const float* ln2g = (const float*)d_in[7];
    const float* ln2b = (const float*)d_in[8];
    const float* W1 = (const float*)d_in[9];
    const float* b1 = (const float*)d_in[10];
    const float* W2 = (const float*)d_in[11];
    const float* b2 = (const float*)d_in[12];
    const float* rot = (const float*)d_in[13];

    float *px1, *px2, *pxn, *pqk, *pv, *pattn, *pff, *pso, *pslog;
    int *pst, *pundo;
    unsigned char* pbkt;
    __nv_bfloat16 *pA3, *pB3;
    cudaGetSymbolAddress((void**)&px1, g_x1);
    cudaGetSymbolAddress((void**)&px2, g_x2);
    cudaGetSymbolAddress((void**)&pxn, g_xn);
    cudaGetSymbolAddress((void**)&pqk, g_qk);
    cudaGetSymbolAddress((void**)&pv, g_v);
    cudaGetSymbolAddress((void**)&pattn, g_attn);
    cudaGetSymbolAddress((void**)&pff, g_ff);
    cudaGetSymbolAddress((void**)&pso, g_so);
    cudaGetSymbolAddress((void**)&pslog, g_slog);
    cudaGetSymbolAddress((void**)&pst, g_st);
    cudaGetSymbolAddress((void**)&pundo, g_undo);
    cudaGetSymbolAddress((void**)&pbkt, g_bucket);
    cudaGetSymbolAddress((void**)&pA3, g_A3);
    cudaGetSymbolAddress((void**)&pB3, g_B3);

    cudaFuncSetAttribute(attn_kernel, cudaFuncAttributeMaxDynamicSharedMemorySize, ATTN_SMEM);
    cudaFuncSetAttribute(tgemm<0>, cudaFuncAttributeMaxDynamicSharedMemorySize, TG_DSMEM);
    cudaFuncSetAttribute(tgemm<3>, cudaFuncAttributeMaxDynamicSharedMemorySize, TG_DSMEM);
    cudaFuncSetAttribute(tgemm<5>, cudaFuncAttributeMaxDynamicSharedMemorySize, TG_DSMEM);

    init_xx<<<TOK * DIMC / 4 / 256, 256>>>(x);

    for (int L = 0; L < 2; L++) {
        const float* wqk = Wqk + (size_t)L * DIMC * DIMC;
        const float* wv = Wv + (size_t)L * DIMC * DIMC;
        const float* wo = Wo + (size_t)L * DIMC * DIMC;
        const float* w1 = W1 + (size_t)L * DIMC * FFD;
        const float* w2 = W2 + (size_t)L * FFD * DIMC;
        const float* rl = rot + (size_t)L * DHH * NHSH * (NBKT / 2);

        // attn input projection: qk & v
        ln_kernel<<<TOK, 256>>>(px2, ln1g + L * DIMC, ln1b + L * DIMC, pxn);
        convA_kernel<<<TOK * DIMC / 4 / 256, 256>>>(pxn, pA3, DIMC);
        convB_kernel<<<dim3(DIMC / 32, DIMC / 32), 256>>>(wqk, pB3, DIMC, DIMC);
        tgemm<0><<<dim3(8, 64), 256, TG_DSMEM>>>(pA3, pB3, pqk, nullptr, nullptr, 1024, 3072);
        convB_kernel<<<dim3(DIMC / 32, DIMC / 32), 256>>>(wv, pB3, DIMC, DIMC);
        tgemm<0><<<dim3(8, 64), 256, TG_DSMEM>>>(pA3, pB3, pv, nullptr, nullptr, 1024, 3072);

        hash_kernel<<<TOK, 256>>>(pqk, rl, pbkt);
        sort_kernel<<<64, 256>>>(pbkt, pst, pundo);
        attn_kernel<<<BHC * NCHK, 256, ATTN_SMEM>>>(pqk, pv, pst, pso, pslog);
        combine_kernel<<<TOK, 256>>>(pso, pslog, pundo, pattn);

        // output projection + residual
        convA_kernel<<<TOK * DIMC / 4 / 256, 256>>>(pattn, pA3, DIMC);
        convB_kernel<<<dim3(DIMC / 32, DIMC / 32), 256>>>(wo, pB3, DIMC, DIMC);
        tgemm<3><<<dim3(8, 64), 256, TG_DSMEM>>>(pA3, pB3, px1, bo + L * DIMC, px1, 1024, 3072);

        // feedforward
        ln_kernel<<<TOK, 256>>>(px1, ln2g + L * DIMC, ln2b + L * DIMC, pxn);
        convA_kernel<<<TOK * DIMC / 4 / 256, 256>>>(pxn, pA3, DIMC);
        convB_kernel<<<dim3(FFD / 32, DIMC / 32), 256>>>(w1, pB3, DIMC, FFD);
        tgemm<5><<<dim3(32, 64), 256, TG_DSMEM>>>(pA3, pB3, pff, b1 + L * FFD, nullptr, 4096, 3072);
        convA_kernel<<<TOK * FFD / 4 / 256, 256>>>(pff, pA3, FFD);
        convB_kernel<<<dim3(DIMC / 32, FFD / 32), 256>>>(w2, pB3, FFD, DIMC);
        tgemm<3><<<dim3(8, 64), 256, TG_DSMEM>>>(pA3, pB3, px2, b2 + L * DIMC, px2, 1024, 12288);
    }

    add_out<<<TOK * DIMC / 4 / 256, 256>>>((float*)d_out);
}

// round 9
// speedup vs baseline: 1.9767x; 1.0205x over previous
#include <cuda_runtime.h>
#include <cuda_bf16.h>
#include <math.h>
#include <stdint.h>

#define DIMC 1024
#define TT   4096
#define BBAT 2
#define HH   8
#define DHH  128
#define BHC  16
#define TOK  8192
#define NHSH 4
#define NBKT 64
#define NCHK 256
#define FFD  4096

// ------------------------- scratch (device globals, no allocs) -------------
__device__ float g_x1[TOK * DIMC];
__device__ float g_x2[TOK * DIMC];
__device__ float g_xn[TOK * DIMC];
__device__ float g_qk[TOK * DIMC];
__device__ float g_v[TOK * DIMC];
__device__ float g_attn[TOK * DIMC];
__device__ float g_ff[TOK * FFD];
__device__ float g_so[BHC * NHSH * TT * DHH];
__device__ float g_slog[BHC * NHSH * TT];
__device__ int g_st[BHC * NHSH * TT];
__device__ int g_undo[BHC * NHSH * TT];
__device__ unsigned char g_bucket[BHC * NHSH * TT];
// split-bf16 operand buffers (uint4 for 16B alignment)
__device__ uint4 g_A3[(size_t)TOK * 3 * FFD * 2 / 16];
__device__ uint4 g_B3[(size_t)FFD * 3 * DIMC * 2 / 16];

// ------------------------- helpers ----------------------------------------
__device__ __forceinline__ uint32_t smem_u32(const void* p) {
    uint32_t a;
    asm("{ .reg .u64 t; cvta.to.shared.u64 t, %1; cvt.u32.u64 %0, t; }" : "=r"(a) : "l"(p));
    return a;
}
__device__ __forceinline__ uint32_t swz128(uint32_t off) { return off ^ ((off >> 3) & 0x70); }

__device__ __forceinline__ void cp_async16(uint32_t so, const void* g) {
    asm volatile("cp.async.cg.shared.global [%0], [%1], 16;" :: "r"(so), "l"(g));
}
__device__ __forceinline__ void ldm_x4(uint32_t& r0, uint32_t& r1, uint32_t& r2, uint32_t& r3,
                                       uint32_t a) {
    asm volatile("ldmatrix.sync.aligned.m8n8.x4.shared.b16 {%0,%1,%2,%3}, [%4];"
                 : "=r"(r0), "=r"(r1), "=r"(r2), "=r"(r3) : "r"(a));
}
__device__ __forceinline__ void mma16816(float* c, uint32_t a0, uint32_t a1, uint32_t a2,
                                         uint32_t a3, uint32_t b0, uint32_t b1) {
    asm volatile(
        "mma.sync.aligned.m16n8k16.row.col.f32.bf16.bf16.f32 "
        "{%0,%1,%2,%3}, {%4,%5,%6,%7}, {%8,%9}, {%0,%1,%2,%3};"
        : "+f"(c[0]), "+f"(c[1]), "+f"(c[2]), "+f"(c[3])
        : "r"(a0), "r"(a1), "r"(a2), "r"(a3), "r"(b0), "r"(b1));
}

// ------------------------- init: x1 = x2 = x ------------------------------
__global__ void init_xx(const float* __restrict__ x) {
    int i = blockIdx.x * blockDim.x + threadIdx.x;
    float4 v = ((const float4*)x)[i];
    ((float4*)g_x1)[i] = v;
    ((float4*)g_x2)[i] = v;
}

// ------------------------- layernorm --------------------------------------
__global__ void ln_kernel(const float* __restrict__ in, const float* __restrict__ g,
                          const float* __restrict__ b, float* __restrict__ out) {
    int row = blockIdx.x;
    int tid = threadIdx.x;
    const float* p = in + (size_t)row * DIMC;
    float v[4];
    float s = 0.f, sq = 0.f;
#pragma unroll
    for (int j = 0; j < 4; j++) {
        float x = p[tid + j * 256];
        v[j] = x;
        s += x;
        sq += x * x;
    }
#pragma unroll
    for (int o = 16; o; o >>= 1) {
        s += __shfl_xor_sync(~0u, s, o);
        sq += __shfl_xor_sync(~0u, sq, o);
    }
    __shared__ float rs[8], rq[8];
    if ((tid & 31) == 0) { rs[tid >> 5] = s; rq[tid >> 5] = sq; }
    __syncthreads();
    float S = 0.f, Q = 0.f;
#pragma unroll
    for (int w = 0; w < 8; w++) { S += rs[w]; Q += rq[w]; }
    float mean = S * (1.0f / DIMC);
    float var = Q * (1.0f / DIMC) - mean * mean;
    float inv = rsqrtf(var + 1e-5f);
#pragma unroll
    for (int j = 0; j < 4; j++) {
        int c = tid + j * 256;
        out[(size_t)row * DIMC + c] = (v[j] - mean) * inv * g[c] + b[c];
    }
}

// ------------------------- split-bf16 conversions --------------------------
// A' [M, 3K]: [hi | hi | lo]
__global__ void convA_kernel(const float* __restrict__ X, __nv_bfloat16* __restrict__ A3, int K) {
    int lin = blockIdx.x * blockDim.x + threadIdx.x;
    int kq = K >> 2;
    int m = lin / kq;
    int k4 = (lin - m * kq) * 4;
    float4 x = *(const float4*)(X + (size_t)m * K + k4);
    size_t rb = (size_t)m * 3 * K;
    float xs[4] = {x.x, x.y, x.z, x.w};
#pragma unroll
    for (int j = 0; j < 4; j++) {
        __nv_bfloat16 h = __float2bfloat16(xs[j]);
        __nv_bfloat16 l = __float2bfloat16(xs[j] - __bfloat162float(h));
        A3[rb + k4 + j] = h;
        A3[rb + K + k4 + j] = h;
        A3[rb + 2 * K + k4 + j] = l;
    }
}

// B'^T [N, 3K] from W [K, N]: [hi | lo | hi]
__global__ void convB_kernel(const float* __restrict__ W, __nv_bfloat16* __restrict__ B3,
                             int K, int N) {
    __shared__ float s[32][33];
    int tx = threadIdx.x & 31, ty = threadIdx.x >> 5;
    int n0 = blockIdx.x * 32, k0 = blockIdx.y * 32;
#pragma unroll
    for (int j = 0; j < 4; j++)
        s[ty + 8 * j][tx] = W[(size_t)(k0 + ty + 8 * j) * N + n0 + tx];
    __syncthreads();
#pragma unroll
    for (int j = 0; j < 4; j++) {
        int r = ty + 8 * j;
        int n = n0 + r;
        int k = k0 + tx;
        float x = s[tx][r];
        __nv_bfloat16 h = __float2bfloat16(x);
        __nv_bfloat16 l = __float2bfloat16(x - __bfloat162float(h));
        size_t rb = (size_t)n * 3 * K;
        B3[rb + k] = h;
        B3[rb + K + k] = l;
        B3[rb + 2 * K + k] = h;
    }
}

// ------------------------- HMMA bf16 GEMM (mma.sync) -----------------------
// C[M,N] fp32 = A'[M,K3] x B'[N,K3]^T. Tile 128x256, BK=64, 3-stage cp.async.
// Warp layout 2x4 (each warp 64x64). FLAGS: 1=+bias, 2=+res, 4=exact gelu.
#define TG_STAGE 49152          // A 16KB + B 32KB per stage
#define TG_DSMEM (3 * TG_STAGE)

template <int FLAGS>
__global__ void __launch_bounds__(256) tgemm(const __nv_bfloat16* __restrict__ A,
                                             const __nv_bfloat16* __restrict__ B,
                                             float* __restrict__ C,
                                             const float* __restrict__ bias,
                                             const float* __restrict__ res,
                                             int N, int K3) {
    extern __shared__ char sm_[];
    int tid = threadIdx.x, lane = tid & 31, wid = tid >> 5;
    int wm = wid >> 2, wn = wid & 3;
    int bx = blockIdx.x, by = blockIdx.y;
    const char* Ag = (const char*)(A + (size_t)(by * 128) * K3);
    const char* Bg = (const char*)(B + (size_t)(bx * 256) * K3);
    size_t rs = (size_t)K3 * 2;
    int nk = K3 >> 6;
    uint32_t sbase = smem_u32(sm_);

    auto load_stage = [&](int kc, int s) {
        uint32_t sb = sbase + s * TG_STAGE;
#pragma unroll
        for (int j = 0; j < 12; j++) {
            int idx = tid + j * 256;       // 0..3071
            if (idx < 1024) {              // A: 128 rows x 8 segs
                int r = idx >> 3, seg = idx & 7;
                const char* g = Ag + (size_t)r * rs + (size_t)kc * 128 + seg * 16;
                cp_async16(sb + swz128(r * 128 + seg * 16), g);
            } else {                       // B: 256 rows x 8 segs
                int t = idx - 1024;
                int r = t >> 3, seg = t & 7;
                const char* g = Bg + (size_t)r * rs + (size_t)kc * 128 + seg * 16;
                cp_async16(sb + 16384 + swz128(r * 128 + seg * 16), g);
            }
        }
        asm volatile("cp.async.commit_group;");
    };

    float acc[4][8][4];
#pragma unroll
    for (int a = 0; a < 4; a++)
#pragma unroll
        for (int b = 0; b < 8; b++)
#pragma unroll
            for (int c = 0; c < 4; c++) acc[a][b][c] = 0.f;

    load_stage(0, 0);
    load_stage(1, 1);

    int mat = lane >> 3, rin = lane & 7;
    for (int i = 0; i < nk; i++) {
        __syncthreads();  // all warps done computing stage (i+2)%3 (iter i-1)
        if (i + 2 < nk) load_stage(i + 2, (i + 2) % 3);
        if (i + 2 < nk)       asm volatile("cp.async.wait_group 2;");
        else if (i + 1 < nk)  asm volatile("cp.async.wait_group 1;");
        else                  asm volatile("cp.async.wait_group 0;");
        __syncthreads();

        uint32_t sa = sbase + (i % 3) * TG_STAGE;
        uint32_t sb = sa + 16384;
#pragma unroll
        for (int ks = 0; ks < 4; ks++) {
            uint32_t af[4][4], bf[8][2];
#pragma unroll
            for (int mt = 0; mt < 4; mt++) {
                int row = wm * 64 + mt * 16 + (mat & 1) * 8 + rin;
                int kb = 2 * ks + (mat >> 1);
                ldm_x4(af[mt][0], af[mt][1], af[mt][2], af[mt][3],
                       sa + swz128(row * 128 + kb * 16));
            }
#pragma unroll
            for (int g = 0; g < 4; g++) {
                int nt = 2 * g + (mat >> 1);
                int n = wn * 64 + nt * 8 + rin;
                int kb = 2 * ks + (mat & 1);
                uint32_t b0, b1, b2, b3;
                ldm_x4(b0, b1, b2, b3, sb + swz128(n * 128 + kb * 16));
                bf[2 * g][0] = b0; bf[2 * g][1] = b1;
                bf[2 * g + 1][0] = b2; bf[2 * g + 1][1] = b3;
            }
#pragma unroll
            for (int mt = 0; mt < 4; mt++)
#pragma unroll
                for (int nt = 0; nt < 8; nt++)
                    mma16816(acc[mt][nt], af[mt][0], af[mt][1], af[mt][2], af[mt][3],
                             bf[nt][0], bf[nt][1]);
        }
    }

    // epilogue: direct float2 stores
#pragma unroll
    for (int mt = 0; mt < 4; mt++) {
        int gr0 = by * 128 + wm * 64 + mt * 16 + (lane >> 2);
#pragma unroll
        for (int nt = 0; nt < 8; nt++) {
            int gc = bx * 256 + wn * 64 + nt * 8 + (lane & 3) * 2;
            float v0 = acc[mt][nt][0], v1 = acc[mt][nt][1];
            float v2 = acc[mt][nt][2], v3 = acc[mt][nt][3];
            if (FLAGS & 1) {
                float b0 = bias[gc], b1 = bias[gc + 1];
                v0 += b0; v1 += b1; v2 += b0; v3 += b1;
            }
            if (FLAGS & 4) {
                v0 = 0.5f * v0 * (1.0f + erff(v0 * 0.70710678118654752f));
                v1 = 0.5f * v1 * (1.0f + erff(v1 * 0.70710678118654752f));
                v2 = 0.5f * v2 * (1.0f + erff(v2 * 0.70710678118654752f));
                v3 = 0.5f * v3 * (1.0f + erff(v3 * 0.70710678118654752f));
            }
            if (FLAGS & 2) {
                const float* r0p = res + (size_t)gr0 * N + gc;
                const float* r1p = res + (size_t)(gr0 + 8) * N + gc;
                v0 += r0p[0]; v1 += r0p[1]; v2 += r1p[0]; v3 += r1p[1];
            }
            float2 o0 = {v0, v1}, o1 = {v2, v3};
            *(float2*)(C + (size_t)gr0 * N + gc) = o0;
            *(float2*)(C + (size_t)(gr0 + 8) * N + gc) = o1;
        }
    }
}

// ------------------------- LSH hashing ------------------------------------
__global__ void hash_kernel(const float* __restrict__ qk, const float* __restrict__ rot,
                            unsigned char* __restrict__ bucket) {
    __shared__ float srow[8][128];
    int warp = threadIdx.x >> 5, lane = threadIdx.x & 31;
    int rid = blockIdx.x * 8 + warp;
    int bh = rid >> 12, t = rid & 4095;
    int b = bh >> 3, h = bh & 7;
    const float* qp = qk + ((size_t)(b * TT + t)) * DIMC + h * DHH;
#pragma unroll
    for (int j = 0; j < 4; j++) srow[warp][lane + j * 32] = qp[lane + j * 32];
    __syncwarp();
#pragma unroll
    for (int hh = 0; hh < 4; hh++) {
        float acc = 0.f;
#pragma unroll 8
        for (int f = 0; f < 128; f++)
            acc = fmaf(srow[warp][f], rot[f * 128 + hh * 32 + lane], acc);
        float val = fmaxf(acc, -acc);
        int idx = (acc >= -acc) ? lane : 32 + lane;
#pragma unroll
        for (int o = 16; o; o >>= 1) {
            float ov = __shfl_down_sync(~0u, val, o);
            int oi = __shfl_down_sync(~0u, idx, o);
            if (ov > val || (ov == val && oi < idx)) { val = ov; idx = oi; }
        }
        if (lane == 0) bucket[((size_t)bh * 4 + hh) * TT + t] = (unsigned char)idx;
    }
}

// ------------------------- stable counting sort per (bh, hash) ------------
__global__ void sort_kernel(const unsigned char* __restrict__ bucket,
                            int* __restrict__ st, int* __restrict__ undo) {
    __shared__ unsigned char sb[4096];
    __shared__ unsigned short hist[64 * 257];
    __shared__ int base[65];
    __shared__ int tot[64];
    int blk = blockIdx.x;
    int tid = threadIdx.x;
    const unsigned char* bp = bucket + (size_t)blk * TT;
    for (int i = tid; i < 4096; i += 256) sb[i] = bp[i];
    for (int i = tid; i < 64 * 257; i += 256) hist[i] = 0;
    __syncthreads();
#pragma unroll
    for (int j = 0; j < 16; j++) {
        int t = tid * 16 + j;
        int b = sb[t];
        hist[b * 257 + tid]++;
    }
    __syncthreads();
    if (tid < 64) {
        unsigned int run = 0;
        int b = tid;
        for (int th = 0; th < 256; th++) {
            unsigned short tmp = hist[b * 257 + th];
            hist[b * 257 + th] = (unsigned short)run;
            run += tmp;
        }
        tot[b] = (int)run;
    }
    __syncthreads();
    if (tid == 0) {
        base[0] = 0;
        for (int b = 0; b < 64; b++) base[b + 1] = base[b] + tot[b];
    }
    __syncthreads();
#pragma unroll
    for (int j = 0; j < 16; j++) {
        int t = tid * 16 + j;
        int b = sb[t];
        int pos = base[b] + hist[b * 257 + tid];
        hist[b * 257 + tid]++;
        st[(size_t)blk * TT + pos] = t;
        undo[(size_t)blk * TT + t] = pos;
    }
}

// ------------------------- chunked LSH attention ---------------------------
#define ATTN_SMEM ((128 * 133 + 64 * 132 + 128) * 4 + 128 * 4)
__global__ void __launch_bounds__(256) attn_kernel(const float* __restrict__ qk,
                                                   const float* __restrict__ v,
                                                   const int* __restrict__ st,
                                                   float* __restrict__ so,
                                                   float* __restrict__ slog) {
    extern __shared__ float sm[];
    float* s_k = sm;
    float* s_p = s_k + 128 * 133;
    float* s_rn = s_p + 64 * 132;
    int* s_pk = (int*)(s_rn + 128);
    int tid = threadIdx.x;
    int bh = blockIdx.x >> 8;
    int c = blockIdx.x & 255;
    int prev = (c + 255) & 255;
    int b = bh >> 3, h = bh & 7;
    const int* stb = st + (size_t)bh * (NHSH * TT);
    if (tid < 64) s_pk[tid] = stb[c * 64 + tid];
    else if (tid < 128) s_pk[tid] = stb[prev * 64 + (tid - 64)];
    __syncthreads();
#pragma unroll
    for (int rep = 0; rep < 16; rep++) {
        int idx = tid + rep * 256;
        int j = idx >> 5, d4 = idx & 31;
        const float* kp = qk + ((size_t)(b * TT + s_pk[j])) * DIMC + h * DHH + d4 * 4;
        float4 kv = *(const float4*)kp;
        float* dst = s_k + j * 133 + d4 * 4;
        dst[0] = kv.x; dst[1] = kv.y; dst[2] = kv.z; dst[3] = kv.w;
    }
    __syncthreads();
    if (tid < 128) {
        float sq = 0.f;
#pragma unroll 8
        for (int d = 0; d < 128; d++) {
            float x = s_k[tid * 133 + d];
            sq += x * x;
        }
        float nrm = sqrtf(sq);
        s_rn[tid] = 1.0f / fmaxf(nrm, 1e-12f);
    }
    __syncthreads();
    int lane = tid & 31, w = tid >> 5;
    const float SC = 0.08838834764831845f;
    for (int p2 = 0; p2 < 4; p2++) {
        int i0 = w * 8 + p2 * 2;
        float acc0[4] = {0, 0, 0, 0}, acc1[4] = {0, 0, 0, 0};
        const float* k0 = s_k + i0 * 133;
        const float* k1 = s_k + (i0 + 1) * 133;
        for (int d = 0; d < 128; d++) {
            float q0 = k0[d], q1 = k1[d];
#pragma unroll
            for (int cc = 0; cc < 4; cc++) {
                float kv = s_k[(lane + 32 * cc) * 133 + d];
                acc0[cc] = fmaf(q0, kv, acc0[cc]);
                acc1[cc] = fmaf(q1, kv, acc1[cc]);
            }
        }
        int pq0 = s_pk[i0], pq1 = s_pk[i0 + 1];
#pragma unroll
        for (int cc = 0; cc < 4; cc++) {
            int j = lane + 32 * cc;
            float rn = s_rn[j];
            int pkj = s_pk[j];
            s_p[i0 * 132 + j] = (pq0 == pkj) ? -5e4f : acc0[cc] * rn * SC;
            s_p[(i0 + 1) * 132 + j] = (pq1 == pkj) ? -5e4f : acc1[cc] * rn * SC;
        }
    }
    __syncthreads();
    for (int rr = 0; rr < 8; rr++) {
        int i = w * 8 + rr;
        float vv[4];
#pragma unroll
        for (int cc = 0; cc < 4; cc++) vv[cc] = s_p[i * 132 + lane + 32 * cc];
        float m = fmaxf(fmaxf(vv[0], vv[1]), fmaxf(vv[2], vv[3]));
#pragma unroll
        for (int o = 16; o; o >>= 1) m = fmaxf(m, __shfl_xor_sync(~0u, m, o));
        float sum = 0.f;
#pragma unroll
        for (int cc = 0; cc < 4; cc++) {
            vv[cc] = expf(vv[cc] - m);
            sum += vv[cc];
        }
#pragma unroll
        for (int o = 16; o; o >>= 1) sum += __shfl_xor_sync(~0u, sum, o);
        float lse = m + logf(sum);
        float isum = 1.0f / sum;
#pragma unroll
        for (int cc = 0; cc < 4; cc++) s_p[i * 132 + lane + 32 * cc] = vv[cc] * isum;
        if (lane == 0) slog[(size_t)bh * (NHSH * TT) + c * 64 + i] = lse;
    }
    __syncthreads();
    float acc[8][4];
#pragma unroll
    for (int ii = 0; ii < 8; ii++)
#pragma unroll
        for (int dd = 0; dd < 4; dd++) acc[ii][dd] = 0.f;
    for (int j = 0; j < 128; j++) {
        const float* vp = v + ((size_t)(b * TT + s_pk[j])) * DIMC + h * DHH;
        float v0 = vp[lane], v1 = vp[lane + 32], v2 = vp[lane + 64], v3 = vp[lane + 96];
#pragma unroll
        for (int ii = 0; ii < 8; ii++) {
            float pij = s_p[(w + 8 * ii) * 132 + j];
            acc[ii][0] = fmaf(pij, v0, acc[ii][0]);
            acc[ii][1] = fmaf(pij, v1, acc[ii][1]);
            acc[ii][2] = fmaf(pij, v2, acc[ii][2]);
            acc[ii][3] = fmaf(pij, v3, acc[ii][3]);
        }
    }
#pragma unroll
    for (int ii = 0; ii < 8; ii++) {
        size_t base = ((size_t)bh * (NHSH * TT) + c * 64 + w + 8 * ii) * 128;
        so[base + lane] = acc[ii][0];
        so[base + lane + 32] = acc[ii][1];
        so[base + lane + 64] = acc[ii][2];
        so[base + lane + 96] = acc[ii][3];
    }
}

// ------------------------- combine hash rounds ----------------------------
__global__ void combine_kernel(const float* __restrict__ so, const float* __restrict__ slog,
                               const int* __restrict__ undo, float* __restrict__ attn) {
    int warp = threadIdx.x >> 5, lane = threadIdx.x & 31;
    int rid = blockIdx.x * 8 + warp;
    int bh = rid >> 12, t = rid & 4095;
    int b = bh >> 3, h = bh & 7;
    int u[4];
    float lg[4];
#pragma unroll
    for (int r = 0; r < 4; r++) {
        u[r] = undo[((size_t)bh * 4 + r) * TT + t];
        lg[r] = slog[(size_t)bh * (NHSH * TT) + r * TT + u[r]];
    }
    float m = fmaxf(fmaxf(lg[0], lg[1]), fmaxf(lg[2], lg[3]));
    float e[4];
    float s = 0.f;
#pragma unroll
    for (int r = 0; r < 4; r++) {
        e[r] = expf(lg[r] - m);
        s += e[r];
    }
    float is = 1.0f / s;
    float a0 = 0, a1 = 0, a2 = 0, a3 = 0;
#pragma unroll
    for (int r = 0; r < 4; r++) {
        const float* op = so + ((size_t)bh * (NHSH * TT) + r * TT + u[r]) * 128;
        float pr = e[r] * is;
        a0 = fmaf(pr, op[lane], a0);
        a1 = fmaf(pr, op[lane + 32], a1);
        a2 = fmaf(pr, op[lane + 64], a2);
        a3 = fmaf(pr, op[lane + 96], a3);
    }
    float* dst = attn + ((size_t)(b * TT + t)) * DIMC + h * DHH;
    dst[lane] = a0;
    dst[lane + 32] = a1;
    dst[lane + 64] = a2;
    dst[lane + 96] = a3;
}

// ------------------------- final y1 + y2 ----------------------------------
__global__ void add_out(float* __restrict__ out) {
    int i = blockIdx.x * blockDim.x + threadIdx.x;
    float4 a = ((float4*)g_x1)[i];
    float4 b = ((float4*)g_x2)[i];
    float4 o;
    o.x = a.x + b.x; o.y = a.y + b.y; o.z = a.z + b.z; o.w = a.w + b.w;
    ((float4*)out)[i] = o;
}

// ------------------------- launch -----------------------------------------
extern "C" void kernel_launch(void* const* d_in, const int* in_sizes, int n_in,
                              void* d_out, int out_size) {
    const float* x = (const float*)d_in[0];
    const float* ln1g = (const float*)d_in[1];
    const float* ln1b = (const float*)d_in[2];
    const float* Wqk = (const float*)d_in[3];
    const float* Wv = (const float*)d_in[4];
    const float* Wo = (const float*)d_in[5];
    const float* bo = (const float*)d_in[6];
    const float* ln2g = (const float*)d_in[7];
    const float* ln2b = (const float*)d_in[8];
    const float* W1 = (const float*)d_in[9];
    const float* b1 = (const float*)d_in[10];
    const float* W2 = (const float*)d_in[11];
    const float* b2 = (const float*)d_in[12];
    const float* rot = (const float*)d_in[13];

    float *px1, *px2, *pxn, *pqk, *pv, *pattn, *pff, *pso, *pslog;
    int *pst, *pundo;
    unsigned char* pbkt;
    __nv_bfloat16 *pA3, *pB3;
    cudaGetSymbolAddress((void**)&px1, g_x1);
    cudaGetSymbolAddress((void**)&px2, g_x2);
    cudaGetSymbolAddress((void**)&pxn, g_xn);
    cudaGetSymbolAddress((void**)&pqk, g_qk);
    cudaGetSymbolAddress((void**)&pv, g_v);
    cudaGetSymbolAddress((void**)&pattn, g_attn);
    cudaGetSymbolAddress((void**)&pff, g_ff);
    cudaGetSymbolAddress((void**)&pso, g_so);
    cudaGetSymbolAddress((void**)&pslog, g_slog);
    cudaGetSymbolAddress((void**)&pst, g_st);
    cudaGetSymbolAddress((void**)&pundo, g_undo);
    cudaGetSymbolAddress((void**)&pbkt, g_bucket);
    cudaGetSymbolAddress((void**)&pA3, g_A3);
    cudaGetSymbolAddress((void**)&pB3, g_B3);

    cudaFuncSetAttribute(attn_kernel, cudaFuncAttributeMaxDynamicSharedMemorySize, ATTN_SMEM);
    cudaFuncSetAttribute(tgemm<0>, cudaFuncAttributeMaxDynamicSharedMemorySize, TG_DSMEM);
    cudaFuncSetAttribute(tgemm<3>, cudaFuncAttributeMaxDynamicSharedMemorySize, TG_DSMEM);
    cudaFuncSetAttribute(tgemm<5>, cudaFuncAttributeMaxDynamicSharedMemorySize, TG_DSMEM);

    init_xx<<<TOK * DIMC / 4 / 256, 256>>>(x);

    for (int L = 0; L < 2; L++) {
        const float* wqk = Wqk + (size_t)L * DIMC * DIMC;
        const float* wv = Wv + (size_t)L * DIMC * DIMC;
        const float* wo = Wo + (size_t)L * DIMC * DIMC;
        const float* w1 = W1 + (size_t)L * DIMC * FFD;
        const float* w2 = W2 + (size_t)L * FFD * DIMC;
        const float* rl = rot + (size_t)L * DHH * NHSH * (NBKT / 2);

        // attn input projection: qk & v
        ln_kernel<<<TOK, 256>>>(px2, ln1g + L * DIMC, ln1b + L * DIMC, pxn);
        convA_kernel<<<TOK * DIMC / 4 / 256, 256>>>(pxn, pA3, DIMC);
        convB_kernel<<<dim3(DIMC / 32, DIMC / 32), 256>>>(wqk, pB3, DIMC, DIMC);
        tgemm<0><<<dim3(4, 64), 256, TG_DSMEM>>>(pA3, pB3, pqk, nullptr, nullptr, 1024, 3072);
        convB_kernel<<<dim3(DIMC / 32, DIMC / 32), 256>>>(wv, pB3, DIMC, DIMC);
        tgemm<0><<<dim3(4, 64), 256, TG_DSMEM>>>(pA3, pB3, pv, nullptr, nullptr, 1024, 3072);

        hash_kernel<<<TOK, 256>>>(pqk, rl, pbkt);
        sort_kernel<<<64, 256>>>(pbkt, pst, pundo);
        attn_kernel<<<BHC * NCHK, 256, ATTN_SMEM>>>(pqk, pv, pst, pso, pslog);
        combine_kernel<<<TOK, 256>>>(pso, pslog, pundo, pattn);

        // output projection + residual
        convA_kernel<<<TOK * DIMC / 4 / 256, 256>>>(pattn, pA3, DIMC);
        convB_kernel<<<dim3(DIMC / 32, DIMC / 32), 256>>>(wo, pB3, DIMC, DIMC);
        tgemm<3><<<dim3(4, 64), 256, TG_DSMEM>>>(pA3, pB3, px1, bo + L * DIMC, px1, 1024, 3072);

        // feedforward
        ln_kernel<<<TOK, 256>>>(px1, ln2g + L * DIMC, ln2b + L * DIMC, pxn);
        convA_kernel<<<TOK * DIMC / 4 / 256, 256>>>(pxn, pA3, DIMC);
        convB_kernel<<<dim3(FFD / 32, DIMC / 32), 256>>>(w1, pB3, DIMC, FFD);
        tgemm<5><<<dim3(16, 64), 256, TG_DSMEM>>>(pA3, pB3, pff, b1 + L * FFD, nullptr, 4096, 3072);
        convA_kernel<<<TOK * FFD / 4 / 256, 256>>>(pff, pA3, FFD);
        convB_kernel<<<dim3(DIMC / 32, FFD / 32), 256>>>(w2, pB3, FFD, DIMC);
        tgemm<3><<<dim3(4, 64), 256, TG_DSMEM>>>(pA3, pB3, px2, b2 + L * DIMC, px2, 1024, 12288);
    }

    add_out<<<TOK * DIMC / 4 / 256, 256>>>((float*)d_out);
}

// round 10
// speedup vs baseline: 2.1587x; 1.0921x over previous
#include <cuda_runtime.h>
#include <cuda_bf16.h>
#include <cuda_fp16.h>
#include <math.h>
#include <stdint.h>

#define DIMC 1024
#define TT   4096
#define BBAT 2
#define HH   8
#define DHH  128
#define BHC  16
#define TOK  8192
#define NHSH 4
#define NBKT 64
#define NCHK 256
#define FFD  4096

// ------------------------- scratch (device globals, no allocs) -------------
__device__ float g_x1[TOK * DIMC];
__device__ float g_x2[TOK * DIMC];
__device__ float g_xn[TOK * DIMC];
__device__ float g_qk[TOK * DIMC];
__device__ float g_v[TOK * DIMC];
__device__ float g_attn[TOK * DIMC];
__device__ float g_ff[TOK * FFD];
__device__ float g_so[BHC * NHSH * TT * DHH];
__device__ float g_slog[BHC * NHSH * TT];
__device__ int g_st[BHC * NHSH * TT];
__device__ int g_undo[BHC * NHSH * TT];
__device__ unsigned char g_bucket[BHC * NHSH * TT];
// split operand buffers (uint4 for 16B alignment)
__device__ uint4 g_A3[(size_t)TOK * 3 * FFD * 2 / 16];
__device__ uint4 g_B3[(size_t)FFD * 3 * DIMC * 2 / 16];

// ------------------------- helpers ----------------------------------------
__device__ __forceinline__ uint32_t smem_u32(const void* p) {
    uint32_t a;
    asm("{ .reg .u64 t; cvta.to.shared.u64 t, %1; cvt.u32.u64 %0, t; }" : "=r"(a) : "l"(p));
    return a;
}
__device__ __forceinline__ uint32_t swz128(uint32_t off) { return off ^ ((off >> 3) & 0x70); }

__device__ __forceinline__ void cp_async16(uint32_t so, const void* g) {
    asm volatile("cp.async.cg.shared.global [%0], [%1], 16;" :: "r"(so), "l"(g));
}
__device__ __forceinline__ void ldm_x4(uint32_t& r0, uint32_t& r1, uint32_t& r2, uint32_t& r3,
                                       uint32_t a) {
    asm volatile("ldmatrix.sync.aligned.m8n8.x4.shared.b16 {%0,%1,%2,%3}, [%4];"
                 : "=r"(r0), "=r"(r1), "=r"(r2), "=r"(r3) : "r"(a));
}
__device__ __forceinline__ void mma_bf16(float* c, uint32_t a0, uint32_t a1, uint32_t a2,
                                         uint32_t a3, uint32_t b0, uint32_t b1) {
    asm volatile(
        "mma.sync.aligned.m16n8k16.row.col.f32.bf16.bf16.f32 "
        "{%0,%1,%2,%3}, {%4,%5,%6,%7}, {%8,%9}, {%0,%1,%2,%3};"
        : "+f"(c[0]), "+f"(c[1]), "+f"(c[2]), "+f"(c[3])
        : "r"(a0), "r"(a1), "r"(a2), "r"(a3), "r"(b0), "r"(b1));
}
__device__ __forceinline__ void mma_fp16(float* c, uint32_t a0, uint32_t a1, uint32_t a2,
                                         uint32_t a3, uint32_t b0, uint32_t b1) {
    asm volatile(
        "mma.sync.aligned.m16n8k16.row.col.f32.f16.f16.f32 "
        "{%0,%1,%2,%3}, {%4,%5,%6,%7}, {%8,%9}, {%0,%1,%2,%3};"
        : "+f"(c[0]), "+f"(c[1]), "+f"(c[2]), "+f"(c[3])
        : "r"(a0), "r"(a1), "r"(a2), "r"(a3), "r"(b0), "r"(b1));
}

// ------------------------- init: x1 = x2 = x ------------------------------
__global__ void init_xx(const float* __restrict__ x) {
    int i = blockIdx.x * blockDim.x + threadIdx.x;
    float4 v = ((const float4*)x)[i];
    ((float4*)g_x1)[i] = v;
    ((float4*)g_x2)[i] = v;
}

// ------------------------- layernorm --------------------------------------
__global__ void ln_kernel(const float* __restrict__ in, const float* __restrict__ g,
                          const float* __restrict__ b, float* __restrict__ out) {
    int row = blockIdx.x;
    int tid = threadIdx.x;
    const float* p = in + (size_t)row * DIMC;
    float v[4];
    float s = 0.f, sq = 0.f;
#pragma unroll
    for (int j = 0; j < 4; j++) {
        float x = p[tid + j * 256];
        v[j] = x;
        s += x;
        sq += x * x;
    }
#pragma unroll
    for (int o = 16; o; o >>= 1) {
        s += __shfl_xor_sync(~0u, s, o);
        sq += __shfl_xor_sync(~0u, sq, o);
    }
    __shared__ float rs[8], rq[8];
    if ((tid & 31) == 0) { rs[tid >> 5] = s; rq[tid >> 5] = sq; }
    __syncthreads();
    float S = 0.f, Q = 0.f;
#pragma unroll
    for (int w = 0; w < 8; w++) { S += rs[w]; Q += rq[w]; }
    float mean = S * (1.0f / DIMC);
    float var = Q * (1.0f / DIMC) - mean * mean;
    float inv = rsqrtf(var + 1e-5f);
#pragma unroll
    for (int j = 0; j < 4; j++) {
        int c = tid + j * 256;
        out[(size_t)row * DIMC + c] = (v[j] - mean) * inv * g[c] + b[c];
    }
}

// ------------------------- split conversions --------------------------
// 3-term bf16: A' [M, 3K]: [hi | hi | lo]
__global__ void convA_kernel(const float* __restrict__ X, __nv_bfloat16* __restrict__ A3, int K) {
    int lin = blockIdx.x * blockDim.x + threadIdx.x;
    int kq = K >> 2;
    int m = lin / kq;
    int k4 = (lin - m * kq) * 4;
    float4 x = *(const float4*)(X + (size_t)m * K + k4);
    size_t rb = (size_t)m * 3 * K;
    float xs[4] = {x.x, x.y, x.z, x.w};
#pragma unroll
    for (int j = 0; j < 4; j++) {
        __nv_bfloat16 h = __float2bfloat16(xs[j]);
        __nv_bfloat16 l = __float2bfloat16(xs[j] - __bfloat162float(h));
        A3[rb + k4 + j] = h;
        A3[rb + K + k4 + j] = h;
        A3[rb + 2 * K + k4 + j] = l;
    }
}

// 3-term bf16: B'^T [N, 3K] from W [K, N]: [hi | lo | hi]
__global__ void convB_kernel(const float* __restrict__ W, __nv_bfloat16* __restrict__ B3,
                             int K, int N) {
    __shared__ float s[32][33];
    int tx = threadIdx.x & 31, ty = threadIdx.x >> 5;
    int n0 = blockIdx.x * 32, k0 = blockIdx.y * 32;
#pragma unroll
    for (int j = 0; j < 4; j++)
        s[ty + 8 * j][tx] = W[(size_t)(k0 + ty + 8 * j) * N + n0 + tx];
    __syncthreads();
#pragma unroll
    for (int j = 0; j < 4; j++) {
        int r = ty + 8 * j;
        int n = n0 + r;
        int k = k0 + tx;
        float x = s[tx][r];
        __nv_bfloat16 h = __float2bfloat16(x);
        __nv_bfloat16 l = __float2bfloat16(x - __bfloat162float(h));
        size_t rb = (size_t)n * 3 * K;
        B3[rb + k] = h;
        B3[rb + K + k] = l;
        B3[rb + 2 * K + k] = h;
    }
}

// 2-term fp16: A' [M, 2K]: [hi | lo]
__global__ void convA2h_kernel(const float* __restrict__ X, __half* __restrict__ A2, int K) {
    int lin = blockIdx.x * blockDim.x + threadIdx.x;
    int kq = K >> 2;
    int m = lin / kq;
    int k4 = (lin - m * kq) * 4;
    float4 x = *(const float4*)(X + (size_t)m * K + k4);
    size_t rb = (size_t)m * 2 * K;
    float xs[4] = {x.x, x.y, x.z, x.w};
#pragma unroll
    for (int j = 0; j < 4; j++) {
        __half h = __float2half(xs[j]);
        __half l = __float2half(xs[j] - __half2float(h));
        A2[rb + k4 + j] = h;
        A2[rb + K + k4 + j] = l;
    }
}

// 2-term fp16: B'^T [N, 2K] from W [K, N]: [hi | hi]
__global__ void convB2h_kernel(const float* __restrict__ W, __half* __restrict__ B2,
                               int K, int N) {
    __shared__ float s[32][33];
    int tx = threadIdx.x & 31, ty = threadIdx.x >> 5;
    int n0 = blockIdx.x * 32, k0 = blockIdx.y * 32;
#pragma unroll
    for (int j = 0; j < 4; j++)
        s[ty + 8 * j][tx] = W[(size_t)(k0 + ty + 8 * j) * N + n0 + tx];
    __syncthreads();
#pragma unroll
    for (int j = 0; j < 4; j++) {
        int r = ty + 8 * j;
        int n = n0 + r;
        int k = k0 + tx;
        __half h = __float2half(s[tx][r]);
        size_t rb = (size_t)n * 2 * K;
        B2[rb + k] = h;
        B2[rb + K + k] = h;
    }
}

// ------------------------- HMMA GEMM (mma.sync) ----------------------------
// C[M,N] fp32 = A'[M,K3] x B'[N,K3]^T. Tile 128x256, BK=64, 3-stage cp.async.
// Warp layout 2x4 (each warp 64x64). FLAGS: 1=+bias, 2=+res, 4=exact gelu.
// FP16: 0 = bf16 operands, 1 = fp16 operands.
#define TG_STAGE 49152          // A 16KB + B 32KB per stage
#define TG_DSMEM (3 * TG_STAGE)

template <int FLAGS, int FP16>
__global__ void __launch_bounds__(256) tgemm(const void* __restrict__ Av,
                                             const void* __restrict__ Bv,
                                             float* __restrict__ C,
                                             const float* __restrict__ bias,
                                             const float* __restrict__ res,
                                             int N, int K3) {
    extern __shared__ char sm_[];
    int tid = threadIdx.x, lane = tid & 31, wid = tid >> 5;
    int wm = wid >> 2, wn = wid & 3;
    int bx = blockIdx.x, by = blockIdx.y;
    const char* Ag = (const char*)Av + (size_t)(by * 128) * K3 * 2;
    const char* Bg = (const char*)Bv + (size_t)(bx * 256) * K3 * 2;
    size_t rs = (size_t)K3 * 2;
    int nk = K3 >> 6;
    uint32_t sbase = smem_u32(sm_);

    auto load_stage = [&](int kc, int s) {
        uint32_t sb = sbase + s * TG_STAGE;
#pragma unroll
        for (int j = 0; j < 12; j++) {
            int idx = tid + j * 256;       // 0..3071
            if (idx < 1024) {              // A: 128 rows x 8 segs
                int r = idx >> 3, seg = idx & 7;
                const char* g = Ag + (size_t)r * rs + (size_t)kc * 128 + seg * 16;
                cp_async16(sb + swz128(r * 128 + seg * 16), g);
            } else {                       // B: 256 rows x 8 segs
                int t = idx - 1024;
                int r = t >> 3, seg = t & 7;
                const char* g = Bg + (size_t)r * rs + (size_t)kc * 128 + seg * 16;
                cp_async16(sb + 16384 + swz128(r * 128 + seg * 16), g);
            }
        }
        asm volatile("cp.async.commit_group;");
    };

    float acc[4][8][4];
#pragma unroll
    for (int a = 0; a < 4; a++)
#pragma unroll
        for (int b = 0; b < 8; b++)
#pragma unroll
            for (int c = 0; c < 4; c++) acc[a][b][c] = 0.f;

    load_stage(0, 0);
    load_stage(1, 1);

    int mat = lane >> 3, rin = lane & 7;
    for (int i = 0; i < nk; i++) {
        __syncthreads();  // all warps done computing stage (i+2)%3 (iter i-1)
        if (i + 2 < nk) load_stage(i + 2, (i + 2) % 3);
        if (i + 2 < nk)       asm volatile("cp.async.wait_group 2;");
        else if (i + 1 < nk)  asm volatile("cp.async.wait_group 1;");
        else                  asm volatile("cp.async.wait_group 0;");
        __syncthreads();

        uint32_t sa = sbase + (i % 3) * TG_STAGE;
        uint32_t sb = sa + 16384;
#pragma unroll
        for (int ks = 0; ks < 4; ks++) {
            uint32_t af[4][4], bf[8][2];
#pragma unroll
            for (int mt = 0; mt < 4; mt++) {
                int row = wm * 64 + mt * 16 + (mat & 1) * 8 + rin;
                int kb = 2 * ks + (mat >> 1);
                ldm_x4(af[mt][0], af[mt][1], af[mt][2], af[mt][3],
                       sa + swz128(row * 128 + kb * 16));
            }
#pragma unroll
            for (int g = 0; g < 4; g++) {
                int nt = 2 * g + (mat >> 1);
                int n = wn * 64 + nt * 8 + rin;
                int kb = 2 * ks + (mat & 1);
                uint32_t b0, b1, b2, b3;
                ldm_x4(b0, b1, b2, b3, sb + swz128(n * 128 + kb * 16));
                bf[2 * g][0] = b0; bf[2 * g][1] = b1;
                bf[2 * g + 1][0] = b2; bf[2 * g + 1][1] = b3;
            }
#pragma unroll
            for (int mt = 0; mt < 4; mt++)
#pragma unroll
                for (int nt = 0; nt < 8; nt++) {
                    if (FP16)
                        mma_fp16(acc[mt][nt], af[mt][0], af[mt][1], af[mt][2], af[mt][3],
                                 bf[nt][0], bf[nt][1]);
                    else
                        mma_bf16(acc[mt][nt], af[mt][0], af[mt][1], af[mt][2], af[mt][3],
                                 bf[nt][0], bf[nt][1]);
                }
        }
    }

    // epilogue: direct float2 stores
#pragma unroll
    for (int mt = 0; mt < 4; mt++) {
        int gr0 = by * 128 + wm * 64 + mt * 16 + (lane >> 2);
#pragma unroll
        for (int nt = 0; nt < 8; nt++) {
            int gc = bx * 256 + wn * 64 + nt * 8 + (lane & 3) * 2;
            float v0 = acc[mt][nt][0], v1 = acc[mt][nt][1];
            float v2 = acc[mt][nt][2], v3 = acc[mt][nt][3];
            if (FLAGS & 1) {
                float b0 = bias[gc], b1 = bias[gc + 1];
                v0 += b0; v1 += b1; v2 += b0; v3 += b1;
            }
            if (FLAGS & 4) {
                v0 = 0.5f * v0 * (1.0f + erff(v0 * 0.70710678118654752f));
                v1 = 0.5f * v1 * (1.0f + erff(v1 * 0.70710678118654752f));
                v2 = 0.5f * v2 * (1.0f + erff(v2 * 0.70710678118654752f));
                v3 = 0.5f * v3 * (1.0f + erff(v3 * 0.70710678118654752f));
            }
            if (FLAGS & 2) {
                const float* r0p = res + (size_t)gr0 * N + gc;
                const float* r1p = res + (size_t)(gr0 + 8) * N + gc;
                v0 += r0p[0]; v1 += r0p[1]; v2 += r1p[0]; v3 += r1p[1];
            }
            float2 o0 = {v0, v1}, o1 = {v2, v3};
            *(float2*)(C + (size_t)gr0 * N + gc) = o0;
            *(float2*)(C + (size_t)(gr0 + 8) * N + gc) = o1;
        }
    }
}

// ------------------------- LSH hashing ------------------------------------
__global__ void hash_kernel(const float* __restrict__ qk, const float* __restrict__ rot,
                            unsigned char* __restrict__ bucket) {
    __shared__ float srow[8][128];
    int warp = threadIdx.x >> 5, lane = threadIdx.x & 31;
    int rid = blockIdx.x * 8 + warp;
    int bh = rid >> 12, t = rid & 4095;
    int b = bh >> 3, h = bh & 7;
    const float* qp = qk + ((size_t)(b * TT + t)) * DIMC + h * DHH;
#pragma unroll
    for (int j = 0; j < 4; j++) srow[warp][lane + j * 32] = qp[lane + j * 32];
    __syncwarp();
#pragma unroll
    for (int hh = 0; hh < 4; hh++) {
        float acc = 0.f;
#pragma unroll 8
        for (int f = 0; f < 128; f++)
            acc = fmaf(srow[warp][f], rot[f * 128 + hh * 32 + lane], acc);
        float val = fmaxf(acc, -acc);
        int idx = (acc >= -acc) ? lane : 32 + lane;
#pragma unroll
        for (int o = 16; o; o >>= 1) {
            float ov = __shfl_down_sync(~0u, val, o);
            int oi = __shfl_down_sync(~0u, idx, o);
            if (ov > val || (ov == val && oi < idx)) { val = ov; idx = oi; }
        }
        if (lane == 0) bucket[((size_t)bh * 4 + hh) * TT + t] = (unsigned char)idx;
    }
}

// ------------------------- stable counting sort per (bh, hash) ------------
__global__ void sort_kernel(const unsigned char* __restrict__ bucket,
                            int* __restrict__ st, int* __restrict__ undo) {
    __shared__ unsigned char sb[4096];
    __shared__ unsigned short hist[64 * 257];
    __shared__ int base[65];
    __shared__ int tot[64];
    int blk = blockIdx.x;
    int tid = threadIdx.x;
    const unsigned char* bp = bucket + (size_t)blk * TT;
    for (int i = tid; i < 4096; i += 256) sb[i] = bp[i];
    for (int i = tid; i < 64 * 257; i += 256) hist[i] = 0;
    __syncthreads();
#pragma unroll
    for (int j = 0; j < 16; j++) {
        int t = tid * 16 + j;
        int b = sb[t];
        hist[b * 257 + tid]++;
    }
    __syncthreads();
    if (tid < 64) {
        unsigned int run = 0;
        int b = tid;
        for (int th = 0; th < 256; th++) {
            unsigned short tmp = hist[b * 257 + th];
            hist[b * 257 + th] = (unsigned short)run;
            run += tmp;
        }
        tot[b] = (int)run;
    }
    __syncthreads();
    if (tid == 0) {
        base[0] = 0;
        for (int b = 0; b < 64; b++) base[b + 1] = base[b] + tot[b];
    }
    __syncthreads();
#pragma unroll
    for (int j = 0; j < 16; j++) {
        int t = tid * 16 + j;
        int b = sb[t];
        int pos = base[b] + hist[b * 257 + tid];
        hist[b * 257 + tid]++;
        st[(size_t)blk * TT + pos] = t;
        undo[(size_t)blk * TT + t] = pos;
    }
}

// ------------------------- chunked LSH attention ---------------------------
#define ATTN_SMEM ((128 * 133 + 64 * 132 + 128) * 4 + 128 * 4)
__global__ void __launch_bounds__(256) attn_kernel(const float* __restrict__ qk,
                                                   const float* __restrict__ v,
                                                   const int* __restrict__ st,
                                                   float* __restrict__ so,
                                                   float* __restrict__ slog) {
    extern __shared__ float sm[];
    float* s_k = sm;
    float* s_p = s_k + 128 * 133;
    float* s_rn = s_p + 64 * 132;
    int* s_pk = (int*)(s_rn + 128);
    int tid = threadIdx.x;
    int bh = blockIdx.x >> 8;
    int c = blockIdx.x & 255;
    int prev = (c + 255) & 255;
    int b = bh >> 3, h = bh & 7;
    const int* stb = st + (size_t)bh * (NHSH * TT);
    if (tid < 64) s_pk[tid] = stb[c * 64 + tid];
    else if (tid < 128) s_pk[tid] = stb[prev * 64 + (tid - 64)];
    __syncthreads();
#pragma unroll
    for (int rep = 0; rep < 16; rep++) {
        int idx = tid + rep * 256;
        int j = idx >> 5, d4 = idx & 31;
        const float* kp = qk + ((size_t)(b * TT + s_pk[j])) * DIMC + h * DHH + d4 * 4;
        float4 kv = *(const float4*)kp;
        float* dst = s_k + j * 133 + d4 * 4;
        dst[0] = kv.x; dst[1] = kv.y; dst[2] = kv.z; dst[3] = kv.w;
    }
    __syncthreads();
    if (tid < 128) {
        float sq = 0.f;
#pragma unroll 8
        for (int d = 0; d < 128; d++) {
            float x = s_k[tid * 133 + d];
            sq += x * x;
        }
        float nrm = sqrtf(sq);
        s_rn[tid] = 1.0f / fmaxf(nrm, 1e-12f);
    }
    __syncthreads();
    int lane = tid & 31, w = tid >> 5;
    const float SC = 0.08838834764831845f;
    for (int p2 = 0; p2 < 4; p2++) {
        int i0 = w * 8 + p2 * 2;
        float acc0[4] = {0, 0, 0, 0}, acc1[4] = {0, 0, 0, 0};
        const float* k0 = s_k + i0 * 133;
        const float* k1 = s_k + (i0 + 1) * 133;
        for (int d = 0; d < 128; d++) {
            float q0 = k0[d], q1 = k1[d];
#pragma unroll
            for (int cc = 0; cc < 4; cc++) {
                float kv = s_k[(lane + 32 * cc) * 133 + d];
                acc0[cc] = fmaf(q0, kv, acc0[cc]);
                acc1[cc] = fmaf(q1, kv, acc1[cc]);
            }
        }
        int pq0 = s_pk[i0], pq1 = s_pk[i0 + 1];
#pragma unroll
        for (int cc = 0; cc < 4; cc++) {
            int j = lane + 32 * cc;
            float rn = s_rn[j];
            int pkj = s_pk[j];
            s_p[i0 * 132 + j] = (pq0 == pkj) ? -5e4f : acc0[cc] * rn * SC;
            s_p[(i0 + 1) * 132 + j] = (pq1 == pkj) ? -5e4f : acc1[cc] * rn * SC;
        }
    }
    __syncthreads();
    for (int rr = 0; rr < 8; rr++) {
        int i = w * 8 + rr;
        float vv[4];
#pragma unroll
        for (int cc = 0; cc < 4; cc++) vv[cc] = s_p[i * 132 + lane + 32 * cc];
        float m = fmaxf(fmaxf(vv[0], vv[1]), fmaxf(vv[2], vv[3]));
#pragma unroll
        for (int o = 16; o; o >>= 1) m = fmaxf(m, __shfl_xor_sync(~0u, m, o));
        float sum = 0.f;
#pragma unroll
        for (int cc = 0; cc < 4; cc++) {
            vv[cc] = expf(vv[cc] - m);
            sum += vv[cc];
        }
#pragma unroll
        for (int o = 16; o; o >>= 1) sum += __shfl_xor_sync(~0u, sum, o);
        float lse = m + logf(sum);
        float isum = 1.0f / sum;
#pragma unroll
        for (int cc = 0; cc < 4; cc++) s_p[i * 132 + lane + 32 * cc] = vv[cc] * isum;
        if (lane == 0) slog[(size_t)bh * (NHSH * TT) + c * 64 + i] = lse;
    }
    __syncthreads();
    float acc[8][4];
#pragma unroll
    for (int ii = 0; ii < 8; ii++)
#pragma unroll
        for (int dd = 0; dd < 4; dd++) acc[ii][dd] = 0.f;
    for (int j = 0; j < 128; j++) {
        const float* vp = v + ((size_t)(b * TT + s_pk[j])) * DIMC + h * DHH;
        float v0 = vp[lane], v1 = vp[lane + 32], v2 = vp[lane + 64], v3 = vp[lane + 96];
#pragma unroll
        for (int ii = 0; ii < 8; ii++) {
            float pij = s_p[(w + 8 * ii) * 132 + j];
            acc[ii][0] = fmaf(pij, v0, acc[ii][0]);
            acc[ii][1] = fmaf(pij, v1, acc[ii][1]);
            acc[ii][2] = fmaf(pij, v2, acc[ii][2]);
            acc[ii][3] = fmaf(pij, v3, acc[ii][3]);
        }
    }
#pragma unroll
    for (int ii = 0; ii < 8; ii++) {
        size_t base = ((size_t)bh * (NHSH * TT) + c * 64 + w + 8 * ii) * 128;
        so[base + lane] = acc[ii][0];
        so[base + lane + 32] = acc[ii][1];
        so[base + lane + 64] = acc[ii][2];
        so[base + lane + 96] = acc[ii][3];
    }
}

// ------------------------- combine hash rounds ----------------------------
__global__ void combine_kernel(const float* __restrict__ so, const float* __restrict__ slog,
                               const int* __restrict__ undo, float* __restrict__ attn) {
    int warp = threadIdx.x >> 5, lane = threadIdx.x & 31;
    int rid = blockIdx.x * 8 + warp;
    int bh = rid >> 12, t = rid & 4095;
    int b = bh >> 3, h = bh & 7;
    int u[4];
    float lg[4];
#pragma unroll
    for (int r = 0; r < 4; r++) {
        u[r] = undo[((size_t)bh * 4 + r) * TT + t];
        lg[r] = slog[(size_t)bh * (NHSH * TT) + r * TT + u[r]];
    }
    float m = fmaxf(fmaxf(lg[0], lg[1]), fmaxf(lg[2], lg[3]));
    float e[4];
    float s = 0.f;
#pragma unroll
    for (int r = 0; r < 4; r++) {
        e[r] = expf(lg[r] - m);
        s += e[r];
    }
    float is = 1.0f / s;
    float a0 = 0, a1 = 0, a2 = 0, a3 = 0;
#pragma unroll
    for (int r = 0; r < 4; r++) {
        const float* op = so + ((size_t)bh * (NHSH * TT) + r * TT + u[r]) * 128;
        float pr = e[r] * is;
        a0 = fmaf(pr, op[lane], a0);
        a1 = fmaf(pr, op[lane + 32], a1);
        a2 = fmaf(pr, op[lane + 64], a2);
        a3 = fmaf(pr, op[lane + 96], a3);
    }
    float* dst = attn + ((size_t)(b * TT + t)) * DIMC + h * DHH;
    dst[lane] = a0;
    dst[lane + 32] = a1;
    dst[lane + 64] = a2;
    dst[lane + 96] = a3;
}

// ------------------------- final y1 + y2 ----------------------------------
__global__ void add_out(float* __restrict__ out) {
    int i = blockIdx.x * blockDim.x + threadIdx.x;
    float4 a = ((float4*)g_x1)[i];
    float4 b = ((float4*)g_x2)[i];
    float4 o;
    o.x = a.x + b.x; o.y = a.y + b.y; o.z = a.z + b.z; o.w = a.w + b.w;
    ((float4*)out)[i] = o;
}

// ------------------------- launch -----------------------------------------
extern "C" void kernel_launch(void* const* d_in, const int* in_sizes, int n_in,
                              void* d_out, int out_size) {
    const float* x = (const float*)d_in[0];
    const float* ln1g = (const float*)d_in[1];
    const float* ln1b = (const float*)d_in[2];
    const float* Wqk = (const float*)d_in[3];
    const float* Wv = (const float*)d_in[4];
    const float* Wo = (const float*)d_in[5];
    const float* bo = (const float*)d_in[6];
    const float* ln2g = (const float*)d_in[7];
    const float* ln2b = (const float*)d_in[8];
    const float* W1 = (const float*)d_in[9];
    const float* b1 = (const float*)d_in[10];
    const float* W2 = (const float*)d_in[11];
    const float* b2 = (const float*)d_in[12];
    const float* rot = (const float*)d_in[13];

    float *px1, *px2, *pxn, *pqk, *pv, *pattn, *pff, *pso, *pslog;
    int *pst, *pundo;
    unsigned char* pbkt;
    __nv_bfloat16 *pA3, *pB3;
    cudaGetSymbolAddress((void**)&px1, g_x1);
    cudaGetSymbolAddress((void**)&px2, g_x2);
    cudaGetSymbolAddress((void**)&pxn, g_xn);
    cudaGetSymbolAddress((void**)&pqk, g_qk);
    cudaGetSymbolAddress((void**)&pv, g_v);
    cudaGetSymbolAddress((void**)&pattn, g_attn);
    cudaGetSymbolAddress((void**)&pff, g_ff);
    cudaGetSymbolAddress((void**)&pso, g_so);
    cudaGetSymbolAddress((void**)&pslog, g_slog);
    cudaGetSymbolAddress((void**)&pst, g_st);
    cudaGetSymbolAddress((void**)&pundo, g_undo);
    cudaGetSymbolAddress((void**)&pbkt, g_bucket);
    cudaGetSymbolAddress((void**)&pA3, g_A3);
    cudaGetSymbolAddress((void**)&pB3, g_B3);
    __half* pA2h = (__half*)pA3;
    __half* pB2h = (__half*)pB3;

    cudaFuncSetAttribute(attn_kernel, cudaFuncAttributeMaxDynamicSharedMemorySize, ATTN_SMEM);
    cudaFuncSetAttribute(tgemm<0, 0>, cudaFuncAttributeMaxDynamicSharedMemorySize, TG_DSMEM);
    cudaFuncSetAttribute(tgemm<3, 0>, cudaFuncAttributeMaxDynamicSharedMemorySize, TG_DSMEM);
    cudaFuncSetAttribute(tgemm<5, 0>, cudaFuncAttributeMaxDynamicSharedMemorySize, TG_DSMEM);
    cudaFuncSetAttribute(tgemm<0, 1>, cudaFuncAttributeMaxDynamicSharedMemorySize, TG_DSMEM);
    cudaFuncSetAttribute(tgemm<3, 1>, cudaFuncAttributeMaxDynamicSharedMemorySize, TG_DSMEM);
    cudaFuncSetAttribute(tgemm<5, 1>, cudaFuncAttributeMaxDynamicSharedMemorySize, TG_DSMEM);

    init_xx<<<TOK * DIMC / 4 / 256, 256>>>(x);

    for (int L = 0; L < 2; L++) {
        const float* wqk = Wqk + (size_t)L * DIMC * DIMC;
        const float* wv = Wv + (size_t)L * DIMC * DIMC;
        const float* wo = Wo + (size_t)L * DIMC * DIMC;
        const float* w1 = W1 + (size_t)L * DIMC * FFD;
        const float* w2 = W2 + (size_t)L * FFD * DIMC;
        const float* rl = rot + (size_t)L * DHH * NHSH * (NBKT / 2);

        // attn input projection: qk (always 3-term bf16 — feeds hashing)
        ln_kernel<<<TOK, 256>>>(px2, ln1g + L * DIMC, ln1b + L * DIMC, pxn);
        convA_kernel<<<TOK * DIMC / 4 / 256, 256>>>(pxn, pA3, DIMC);
        convB_kernel<<<dim3(DIMC / 32, DIMC / 32), 256>>>(wqk, pB3, DIMC, DIMC);
        tgemm<0, 0><<<dim3(4, 64), 256, TG_DSMEM>>>(pA3, pB3, pqk, nullptr, nullptr, 1024, 3072);

        if (L == 0) {
            // layer-1: everything upstream of layer-2 hashing -> 3-term bf16
            convB_kernel<<<dim3(DIMC / 32, DIMC / 32), 256>>>(wv, pB3, DIMC, DIMC);
            tgemm<0, 0><<<dim3(4, 64), 256, TG_DSMEM>>>(pA3, pB3, pv, nullptr, nullptr, 1024, 3072);

            hash_kernel<<<TOK, 256>>>(pqk, rl, pbkt);
            sort_kernel<<<64, 256>>>(pbkt, pst, pundo);
            attn_kernel<<<BHC * NCHK, 256, ATTN_SMEM>>>(pqk, pv, pst, pso, pslog);
            combine_kernel<<<TOK, 256>>>(pso, pslog, pundo, pattn);

            convA_kernel<<<TOK * DIMC / 4 / 256, 256>>>(pattn, pA3, DIMC);
            convB_kernel<<<dim3(DIMC / 32, DIMC / 32), 256>>>(wo, pB3, DIMC, DIMC);
            tgemm<3, 0><<<dim3(4, 64), 256, TG_DSMEM>>>(pA3, pB3, px1, bo + L * DIMC, px1, 1024, 3072);

            ln_kernel<<<TOK, 256>>>(px1, ln2g + L * DIMC, ln2b + L * DIMC, pxn);
            convA_kernel<<<TOK * DIMC / 4 / 256, 256>>>(pxn, pA3, DIMC);
            convB_kernel<<<dim3(FFD / 32, DIMC / 32), 256>>>(w1, pB3, DIMC, FFD);
            tgemm<5, 0><<<dim3(16, 64), 256, TG_DSMEM>>>(pA3, pB3, pff, b1 + L * FFD, nullptr, 4096, 3072);
            convA_kernel<<<TOK * FFD / 4 / 256, 256>>>(pff, pA3, FFD);
            convB_kernel<<<dim3(DIMC / 32, FFD / 32), 256>>>(w2, pB3, FFD, DIMC);
            tgemm<3, 0><<<dim3(4, 64), 256, TG_DSMEM>>>(pA3, pB3, px2, b2 + L * DIMC, px2, 1024, 12288);
        } else {
            // layer-2: V/Wo/W1/W2 feed no hashing -> 2-term fp16 (2K instead of 3K)
            convA2h_kernel<<<TOK * DIMC / 4 / 256, 256>>>(pxn, pA2h, DIMC);
            convB2h_kernel<<<dim3(DIMC / 32, DIMC / 32), 256>>>(wv, pB2h, DIMC, DIMC);
            tgemm<0, 1><<<dim3(4, 64), 256, TG_DSMEM>>>(pA2h, pB2h, pv, nullptr, nullptr, 1024, 2048);

            hash_kernel<<<TOK, 256>>>(pqk, rl, pbkt);
            sort_kernel<<<64, 256>>>(pbkt, pst, pundo);
            attn_kernel<<<BHC * NCHK, 256, ATTN_SMEM>>>(pqk, pv, pst, pso, pslog);
            combine_kernel<<<TOK, 256>>>(pso, pslog, pundo, pattn);

            convA2h_kernel<<<TOK * DIMC / 4 / 256, 256>>>(pattn, pA2h, DIMC);
            convB2h_kernel<<<dim3(DIMC / 32, DIMC / 32), 256>>>(wo, pB2h, DIMC, DIMC);
            tgemm<3, 1><<<dim3(4, 64), 256, TG_DSMEM>>>(pA2h, pB2h, px1, bo + L * DIMC, px1, 1024, 2048);

            ln_kernel<<<TOK, 256>>>(px1, ln2g + L * DIMC, ln2b + L * DIMC, pxn);
            convA2h_kernel<<<TOK * DIMC / 4 / 256, 256>>>(pxn, pA2h, DIMC);
            convB2h_kernel<<<dim3(FFD / 32, DIMC / 32), 256>>>(w1, pB2h, DIMC, FFD);
            tgemm<5, 1><<<dim3(16, 64), 256, TG_DSMEM>>>(pA2h, pB2h, pff, b1 + L * FFD, nullptr, 4096, 2048);
            convA2h_kernel<<<TOK * FFD / 4 / 256, 256>>>(pff, pA2h, FFD);
            convB2h_kernel<<<dim3(DIMC / 32, FFD / 32), 256>>>(w2, pB2h, FFD, DIMC);
            tgemm<3, 1><<<dim3(4, 64), 256, TG_DSMEM>>>(pA2h, pB2h, px2, b2 + L * DIMC, px2, 1024, 8192);
        }
    }

    add_out<<<TOK * DIMC / 4 / 256, 256>>>((float*)d_out);
}

// round 11
// speedup vs baseline: 2.1838x; 1.0116x over previous
#include <cuda_runtime.h>
#include <cuda_bf16.h>
#include <cuda_fp16.h>
#include <math.h>
#include <stdint.h>

#define DIMC 1024
#define TT   4096
#define BBAT 2
#define HH   8
#define DHH  128
#define BHC  16
#define TOK  8192
#define NHSH 4
#define NBKT 64
#define NCHK 256
#define FFD  4096

// ------------------------- scratch (device globals, no allocs) -------------
__device__ float g_x1[TOK * DIMC];
__device__ float g_x2[TOK * DIMC];
__device__ float g_xn[TOK * DIMC];
__device__ float g_qk[TOK * DIMC];
__device__ float g_v[TOK * DIMC];
__device__ float g_attn[TOK * DIMC];
__device__ float g_ff[TOK * FFD];
__device__ float g_so[BHC * NHSH * TT * DHH];
__device__ float g_slog[BHC * NHSH * TT];
__device__ int g_st[BHC * NHSH * TT];
__device__ int g_undo[BHC * NHSH * TT];
__device__ unsigned char g_bucket[BHC * NHSH * TT];
// split operand buffers (uint4 for 16B alignment)
__device__ uint4 g_A3[(size_t)TOK * 3 * FFD * 2 / 16];
__device__ uint4 g_B3[(size_t)FFD * 3 * DIMC * 2 / 16];

// ------------------------- helpers ----------------------------------------
__device__ __forceinline__ uint32_t smem_u32(const void* p) {
    uint32_t a;
    asm("{ .reg .u64 t; cvta.to.shared.u64 t, %1; cvt.u32.u64 %0, t; }" : "=r"(a) : "l"(p));
    return a;
}
__device__ __forceinline__ uint32_t swz128(uint32_t off) { return off ^ ((off >> 3) & 0x70); }

__device__ __forceinline__ void cp_async16(uint32_t so, const void* g) {
    asm volatile("cp.async.cg.shared.global [%0], [%1], 16;" :: "r"(so), "l"(g));
}
__device__ __forceinline__ void ldm_x4(uint32_t& r0, uint32_t& r1, uint32_t& r2, uint32_t& r3,
                                       uint32_t a) {
    asm volatile("ldmatrix.sync.aligned.m8n8.x4.shared.b16 {%0,%1,%2,%3}, [%4];"
                 : "=r"(r0), "=r"(r1), "=r"(r2), "=r"(r3) : "r"(a));
}
__device__ __forceinline__ void mma_bf16(float* c, uint32_t a0, uint32_t a1, uint32_t a2,
                                         uint32_t a3, uint32_t b0, uint32_t b1) {
    asm volatile(
        "mma.sync.aligned.m16n8k16.row.col.f32.bf16.bf16.f32 "
        "{%0,%1,%2,%3}, {%4,%5,%6,%7}, {%8,%9}, {%0,%1,%2,%3};"
        : "+f"(c[0]), "+f"(c[1]), "+f"(c[2]), "+f"(c[3])
        : "r"(a0), "r"(a1), "r"(a2), "r"(a3), "r"(b0), "r"(b1));
}
__device__ __forceinline__ void mma_fp16(float* c, uint32_t a0, uint32_t a1, uint32_t a2,
                                         uint32_t a3, uint32_t b0, uint32_t b1) {
    asm volatile(
        "mma.sync.aligned.m16n8k16.row.col.f32.f16.f16.f32 "
        "{%0,%1,%2,%3}, {%4,%5,%6,%7}, {%8,%9}, {%0,%1,%2,%3};"
        : "+f"(c[0]), "+f"(c[1]), "+f"(c[2]), "+f"(c[3])
        : "r"(a0), "r"(a1), "r"(a2), "r"(a3), "r"(b0), "r"(b1));
}
// packed fp32x2 fma (B300 FFMA2) — full fp32 precision per lane
__device__ __forceinline__ void fma2(unsigned long long& d, unsigned long long a,
                                     unsigned long long b) {
    asm("fma.rn.f32x2 %0, %1, %2, %0;" : "+l"(d) : "l"(a), "l"(b));
}
__device__ __forceinline__ unsigned long long packf2(float lo, float hi) {
    unsigned long long r;
    asm("mov.b64 %0, {%1, %2};" : "=l"(r) : "f"(lo), "f"(hi));
    return r;
}
__device__ __forceinline__ float sumf2(unsigned long long v) {
    float lo, hi;
    asm("mov.b64 {%0, %1}, %2;" : "=f"(lo), "=f"(hi) : "l"(v));
    return lo + hi;
}

// ------------------------- init: x1 = x2 = x ------------------------------
__global__ void init_xx(const float* __restrict__ x) {
    int i = blockIdx.x * blockDim.x + threadIdx.x;
    float4 v = ((const float4*)x)[i];
    ((float4*)g_x1)[i] = v;
    ((float4*)g_x2)[i] = v;
}

// ------------------------- layernorm --------------------------------------
__global__ void ln_kernel(const float* __restrict__ in, const float* __restrict__ g,
                          const float* __restrict__ b, float* __restrict__ out) {
    int row = blockIdx.x;
    int tid = threadIdx.x;
    const float* p = in + (size_t)row * DIMC;
    float v[4];
    float s = 0.f, sq = 0.f;
#pragma unroll
    for (int j = 0; j < 4; j++) {
        float x = p[tid + j * 256];
        v[j] = x;
        s += x;
        sq += x * x;
    }
#pragma unroll
    for (int o = 16; o; o >>= 1) {
        s += __shfl_xor_sync(~0u, s, o);
        sq += __shfl_xor_sync(~0u, sq, o);
    }
    __shared__ float rs[8], rq[8];
    if ((tid & 31) == 0) { rs[tid >> 5] = s; rq[tid >> 5] = sq; }
    __syncthreads();
    float S = 0.f, Q = 0.f;
#pragma unroll
    for (int w = 0; w < 8; w++) { S += rs[w]; Q += rq[w]; }
    float mean = S * (1.0f / DIMC);
    float var = Q * (1.0f / DIMC) - mean * mean;
    float inv = rsqrtf(var + 1e-5f);
#pragma unroll
    for (int j = 0; j < 4; j++) {
        int c = tid + j * 256;
        out[(size_t)row * DIMC + c] = (v[j] - mean) * inv * g[c] + b[c];
    }
}

// ------------------------- split conversions --------------------------
// 3-term bf16: A' [M, 3K]: [hi | hi | lo]
__global__ void convA_kernel(const float* __restrict__ X, __nv_bfloat16* __restrict__ A3, int K) {
    int lin = blockIdx.x * blockDim.x + threadIdx.x;
    int kq = K >> 2;
    int m = lin / kq;
    int k4 = (lin - m * kq) * 4;
    float4 x = *(const float4*)(X + (size_t)m * K + k4);
    size_t rb = (size_t)m * 3 * K;
    float xs[4] = {x.x, x.y, x.z, x.w};
#pragma unroll
    for (int j = 0; j < 4; j++) {
        __nv_bfloat16 h = __float2bfloat16(xs[j]);
        __nv_bfloat16 l = __float2bfloat16(xs[j] - __bfloat162float(h));
        A3[rb + k4 + j] = h;
        A3[rb + K + k4 + j] = h;
        A3[rb + 2 * K + k4 + j] = l;
    }
}

// 3-term bf16: B'^T [N, 3K] from W [K, N]: [hi | lo | hi]
__global__ void convB_kernel(const float* __restrict__ W, __nv_bfloat16* __restrict__ B3,
                             int K, int N) {
    __shared__ float s[32][33];
    int tx = threadIdx.x & 31, ty = threadIdx.x >> 5;
    int n0 = blockIdx.x * 32, k0 = blockIdx.y * 32;
#pragma unroll
    for (int j = 0; j < 4; j++)
        s[ty + 8 * j][tx] = W[(size_t)(k0 + ty + 8 * j) * N + n0 + tx];
    __syncthreads();
#pragma unroll
    for (int j = 0; j < 4; j++) {
        int r = ty + 8 * j;
        int n = n0 + r;
        int k = k0 + tx;
        float x = s[tx][r];
        __nv_bfloat16 h = __float2bfloat16(x);
        __nv_bfloat16 l = __float2bfloat16(x - __bfloat162float(h));
        size_t rb = (size_t)n * 3 * K;
        B3[rb + k] = h;
        B3[rb + K + k] = l;
        B3[rb + 2 * K + k] = h;
    }
}

// 2-term fp16: A' [M, 2K]: [hi | lo]
__global__ void convA2h_kernel(const float* __restrict__ X, __half* __restrict__ A2, int K) {
    int lin = blockIdx.x * blockDim.x + threadIdx.x;
    int kq = K >> 2;
    int m = lin / kq;
    int k4 = (lin - m * kq) * 4;
    float4 x = *(const float4*)(X + (size_t)m * K + k4);
    size_t rb = (size_t)m * 2 * K;
    float xs[4] = {x.x, x.y, x.z, x.w};
#pragma unroll
    for (int j = 0; j < 4; j++) {
        __half h = __float2half(xs[j]);
        __half l = __float2half(xs[j] - __half2float(h));
        A2[rb + k4 + j] = h;
        A2[rb + K + k4 + j] = l;
    }
}

// 2-term fp16: B'^T [N, 2K] from W [K, N]: [hi | hi]
__global__ void convB2h_kernel(const float* __restrict__ W, __half* __restrict__ B2,
                               int K, int N) {
    __shared__ float s[32][33];
    int tx = threadIdx.x & 31, ty = threadIdx.x >> 5;
    int n0 = blockIdx.x * 32, k0 = blockIdx.y * 32;
#pragma unroll
    for (int j = 0; j < 4; j++)
        s[ty + 8 * j][tx] = W[(size_t)(k0 + ty + 8 * j) * N + n0 + tx];
    __syncthreads();
#pragma unroll
    for (int j = 0; j < 4; j++) {
        int r = ty + 8 * j;
        int n = n0 + r;
        int k = k0 + tx;
        __half h = __float2half(s[tx][r]);
        size_t rb = (size_t)n * 2 * K;
        B2[rb + k] = h;
        B2[rb + K + k] = h;
    }
}

// ------------------------- HMMA GEMM (mma.sync) ----------------------------
// C[M,N] fp32 = A'[M,K3] x B'[N,K3]^T. Tile 128x256, BK=64, 3-stage cp.async.
// Warp layout 2x4 (each warp 64x64). FLAGS: 1=+bias, 2=+res, 4=exact gelu.
// FP16: 0 = bf16 operands, 1 = fp16 operands.
#define TG_STAGE 49152          // A 16KB + B 32KB per stage
#define TG_DSMEM (3 * TG_STAGE)

template <int FLAGS, int FP16>
__global__ void __launch_bounds__(256) tgemm(const void* __restrict__ Av,
                                             const void* __restrict__ Bv,
                                             float* __restrict__ C,
                                             const float* __restrict__ bias,
                                             const float* __restrict__ res,
                                             int N, int K3) {
    extern __shared__ char sm_[];
    int tid = threadIdx.x, lane = tid & 31, wid = tid >> 5;
    int wm = wid >> 2, wn = wid & 3;
    int bx = blockIdx.x, by = blockIdx.y;
    const char* Ag = (const char*)Av + (size_t)(by * 128) * K3 * 2;
    const char* Bg = (const char*)Bv + (size_t)(bx * 256) * K3 * 2;
    size_t rs = (size_t)K3 * 2;
    int nk = K3 >> 6;
    uint32_t sbase = smem_u32(sm_);

    auto load_stage = [&](int kc, int s) {
        uint32_t sb = sbase + s * TG_STAGE;
#pragma unroll
        for (int j = 0; j < 12; j++) {
            int idx = tid + j * 256;       // 0..3071
            if (idx < 1024) {              // A: 128 rows x 8 segs
                int r = idx >> 3, seg = idx & 7;
                const char* g = Ag + (size_t)r * rs + (size_t)kc * 128 + seg * 16;
                cp_async16(sb + swz128(r * 128 + seg * 16), g);
            } else {                       // B: 256 rows x 8 segs
                int t = idx - 1024;
                int r = t >> 3, seg = t & 7;
                const char* g = Bg + (size_t)r * rs + (size_t)kc * 128 + seg * 16;
                cp_async16(sb + 16384 + swz128(r * 128 + seg * 16), g);
            }
        }
        asm volatile("cp.async.commit_group;");
    };

    float acc[4][8][4];
#pragma unroll
    for (int a = 0; a < 4; a++)
#pragma unroll
        for (int b = 0; b < 8; b++)
#pragma unroll
            for (int c = 0; c < 4; c++) acc[a][b][c] = 0.f;

    load_stage(0, 0);
    load_stage(1, 1);

    int mat = lane >> 3, rin = lane & 7;
    for (int i = 0; i < nk; i++) {
        __syncthreads();  // all warps done computing stage (i+2)%3 (iter i-1)
        if (i + 2 < nk) load_stage(i + 2, (i + 2) % 3);
        if (i + 2 < nk)       asm volatile("cp.async.wait_group 2;");
        else if (i + 1 < nk)  asm volatile("cp.async.wait_group 1;");
        else                  asm volatile("cp.async.wait_group 0;");
        __syncthreads();

        uint32_t sa = sbase + (i % 3) * TG_STAGE;
        uint32_t sb = sa + 16384;
#pragma unroll
        for (int ks = 0; ks < 4; ks++) {
            uint32_t af[4][4], bf[8][2];
#pragma unroll
            for (int mt = 0; mt < 4; mt++) {
                int row = wm * 64 + mt * 16 + (mat & 1) * 8 + rin;
                int kb = 2 * ks + (mat >> 1);
                ldm_x4(af[mt][0], af[mt][1], af[mt][2], af[mt][3],
                       sa + swz128(row * 128 + kb * 16));
            }
#pragma unroll
            for (int g = 0; g < 4; g++) {
                int nt = 2 * g + (mat >> 1);
                int n = wn * 64 + nt * 8 + rin;
                int kb = 2 * ks + (mat & 1);
                uint32_t b0, b1, b2, b3;
                ldm_x4(b0, b1, b2, b3, sb + swz128(n * 128 + kb * 16));
                bf[2 * g][0] = b0; bf[2 * g][1] = b1;
                bf[2 * g + 1][0] = b2; bf[2 * g + 1][1] = b3;
            }
#pragma unroll
            for (int mt = 0; mt < 4; mt++)
#pragma unroll
                for (int nt = 0; nt < 8; nt++) {
                    if (FP16)
                        mma_fp16(acc[mt][nt], af[mt][0], af[mt][1], af[mt][2], af[mt][3],
                                 bf[nt][0], bf[nt][1]);
                    else
                        mma_bf16(acc[mt][nt], af[mt][0], af[mt][1], af[mt][2], af[mt][3],
                                 bf[nt][0], bf[nt][1]);
                }
        }
    }

    // epilogue: direct float2 stores
#pragma unroll
    for (int mt = 0; mt < 4; mt++) {
        int gr0 = by * 128 + wm * 64 + mt * 16 + (lane >> 2);
#pragma unroll
        for (int nt = 0; nt < 8; nt++) {
            int gc = bx * 256 + wn * 64 + nt * 8 + (lane & 3) * 2;
            float v0 = acc[mt][nt][0], v1 = acc[mt][nt][1];
            float v2 = acc[mt][nt][2], v3 = acc[mt][nt][3];
            if (FLAGS & 1) {
                float b0 = bias[gc], b1 = bias[gc + 1];
                v0 += b0; v1 += b1; v2 += b0; v3 += b1;
            }
            if (FLAGS & 4) {
                v0 = 0.5f * v0 * (1.0f + erff(v0 * 0.70710678118654752f));
                v1 = 0.5f * v1 * (1.0f + erff(v1 * 0.70710678118654752f));
                v2 = 0.5f * v2 * (1.0f + erff(v2 * 0.70710678118654752f));
                v3 = 0.5f * v3 * (1.0f + erff(v3 * 0.70710678118654752f));
            }
            if (FLAGS & 2) {
                const float* r0p = res + (size_t)gr0 * N + gc;
                const float* r1p = res + (size_t)(gr0 + 8) * N + gc;
                v0 += r0p[0]; v1 += r0p[1]; v2 += r1p[0]; v3 += r1p[1];
            }
            float2 o0 = {v0, v1}, o1 = {v2, v3};
            *(float2*)(C + (size_t)gr0 * N + gc) = o0;
            *(float2*)(C + (size_t)(gr0 + 8) * N + gc) = o1;
        }
    }
}

// ------------------------- LSH hashing ------------------------------------
__global__ void hash_kernel(const float* __restrict__ qk, const float* __restrict__ rot,
                            unsigned char* __restrict__ bucket) {
    __shared__ float srow[8][128];
    int warp = threadIdx.x >> 5, lane = threadIdx.x & 31;
    int rid = blockIdx.x * 8 + warp;
    int bh = rid >> 12, t = rid & 4095;
    int b = bh >> 3, h = bh & 7;
    const float* qp = qk + ((size_t)(b * TT + t)) * DIMC + h * DHH;
#pragma unroll
    for (int j = 0; j < 4; j++) srow[warp][lane + j * 32] = qp[lane + j * 32];
    __syncwarp();
#pragma unroll
    for (int hh = 0; hh < 4; hh++) {
        float acc = 0.f;
#pragma unroll 8
        for (int f = 0; f < 128; f++)
            acc = fmaf(srow[warp][f], rot[f * 128 + hh * 32 + lane], acc);
        float val = fmaxf(acc, -acc);
        int idx = (acc >= -acc) ? lane : 32 + lane;
#pragma unroll
        for (int o = 16; o; o >>= 1) {
            float ov = __shfl_down_sync(~0u, val, o);
            int oi = __shfl_down_sync(~0u, idx, o);
            if (ov > val || (ov == val && oi < idx)) { val = ov; idx = oi; }
        }
        if (lane == 0) bucket[((size_t)bh * 4 + hh) * TT + t] = (unsigned char)idx;
    }
}

// ------------------------- stable counting sort per (bh, hash) ------------
__global__ void sort_kernel(const unsigned char* __restrict__ bucket,
                            int* __restrict__ st, int* __restrict__ undo) {
    __shared__ unsigned char sb[4096];
    __shared__ unsigned short hist[64 * 257];
    __shared__ int base[65];
    __shared__ int tot[64];
    int blk = blockIdx.x;
    int tid = threadIdx.x;
    const unsigned char* bp = bucket + (size_t)blk * TT;
    for (int i = tid; i < 4096; i += 256) sb[i] = bp[i];
    for (int i = tid; i < 64 * 257; i += 256) hist[i] = 0;
    __syncthreads();
#pragma unroll
    for (int j = 0; j < 16; j++) {
        int t = tid * 16 + j;
        int b = sb[t];
        hist[b * 257 + tid]++;
    }
    __syncthreads();
    if (tid < 64) {
        unsigned int run = 0;
        int b = tid;
        for (int th = 0; th < 256; th++) {
            unsigned short tmp = hist[b * 257 + th];
            hist[b * 257 + th] = (unsigned short)run;
            run += tmp;
        }
        tot[b] = (int)run;
    }
    __syncthreads();
    if (tid == 0) {
        base[0] = 0;
        for (int b = 0; b < 64; b++) base[b + 1] = base[b] + tot[b];
    }
    __syncthreads();
#pragma unroll
    for (int j = 0; j < 16; j++) {
        int t = tid * 16 + j;
        int b = sb[t];
        int pos = base[b] + hist[b * 257 + tid];
        hist[b * 257 + tid]++;
        st[(size_t)blk * TT + pos] = t;
        undo[(size_t)blk * TT + t] = pos;
    }
}

// ------------------------- chunked LSH attention (f32x2) -------------------
// K-tile row stride 134 floats: rows 8B-aligned, 134/2=67 odd -> conflict-free LDS.64
#define SKW 134
#define ATTN_SMEM ((128 * SKW + 64 * 132 + 128) * 4 + 128 * 4)
__global__ void __launch_bounds__(256) attn_kernel(const float* __restrict__ qk,
                                                   const float* __restrict__ v,
                                                   const int* __restrict__ st,
                                                   float* __restrict__ so,
                                                   float* __restrict__ slog) {
    extern __shared__ float sm[];
    float* s_k = sm;                       // 128 x SKW
    float* s_p = s_k + 128 * SKW;          // 64 x 132
    float* s_rn = s_p + 64 * 132;
    int* s_pk = (int*)(s_rn + 128);
    int tid = threadIdx.x;
    int bh = blockIdx.x >> 8;
    int c = blockIdx.x & 255;
    int prev = (c + 255) & 255;
    int b = bh >> 3, h = bh & 7;
    const int* stb = st + (size_t)bh * (NHSH * TT);
    if (tid < 64) s_pk[tid] = stb[c * 64 + tid];
    else if (tid < 128) s_pk[tid] = stb[prev * 64 + (tid - 64)];
    __syncthreads();
#pragma unroll
    for (int rep = 0; rep < 16; rep++) {
        int idx = tid + rep * 256;
        int j = idx >> 5, d4 = idx & 31;
        const float* kp = qk + ((size_t)(b * TT + s_pk[j])) * DIMC + h * DHH + d4 * 4;
        float4 kv = *(const float4*)kp;
        float* dst = s_k + j * SKW + d4 * 4;   // 8B-aligned (SKW even, d4*4 even)
        *(float2*)(dst) = make_float2(kv.x, kv.y);
        *(float2*)(dst + 2) = make_float2(kv.z, kv.w);
    }
    __syncthreads();
    if (tid < 128) {
        float sq = 0.f;
        const float* kr = s_k + tid * SKW;
#pragma unroll 8
        for (int d = 0; d < 128; d += 2) {
            float2 x = *(const float2*)(kr + d);
            sq += x.x * x.x + x.y * x.y;
        }
        s_rn[tid] = 1.0f / fmaxf(sqrtf(sq), 1e-12f);
    }
    __syncthreads();
    int lane = tid & 31, w = tid >> 5;
    const float SC = 0.08838834764831845f;
    // dots via packed f32x2: lo lane accumulates even d, hi lane odd d
    for (int p2 = 0; p2 < 4; p2++) {
        int i0 = w * 8 + p2 * 2;
        unsigned long long a0[4] = {0, 0, 0, 0}, a1[4] = {0, 0, 0, 0};
        const float* k0 = s_k + i0 * SKW;
        const float* k1 = k0 + SKW;
        const float* kvb = s_k + lane * SKW;
#pragma unroll 4
        for (int d = 0; d < 128; d += 2) {
            unsigned long long q0 = *(const unsigned long long*)(k0 + d);
            unsigned long long q1 = *(const unsigned long long*)(k1 + d);
#pragma unroll
            for (int cc = 0; cc < 4; cc++) {
                unsigned long long kv =
                    *(const unsigned long long*)(kvb + cc * 32 * SKW + d);
                fma2(a0[cc], q0, kv);
                fma2(a1[cc], q1, kv);
            }
        }
        int pq0 = s_pk[i0], pq1 = s_pk[i0 + 1];
#pragma unroll
        for (int cc = 0; cc < 4; cc++) {
            int j = lane + 32 * cc;
            float rn = s_rn[j];
            int pkj = s_pk[j];
            float d0 = sumf2(a0[cc]);
            float d1 = sumf2(a1[cc]);
            s_p[i0 * 132 + j] = (pq0 == pkj) ? -5e4f : d0 * rn * SC;
            s_p[(i0 + 1) * 132 + j] = (pq1 == pkj) ? -5e4f : d1 * rn * SC;
        }
    }
    __syncthreads();
    for (int rr = 0; rr < 8; rr++) {
        int i = w * 8 + rr;
        float vv[4];
#pragma unroll
        for (int cc = 0; cc < 4; cc++) vv[cc] = s_p[i * 132 + lane + 32 * cc];
        float m = fmaxf(fmaxf(vv[0], vv[1]), fmaxf(vv[2], vv[3]));
#pragma unroll
        for (int o = 16; o; o >>= 1) m = fmaxf(m, __shfl_xor_sync(~0u, m, o));
        float sum = 0.f;
#pragma unroll
        for (int cc = 0; cc < 4; cc++) {
            vv[cc] = expf(vv[cc] - m);
            sum += vv[cc];
        }
#pragma unroll
        for (int o = 16; o; o >>= 1) sum += __shfl_xor_sync(~0u, sum, o);
        float lse = m + logf(sum);
        float isum = 1.0f / sum;
#pragma unroll
        for (int cc = 0; cc < 4; cc++) s_p[i * 132 + lane + 32 * cc] = vv[cc] * isum;
        if (lane == 0) slog[(size_t)bh * (NHSH * TT) + c * 64 + i] = lse;
    }
    __syncthreads();
    // PV via packed f32x2 over j pairs; p-pair is a broadcast LDS.64
    unsigned long long acc[8][4];
#pragma unroll
    for (int ii = 0; ii < 8; ii++)
#pragma unroll
        for (int dd = 0; dd < 4; dd++) acc[ii][dd] = 0ull;
    for (int j = 0; j < 128; j += 2) {
        const float* vp0 = v + ((size_t)(b * TT + s_pk[j])) * DIMC + h * DHH;
        const float* vp1 = v + ((size_t)(b * TT + s_pk[j + 1])) * DIMC + h * DHH;
        unsigned long long vv0 = packf2(vp0[lane], vp1[lane]);
        unsigned long long vv1 = packf2(vp0[lane + 32], vp1[lane + 32]);
        unsigned long long vv2 = packf2(vp0[lane + 64], vp1[lane + 64]);
        unsigned long long vv3 = packf2(vp0[lane + 96], vp1[lane + 96]);
#pragma unroll
        for (int ii = 0; ii < 8; ii++) {
            unsigned long long pp =
                *(const unsigned long long*)(s_p + (w + 8 * ii) * 132 + j);
            fma2(acc[ii][0], pp, vv0);
            fma2(acc[ii][1], pp, vv1);
            fma2(acc[ii][2], pp, vv2);
            fma2(acc[ii][3], pp, vv3);
        }
    }
#pragma unroll
    for (int ii = 0; ii < 8; ii++) {
        size_t base = ((size_t)bh * (NHSH * TT) + c * 64 + w + 8 * ii) * 128;
        so[base + lane] = sumf2(acc[ii][0]);
        so[base + lane + 32] = sumf2(acc[ii][1]);
        so[base + lane + 64] = sumf2(acc[ii][2]);
        so[base + lane + 96] = sumf2(acc[ii][3]);
    }
}

// ------------------------- combine hash rounds ----------------------------
__global__ void combine_kernel(const float* __restrict__ so, const float* __restrict__ slog,
                               const int* __restrict__ undo, float* __restrict__ attn) {
    int warp = threadIdx.x >> 5, lane = threadIdx.x & 31;
    int rid = blockIdx.x * 8 + warp;
    int bh = rid >> 12, t = rid & 4095;
    int b = bh >> 3, h = bh & 7;
    int u[4];
    float lg[4];
#pragma unroll
    for (int r = 0; r < 4; r++) {
        u[r] = undo[((size_t)bh * 4 + r) * TT + t];
        lg[r] = slog[(size_t)bh * (NHSH * TT) + r * TT + u[r]];
    }
    float m = fmaxf(fmaxf(lg[0], lg[1]), fmaxf(lg[2], lg[3]));
    float e[4];
    float s = 0.f;
#pragma unroll
    for (int r = 0; r < 4; r++) {
        e[r] = expf(lg[r] - m);
        s += e[r];
    }
    float is = 1.0f / s;
    float a0 = 0, a1 = 0, a2 = 0, a3 = 0;
#pragma unroll
    for (int r = 0; r < 4; r++) {
        const float* op = so + ((size_t)bh * (NHSH * TT) + r * TT + u[r]) * 128;
        float pr = e[r] * is;
        a0 = fmaf(pr, op[lane], a0);
        a1 = fmaf(pr, op[lane + 32], a1);
        a2 = fmaf(pr, op[lane + 64], a2);
        a3 = fmaf(pr, op[lane + 96], a3);
    }
    float* dst = attn + ((size_t)(b * TT + t)) * DIMC + h * DHH;
    dst[lane] = a0;
    dst[lane + 32] = a1;
    dst[lane + 64] = a2;
    dst[lane + 96] = a3;
}

// ------------------------- final y1 + y2 ----------------------------------
__global__ void add_out(float* __restrict__ out) {
    int i = blockIdx.x * blockDim.x + threadIdx.x;
    float4 a = ((float4*)g_x1)[i];
    float4 b = ((float4*)g_x2)[i];
    float4 o;
    o.x = a.x + b.x; o.y = a.y + b.y; o.z = a.z + b.z; o.w = a.w + b.w;
    ((float4*)out)[i] = o;
}

// ------------------------- launch -----------------------------------------
extern "C" void kernel_launch(void* const* d_in, const int* in_sizes, int n_in,
                              void* d_out, int out_size) {
    const float* x = (const float*)d_in[0];
    const float* ln1g = (const float*)d_in[1];
    const float* ln1b = (const float*)d_in[2];
    const float* Wqk = (const float*)d_in[3];
    const float* Wv = (const float*)d_in[4];
    const float* Wo = (const float*)d_in[5];
    const float* bo = (const float*)d_in[6];
    const float* ln2g = (const float*)d_in[7];
    const float* ln2b = (const float*)d_in[8];
    const float* W1 = (const float*)d_in[9];
    const float* b1 = (const float*)d_in[10];
    const float* W2 = (const float*)d_in[11];
    const float* b2 = (const float*)d_in[12];
    const float* rot = (const float*)d_in[13];

    float *px1, *px2, *pxn, *pqk, *pv, *pattn, *pff, *pso, *pslog;
    int *pst, *pundo;
    unsigned char* pbkt;
    __nv_bfloat16 *pA3, *pB3;
    cudaGetSymbolAddress((void**)&px1, g_x1);
    cudaGetSymbolAddress((void**)&px2, g_x2);
    cudaGetSymbolAddress((void**)&pxn, g_xn);
    cudaGetSymbolAddress((void**)&pqk, g_qk);
    cudaGetSymbolAddress((void**)&pv, g_v);
    cudaGetSymbolAddress((void**)&pattn, g_attn);
    cudaGetSymbolAddress((void**)&pff, g_ff);
    cudaGetSymbolAddress((void**)&pso, g_so);
    cudaGetSymbolAddress((void**)&pslog, g_slog);
    cudaGetSymbolAddress((void**)&pst, g_st);
    cudaGetSymbolAddress((void**)&pundo, g_undo);
    cudaGetSymbolAddress((void**)&pbkt, g_bucket);
    cudaGetSymbolAddress((void**)&pA3, g_A3);
    cudaGetSymbolAddress((void**)&pB3, g_B3);
    __half* pA2h = (__half*)pA3;
    __half* pB2h = (__half*)pB3;

    cudaFuncSetAttribute(attn_kernel, cudaFuncAttributeMaxDynamicSharedMemorySize, ATTN_SMEM);
    cudaFuncSetAttribute(tgemm<0, 0>, cudaFuncAttributeMaxDynamicSharedMemorySize, TG_DSMEM);
    cudaFuncSetAttribute(tgemm<3, 0>, cudaFuncAttributeMaxDynamicSharedMemorySize, TG_DSMEM);
    cudaFuncSetAttribute(tgemm<5, 0>, cudaFuncAttributeMaxDynamicSharedMemorySize, TG_DSMEM);
    cudaFuncSetAttribute(tgemm<0, 1>, cudaFuncAttributeMaxDynamicSharedMemorySize, TG_DSMEM);
    cudaFuncSetAttribute(tgemm<3, 1>, cudaFuncAttributeMaxDynamicSharedMemorySize, TG_DSMEM);
    cudaFuncSetAttribute(tgemm<5, 1>, cudaFuncAttributeMaxDynamicSharedMemorySize, TG_DSMEM);

    init_xx<<<TOK * DIMC / 4 / 256, 256>>>(x);

    for (int L = 0; L < 2; L++) {
        const float* wqk = Wqk + (size_t)L * DIMC * DIMC;
        const float* wv = Wv + (size_t)L * DIMC * DIMC;
        const float* wo = Wo + (size_t)L * DIMC * DIMC;
        const float* w1 = W1 + (size_t)L * DIMC * FFD;
        const float* w2 = W2 + (size_t)L * FFD * DIMC;
        const float* rl = rot + (size_t)L * DHH * NHSH * (NBKT / 2);

        // attn input projection: qk (always 3-term bf16 — feeds hashing)
        ln_kernel<<<TOK, 256>>>(px2, ln1g + L * DIMC, ln1b + L * DIMC, pxn);
        convA_kernel<<<TOK * DIMC / 4 / 256, 256>>>(pxn, pA3, DIMC);
        convB_kernel<<<dim3(DIMC / 32, DIMC / 32), 256>>>(wqk, pB3, DIMC, DIMC);
        tgemm<0, 0><<<dim3(4, 64), 256, TG_DSMEM>>>(pA3, pB3, pqk, nullptr, nullptr, 1024, 3072);

        if (L == 0) {
            // layer-1: everything upstream of layer-2 hashing -> 3-term bf16
            convB_kernel<<<dim3(DIMC / 32, DIMC / 32), 256>>>(wv, pB3, DIMC, DIMC);
            tgemm<0, 0><<<dim3(4, 64), 256, TG_DSMEM>>>(pA3, pB3, pv, nullptr, nullptr, 1024, 3072);

            hash_kernel<<<TOK, 256>>>(pqk, rl, pbkt);
            sort_kernel<<<64, 256>>>(pbkt, pst, pundo);
            attn_kernel<<<BHC * NCHK, 256, ATTN_SMEM>>>(pqk, pv, pst, pso, pslog);
            combine_kernel<<<TOK, 256>>>(pso, pslog, pundo, pattn);

            convA_kernel<<<TOK * DIMC / 4 / 256, 256>>>(pattn, pA3, DIMC);
            convB_kernel<<<dim3(DIMC / 32, DIMC / 32), 256>>>(wo, pB3, DIMC, DIMC);
            tgemm<3, 0><<<dim3(4, 64), 256, TG_DSMEM>>>(pA3, pB3, px1, bo + L * DIMC, px1, 1024, 3072);

            ln_kernel<<<TOK, 256>>>(px1, ln2g + L * DIMC, ln2b + L * DIMC, pxn);
            convA_kernel<<<TOK * DIMC / 4 / 256, 256>>>(pxn, pA3, DIMC);
            convB_kernel<<<dim3(FFD / 32, DIMC / 32), 256>>>(w1, pB3, DIMC, FFD);
            tgemm<5, 0><<<dim3(16, 64), 256, TG_DSMEM>>>(pA3, pB3, pff, b1 + L * FFD, nullptr, 4096, 3072);
            convA_kernel<<<TOK * FFD / 4 / 256, 256>>>(pff, pA3, FFD);
            convB_kernel<<<dim3(DIMC / 32, FFD / 32), 256>>>(w2, pB3, FFD, DIMC);
            tgemm<3, 0><<<dim3(4, 64), 256, TG_DSMEM>>>(pA3, pB3, px2, b2 + L * DIMC, px2, 1024, 12288);
        } else {
            // layer-2: V/Wo/W1/W2 feed no hashing -> 2-term fp16 (2K instead of 3K)
            convA2h_kernel<<<TOK * DIMC / 4 / 256, 256>>>(pxn, pA2h, DIMC);
            convB2h_kernel<<<dim3(DIMC / 32, DIMC / 32), 256>>>(wv, pB2h, DIMC, DIMC);
            tgemm<0, 1><<<dim3(4, 64), 256, TG_DSMEM>>>(pA2h, pB2h, pv, nullptr, nullptr, 1024, 2048);

            hash_kernel<<<TOK, 256>>>(pqk, rl, pbkt);
            sort_kernel<<<64, 256>>>(pbkt, pst, pundo);
            attn_kernel<<<BHC * NCHK, 256, ATTN_SMEM>>>(pqk, pv, pst, pso, pslog);
            combine_kernel<<<TOK, 256>>>(pso, pslog, pundo, pattn);

            convA2h_kernel<<<TOK * DIMC / 4 / 256, 256>>>(pattn, pA2h, DIMC);
            convB2h_kernel<<<dim3(DIMC / 32, DIMC / 32), 256>>>(wo, pB2h, DIMC, DIMC);
            tgemm<3, 1><<<dim3(4, 64), 256, TG_DSMEM>>>(pA2h, pB2h, px1, bo + L * DIMC, px1, 1024, 2048);

            ln_kernel<<<TOK, 256>>>(px1, ln2g + L * DIMC, ln2b + L * DIMC, pxn);
            convA2h_kernel<<<TOK * DIMC / 4 / 256, 256>>>(pxn, pA2h, DIMC);
            convB2h_kernel<<<dim3(FFD / 32, DIMC / 32), 256>>>(w1, pB2h, DIMC, FFD);
            tgemm<5, 1><<<dim3(16, 64), 256, TG_DSMEM>>>(pA2h, pB2h, pff, b1 + L * FFD, nullptr, 4096, 2048);
            convA2h_kernel<<<TOK * FFD / 4 / 256, 256>>>(pff, pA2h, FFD);
            convB2h_kernel<<<dim3(DIMC / 32, FFD / 32), 256>>>(w2, pB2h, FFD, DIMC);
            tgemm<3, 1><<<dim3(4, 64), 256, TG_DSMEM>>>(pA2h, pB2h, px2, b2 + L * DIMC, px2, 1024, 8192);
        }
    }

    add_out<<<TOK * DIMC / 4 / 256, 256>>>((float*)d_out);
}

// round 12
// speedup vs baseline: 2.2653x; 1.0373x over previous
#include <cuda_runtime.h>
#include <cuda_bf16.h>
#include <cuda_fp16.h>
#include <math.h>
#include <stdint.h>

#define DIMC 1024
#define TT   4096
#define BBAT 2
#define HH   8
#define DHH  128
#define BHC  16
#define TOK  8192
#define NHSH 4
#define NBKT 64
#define NCHK 256
#define FFD  4096

// ------------------------- scratch (device globals, no allocs) -------------
__device__ float g_x1[TOK * DIMC];
__device__ float g_x2[TOK * DIMC];
__device__ float g_qk[TOK * DIMC];
__device__ float g_v[TOK * DIMC];
__device__ float g_so[BHC * NHSH * TT * DHH];
__device__ float g_slog[BHC * NHSH * TT];
__device__ int g_st[BHC * NHSH * TT];
__device__ int g_undo[BHC * NHSH * TT];
__device__ unsigned char g_bucket[BHC * NHSH * TT];
// split operand buffers (uint4 for 16B alignment)
__device__ uint4 g_Abuf1[(size_t)TOK * 3 * FFD * 2 / 16];
__device__ uint4 g_Abuf2[(size_t)TOK * 3 * FFD * 2 / 16];
__device__ uint4 g_B3[(size_t)FFD * 3 * DIMC * 2 / 16];

// ------------------------- helpers ----------------------------------------
__device__ __forceinline__ uint32_t smem_u32(const void* p) {
    uint32_t a;
    asm("{ .reg .u64 t; cvta.to.shared.u64 t, %1; cvt.u32.u64 %0, t; }" : "=r"(a) : "l"(p));
    return a;
}
__device__ __forceinline__ uint32_t swz128(uint32_t off) { return off ^ ((off >> 3) & 0x70); }

__device__ __forceinline__ void cp_async16(uint32_t so, const void* g) {
    asm volatile("cp.async.cg.shared.global [%0], [%1], 16;" :: "r"(so), "l"(g));
}
__device__ __forceinline__ void ldm_x4(uint32_t& r0, uint32_t& r1, uint32_t& r2, uint32_t& r3,
                                       uint32_t a) {
    asm volatile("ldmatrix.sync.aligned.m8n8.x4.shared.b16 {%0,%1,%2,%3}, [%4];"
                 : "=r"(r0), "=r"(r1), "=r"(r2), "=r"(r3) : "r"(a));
}
__device__ __forceinline__ void mma_bf16(float* c, uint32_t a0, uint32_t a1, uint32_t a2,
                                         uint32_t a3, uint32_t b0, uint32_t b1) {
    asm volatile(
        "mma.sync.aligned.m16n8k16.row.col.f32.bf16.bf16.f32 "
        "{%0,%1,%2,%3}, {%4,%5,%6,%7}, {%8,%9}, {%0,%1,%2,%3};"
        : "+f"(c[0]), "+f"(c[1]), "+f"(c[2]), "+f"(c[3])
        : "r"(a0), "r"(a1), "r"(a2), "r"(a3), "r"(b0), "r"(b1));
}
__device__ __forceinline__ void mma_fp16(float* c, uint32_t a0, uint32_t a1, uint32_t a2,
                                         uint32_t a3, uint32_t b0, uint32_t b1) {
    asm volatile(
        "mma.sync.aligned.m16n8k16.row.col.f32.f16.f16.f32 "
        "{%0,%1,%2,%3}, {%4,%5,%6,%7}, {%8,%9}, {%0,%1,%2,%3};"
        : "+f"(c[0]), "+f"(c[1]), "+f"(c[2]), "+f"(c[3])
        : "r"(a0), "r"(a1), "r"(a2), "r"(a3), "r"(b0), "r"(b1));
}
__device__ __forceinline__ void fma2(unsigned long long& d, unsigned long long a,
                                     unsigned long long b) {
    asm("fma.rn.f32x2 %0, %1, %2, %0;" : "+l"(d) : "l"(a), "l"(b));
}
__device__ __forceinline__ unsigned long long packf2(float lo, float hi) {
    unsigned long long r;
    asm("mov.b64 %0, {%1, %2};" : "=l"(r) : "f"(lo), "f"(hi));
    return r;
}
__device__ __forceinline__ float sumf2(unsigned long long v) {
    float lo, hi;
    asm("mov.b64 {%0, %1}, %2;" : "=f"(lo), "=f"(hi) : "l"(v));
    return lo + hi;
}

// ------------------------- init: x1 = x2 = x ------------------------------
__global__ void init_xx(const float* __restrict__ x) {
    int i = blockIdx.x * blockDim.x + threadIdx.x;
    float4 v = ((const float4*)x)[i];
    ((float4*)g_x1)[i] = v;
    ((float4*)g_x2)[i] = v;
}

// ------------------------- layernorm with fused split output ---------------
// W3: write 3-term bf16 [hi|hi|lo] (K=DIMC). WH: write 2-term fp16 [hi|lo].
template <int W3, int WH>
__global__ void ln_split(const float* __restrict__ in, const float* __restrict__ g,
                         const float* __restrict__ b, __nv_bfloat16* __restrict__ A3,
                         __half* __restrict__ A2) {
    int row = blockIdx.x;
    int tid = threadIdx.x;
    const float* p = in + (size_t)row * DIMC;
    float v[4];
    float s = 0.f, sq = 0.f;
#pragma unroll
    for (int j = 0; j < 4; j++) {
        float x = p[tid + j * 256];
        v[j] = x;
        s += x;
        sq += x * x;
    }
#pragma unroll
    for (int o = 16; o; o >>= 1) {
        s += __shfl_xor_sync(~0u, s, o);
        sq += __shfl_xor_sync(~0u, sq, o);
    }
    __shared__ float rs[8], rq[8];
    if ((tid & 31) == 0) { rs[tid >> 5] = s; rq[tid >> 5] = sq; }
    __syncthreads();
    float S = 0.f, Q = 0.f;
#pragma unroll
    for (int w = 0; w < 8; w++) { S += rs[w]; Q += rq[w]; }
    float mean = S * (1.0f / DIMC);
    float var = Q * (1.0f / DIMC) - mean * mean;
    float inv = rsqrtf(var + 1e-5f);
    size_t rb3 = (size_t)row * 3 * DIMC;
    size_t rb2 = (size_t)row * 2 * DIMC;
#pragma unroll
    for (int j = 0; j < 4; j++) {
        int c = tid + j * 256;
        float y = (v[j] - mean) * inv * g[c] + b[c];
        if (W3) {
            __nv_bfloat16 h = __float2bfloat16(y);
            __nv_bfloat16 l = __float2bfloat16(y - __bfloat162float(h));
            A3[rb3 + c] = h;
            A3[rb3 + DIMC + c] = h;
            A3[rb3 + 2 * DIMC + c] = l;
        }
        if (WH) {
            __half h = __float2half(y);
            __half l = __float2half(y - __half2float(h));
            A2[rb2 + c] = h;
            A2[rb2 + DIMC + c] = l;
        }
    }
}

// ------------------------- weight conversions ------------------------------
// 3-term bf16: B'^T [N, 3K] from W [K, N]: [hi | lo | hi]
__global__ void convB_kernel(const float* __restrict__ W, __nv_bfloat16* __restrict__ B3,
                             int K, int N) {
    __shared__ float s[32][33];
    int tx = threadIdx.x & 31, ty = threadIdx.x >> 5;
    int n0 = blockIdx.x * 32, k0 = blockIdx.y * 32;
#pragma unroll
    for (int j = 0; j < 4; j++)
        s[ty + 8 * j][tx] = W[(size_t)(k0 + ty + 8 * j) * N + n0 + tx];
    __syncthreads();
#pragma unroll
    for (int j = 0; j < 4; j++) {
        int r = ty + 8 * j;
        int n = n0 + r;
        int k = k0 + tx;
        float x = s[tx][r];
        __nv_bfloat16 h = __float2bfloat16(x);
        __nv_bfloat16 l = __float2bfloat16(x - __bfloat162float(h));
        size_t rb = (size_t)n * 3 * K;
        B3[rb + k] = h;
        B3[rb + K + k] = l;
        B3[rb + 2 * K + k] = h;
    }
}

// 2-term fp16: B'^T [N, 2K] from W [K, N]: [hi | hi]
__global__ void convB2h_kernel(const float* __restrict__ W, __half* __restrict__ B2,
                               int K, int N) {
    __shared__ float s[32][33];
    int tx = threadIdx.x & 31, ty = threadIdx.x >> 5;
    int n0 = blockIdx.x * 32, k0 = blockIdx.y * 32;
#pragma unroll
    for (int j = 0; j < 4; j++)
        s[ty + 8 * j][tx] = W[(size_t)(k0 + ty + 8 * j) * N + n0 + tx];
    __syncthreads();
#pragma unroll
    for (int j = 0; j < 4; j++) {
        int r = ty + 8 * j;
        int n = n0 + r;
        int k = k0 + tx;
        __half h = __float2half(s[tx][r]);
        size_t rb = (size_t)n * 2 * K;
        B2[rb + k] = h;
        B2[rb + K + k] = h;
    }
}

// ------------------------- HMMA GEMM (mma.sync) ----------------------------
// C[M,N] fp32 = A'[M,K3] x B'[N,K3]^T. Tile 128x256, BK=64, 3-stage cp.async.
// FLAGS: 1=+bias, 2=+res, 4=exact gelu, 8=write split operand (not fp32).
// FP16: 0 = bf16 operands (3-term out), 1 = fp16 operands (2-term out).
#define TG_STAGE 49152
#define TG_DSMEM (3 * TG_STAGE)

template <int FLAGS, int FP16>
__global__ void __launch_bounds__(256) tgemm(const void* __restrict__ Av,
                                             const void* __restrict__ Bv,
                                             float* __restrict__ C,
                                             const float* __restrict__ bias,
                                             const float* __restrict__ res,
                                             int N, int K3) {
    extern __shared__ char sm_[];
    int tid = threadIdx.x, lane = tid & 31, wid = tid >> 5;
    int wm = wid >> 2, wn = wid & 3;
    int bx = blockIdx.x, by = blockIdx.y;
    const char* Ag = (const char*)Av + (size_t)(by * 128) * K3 * 2;
    const char* Bg = (const char*)Bv + (size_t)(bx * 256) * K3 * 2;
    size_t rs = (size_t)K3 * 2;
    int nk = K3 >> 6;
    uint32_t sbase = smem_u32(sm_);

    auto load_stage = [&](int kc, int s) {
        uint32_t sb = sbase + s * TG_STAGE;
#pragma unroll
        for (int j = 0; j < 12; j++) {
            int idx = tid + j * 256;
            if (idx < 1024) {
                int r = idx >> 3, seg = idx & 7;
                const char* g = Ag + (size_t)r * rs + (size_t)kc * 128 + seg * 16;
                cp_async16(sb + swz128(r * 128 + seg * 16), g);
            } else {
                int t = idx - 1024;
                int r = t >> 3, seg = t & 7;
                const char* g = Bg + (size_t)r * rs + (size_t)kc * 128 + seg * 16;
                cp_async16(sb + 16384 + swz128(r * 128 + seg * 16), g);
            }
        }
        asm volatile("cp.async.commit_group;");
    };

    float acc[4][8][4];
#pragma unroll
    for (int a = 0; a < 4; a++)
#pragma unroll
        for (int b = 0; b < 8; b++)
#pragma unroll
            for (int c = 0; c < 4; c++) acc[a][b][c] = 0.f;

    load_stage(0, 0);
    load_stage(1, 1);

    int mat = lane >> 3, rin = lane & 7;
    for (int i = 0; i < nk; i++) {
        __syncthreads();
        if (i + 2 < nk) load_stage(i + 2, (i + 2) % 3);
        if (i + 2 < nk)       asm volatile("cp.async.wait_group 2;");
        else if (i + 1 < nk)  asm volatile("cp.async.wait_group 1;");
        else                  asm volatile("cp.async.wait_group 0;");
        __syncthreads();

        uint32_t sa = sbase + (i % 3) * TG_STAGE;
        uint32_t sb = sa + 16384;
#pragma unroll
        for (int ks = 0; ks < 4; ks++) {
            uint32_t af[4][4], bf[8][2];
#pragma unroll
            for (int mt = 0; mt < 4; mt++) {
                int row = wm * 64 + mt * 16 + (mat & 1) * 8 + rin;
                int kb = 2 * ks + (mat >> 1);
                ldm_x4(af[mt][0], af[mt][1], af[mt][2], af[mt][3],
                       sa + swz128(row * 128 + kb * 16));
            }
#pragma unroll
            for (int g = 0; g < 4; g++) {
                int nt = 2 * g + (mat >> 1);
                int n = wn * 64 + nt * 8 + rin;
                int kb = 2 * ks + (mat & 1);
                uint32_t b0, b1, b2, b3;
                ldm_x4(b0, b1, b2, b3, sb + swz128(n * 128 + kb * 16));
                bf[2 * g][0] = b0; bf[2 * g][1] = b1;
                bf[2 * g + 1][0] = b2; bf[2 * g + 1][1] = b3;
            }
#pragma unroll
            for (int mt = 0; mt < 4; mt++)
#pragma unroll
                for (int nt = 0; nt < 8; nt++) {
                    if (FP16)
                        mma_fp16(acc[mt][nt], af[mt][0], af[mt][1], af[mt][2], af[mt][3],
                                 bf[nt][0], bf[nt][1]);
                    else
                        mma_bf16(acc[mt][nt], af[mt][0], af[mt][1], af[mt][2], af[mt][3],
                                 bf[nt][0], bf[nt][1]);
                }
        }
    }

    // epilogue
#pragma unroll
    for (int mt = 0; mt < 4; mt++) {
        int gr0 = by * 128 + wm * 64 + mt * 16 + (lane >> 2);
#pragma unroll
        for (int nt = 0; nt < 8; nt++) {
            int gc = bx * 256 + wn * 64 + nt * 8 + (lane & 3) * 2;
            float v0 = acc[mt][nt][0], v1 = acc[mt][nt][1];
            float v2 = acc[mt][nt][2], v3 = acc[mt][nt][3];
            if (FLAGS & 1) {
                float b0 = bias[gc], b1 = bias[gc + 1];
                v0 += b0; v1 += b1; v2 += b0; v3 += b1;
            }
            if (FLAGS & 4) {
                v0 = 0.5f * v0 * (1.0f + erff(v0 * 0.70710678118654752f));
                v1 = 0.5f * v1 * (1.0f + erff(v1 * 0.70710678118654752f));
                v2 = 0.5f * v2 * (1.0f + erff(v2 * 0.70710678118654752f));
                v3 = 0.5f * v3 * (1.0f + erff(v3 * 0.70710678118654752f));
            }
            if (FLAGS & 8) {
                if (!FP16) {
                    __nv_bfloat16* O = (__nv_bfloat16*)C;
                    size_t r0 = (size_t)gr0 * 3 * N, r1 = (size_t)(gr0 + 8) * 3 * N;
                    __nv_bfloat16 h0 = __float2bfloat16(v0);
                    __nv_bfloat16 h1 = __float2bfloat16(v1);
                    __nv_bfloat16 h2 = __float2bfloat16(v2);
                    __nv_bfloat16 h3 = __float2bfloat16(v3);
                    __nv_bfloat162 hp0 = {h0, h1}, hp1 = {h2, h3};
                    __nv_bfloat162 lp0 = {__float2bfloat16(v0 - __bfloat162float(h0)),
                                          __float2bfloat16(v1 - __bfloat162float(h1))};
                    __nv_bfloat162 lp1 = {__float2bfloat16(v2 - __bfloat162float(h2)),
                                          __float2bfloat16(v3 - __bfloat162float(h3))};
                    *(__nv_bfloat162*)(O + r0 + gc) = hp0;
                    *(__nv_bfloat162*)(O + r0 + N + gc) = hp0;
                    *(__nv_bfloat162*)(O + r0 + 2 * N + gc) = lp0;
                    *(__nv_bfloat162*)(O + r1 + gc) = hp1;
                    *(__nv_bfloat162*)(O + r1 + N + gc) = hp1;
                    *(__nv_bfloat162*)(O + r1 + 2 * N + gc) = lp1;
                } else {
                    __half* O = (__half*)C;
                    size_t r0 = (size_t)gr0 * 2 * N, r1 = (size_t)(gr0 + 8) * 2 * N;
                    __half h0 = __float2half(v0), h1 = __float2half(v1);
                    __half h2 = __float2half(v2), h3 = __float2half(v3);
                    __half2 hp0 = {h0, h1}, hp1 = {h2, h3};
                    __half2 lp0 = {__float2half(v0 - __half2float(h0)),
                                   __float2half(v1 - __half2float(h1))};
                    __half2 lp1 = {__float2half(v2 - __half2float(h2)),
                                   __float2half(v3 - __half2float(h3))};
                    *(__half2*)(O + r0 + gc) = hp0;
                    *(__half2*)(O + r0 + N + gc) = lp0;
                    *(__half2*)(O + r1 + gc) = hp1;
                    *(__half2*)(O + r1 + N + gc) = lp1;
                }
            } else {
                if (FLAGS & 2) {
                    const float* r0p = res + (size_t)gr0 * N + gc;
                    const float* r1p = res + (size_t)(gr0 + 8) * N + gc;
                    v0 += r0p[0]; v1 += r0p[1]; v2 += r1p[0]; v3 += r1p[1];
                }
                float2 o0 = {v0, v1}, o1 = {v2, v3};
                *(float2*)(C + (size_t)gr0 * N + gc) = o0;
                *(float2*)(C + (size_t)(gr0 + 8) * N + gc) = o1;
            }
        }
    }
}

// ------------------------- LSH hashing ------------------------------------
__global__ void hash_kernel(const float* __restrict__ qk, const float* __restrict__ rot,
                            unsigned char* __restrict__ bucket) {
    __shared__ float srow[8][128];
    int warp = threadIdx.x >> 5, lane = threadIdx.x & 31;
    int rid = blockIdx.x * 8 + warp;
    int bh = rid >> 12, t = rid & 4095;
    int b = bh >> 3, h = bh & 7;
    const float* qp = qk + ((size_t)(b * TT + t)) * DIMC + h * DHH;
#pragma unroll
    for (int j = 0; j < 4; j++) srow[warp][lane + j * 32] = qp[lane + j * 32];
    __syncwarp();
#pragma unroll
    for (int hh = 0; hh < 4; hh++) {
        float acc = 0.f;
#pragma unroll 8
        for (int f = 0; f < 128; f++)
            acc = fmaf(srow[warp][f], rot[f * 128 + hh * 32 + lane], acc);
        float val = fmaxf(acc, -acc);
        int idx = (acc >= -acc) ? lane : 32 + lane;
#pragma unroll
        for (int o = 16; o; o >>= 1) {
            float ov = __shfl_down_sync(~0u, val, o);
            int oi = __shfl_down_sync(~0u, idx, o);
            if (ov > val || (ov == val && oi < idx)) { val = ov; idx = oi; }
        }
        if (lane == 0) bucket[((size_t)bh * 4 + hh) * TT + t] = (unsigned char)idx;
    }
}

// ------------------------- stable counting sort per (bh, hash) ------------
__global__ void sort_kernel(const unsigned char* __restrict__ bucket,
                            int* __restrict__ st, int* __restrict__ undo) {
    __shared__ unsigned char sb[4096];
    __shared__ unsigned short hist[64 * 257];
    __shared__ int base[65];
    __shared__ int tot[64];
    int blk = blockIdx.x;
    int tid = threadIdx.x;
    const unsigned char* bp = bucket + (size_t)blk * TT;
    for (int i = tid; i < 4096; i += 256) sb[i] = bp[i];
    for (int i = tid; i < 64 * 257; i += 256) hist[i] = 0;
    __syncthreads();
#pragma unroll
    for (int j = 0; j < 16; j++) {
        int t = tid * 16 + j;
        int b = sb[t];
        hist[b * 257 + tid]++;
    }
    __syncthreads();
    if (tid < 64) {
        unsigned int run = 0;
        int b = tid;
        for (int th = 0; th < 256; th++) {
            unsigned short tmp = hist[b * 257 + th];
            hist[b * 257 + th] = (unsigned short)run;
            run += tmp;
        }
        tot[b] = (int)run;
    }
    __syncthreads();
    if (tid == 0) {
        base[0] = 0;
        for (int b = 0; b < 64; b++) base[b + 1] = base[b] + tot[b];
    }
    __syncthreads();
#pragma unroll
    for (int j = 0; j < 16; j++) {
        int t = tid * 16 + j;
        int b = sb[t];
        int pos = base[b] + hist[b * 257 + tid];
        hist[b * 257 + tid]++;
        st[(size_t)blk * TT + pos] = t;
        undo[(size_t)blk * TT + t] = pos;
    }
}

// ------------------------- chunked LSH attention (f32x2) -------------------
#define SKW 134
#define ATTN_SMEM ((128 * SKW + 64 * 132 + 128) * 4 + 128 * 4)
__global__ void __launch_bounds__(256) attn_kernel(const float* __restrict__ qk,
                                                   const float* __restrict__ v,
                                                   const int* __restrict__ st,
                                                   float* __restrict__ so,
                                                   float* __restrict__ slog) {
    extern __shared__ float sm[];
    float* s_k = sm;
    float* s_p = s_k + 128 * SKW;
    float* s_rn = s_p + 64 * 132;
    int* s_pk = (int*)(s_rn + 128);
    int tid = threadIdx.x;
    int bh = blockIdx.x >> 8;
    int c = blockIdx.x & 255;
    int prev = (c + 255) & 255;
    int b = bh >> 3, h = bh & 7;
    const int* stb = st + (size_t)bh * (NHSH * TT);
    if (tid < 64) s_pk[tid] = stb[c * 64 + tid];
    else if (tid < 128) s_pk[tid] = stb[prev * 64 + (tid - 64)];
    __syncthreads();
#pragma unroll
    for (int rep = 0; rep < 16; rep++) {
        int idx = tid + rep * 256;
        int j = idx >> 5, d4 = idx & 31;
        const float* kp = qk + ((size_t)(b * TT + s_pk[j])) * DIMC + h * DHH + d4 * 4;
        float4 kv = *(const float4*)kp;
        float* dst = s_k + j * SKW + d4 * 4;
        *(float2*)(dst) = make_float2(kv.x, kv.y);
        *(float2*)(dst + 2) = make_float2(kv.z, kv.w);
    }
    __syncthreads();
    if (tid < 128) {
        float sq = 0.f;
        const float* kr = s_k + tid * SKW;
#pragma unroll 8
        for (int d = 0; d < 128; d += 2) {
            float2 x = *(const float2*)(kr + d);
            sq += x.x * x.x + x.y * x.y;
        }
        s_rn[tid] = 1.0f / fmaxf(sqrtf(sq), 1e-12f);
    }
    __syncthreads();
    int lane = tid & 31, w = tid >> 5;
    const float SC = 0.08838834764831845f;
    for (int p2 = 0; p2 < 4; p2++) {
        int i0 = w * 8 + p2 * 2;
        unsigned long long a0[4] = {0, 0, 0, 0}, a1[4] = {0, 0, 0, 0};
        const float* k0 = s_k + i0 * SKW;
        const float* k1 = k0 + SKW;
        const float* kvb = s_k + lane * SKW;
#pragma unroll 4
        for (int d = 0; d < 128; d += 2) {
            unsigned long long q0 = *(const unsigned long long*)(k0 + d);
            unsigned long long q1 = *(const unsigned long long*)(k1 + d);
#pragma unroll
            for (int cc = 0; cc < 4; cc++) {
                unsigned long long kv =
                    *(const unsigned long long*)(kvb + cc * 32 * SKW + d);
                fma2(a0[cc], q0, kv);
                fma2(a1[cc], q1, kv);
            }
        }
        int pq0 = s_pk[i0], pq1 = s_pk[i0 + 1];
#pragma unroll
        for (int cc = 0; cc < 4; cc++) {
            int j = lane + 32 * cc;
            float rn = s_rn[j];
            int pkj = s_pk[j];
            float d0 = sumf2(a0[cc]);
            float d1 = sumf2(a1[cc]);
            s_p[i0 * 132 + j] = (pq0 == pkj) ? -5e4f : d0 * rn * SC;
            s_p[(i0 + 1) * 132 + j] = (pq1 == pkj) ? -5e4f : d1 * rn * SC;
        }
    }
    __syncthreads();
    for (int rr = 0; rr < 8; rr++) {
        int i = w * 8 + rr;
        float vv[4];
#pragma unroll
        for (int cc = 0; cc < 4; cc++) vv[cc] = s_p[i * 132 + lane + 32 * cc];
        float m = fmaxf(fmaxf(vv[0], vv[1]), fmaxf(vv[2], vv[3]));
#pragma unroll
        for (int o = 16; o; o >>= 1) m = fmaxf(m, __shfl_xor_sync(~0u, m, o));
        float sum = 0.f;
#pragma unroll
        for (int cc = 0; cc < 4; cc++) {
            vv[cc] = expf(vv[cc] - m);
            sum += vv[cc];
        }
#pragma unroll
        for (int o = 16; o; o >>= 1) sum += __shfl_xor_sync(~0u, sum, o);
        float lse = m + logf(sum);
        float isum = 1.0f / sum;
#pragma unroll
        for (int cc = 0; cc < 4; cc++) s_p[i * 132 + lane + 32 * cc] = vv[cc] * isum;
        if (lane == 0) slog[(size_t)bh * (NHSH * TT) + c * 64 + i] = lse;
    }
    __syncthreads();
    unsigned long long acc[8][4];
#pragma unroll
    for (int ii = 0; ii < 8; ii++)
#pragma unroll
        for (int dd = 0; dd < 4; dd++) acc[ii][dd] = 0ull;
    for (int j = 0; j < 128; j += 2) {
        const float* vp0 = v + ((size_t)(b * TT + s_pk[j])) * DIMC + h * DHH;
        const float* vp1 = v + ((size_t)(b * TT + s_pk[j + 1])) * DIMC + h * DHH;
        unsigned long long vv0 = packf2(vp0[lane], vp1[lane]);
        unsigned long long vv1 = packf2(vp0[lane + 32], vp1[lane + 32]);
        unsigned long long vv2 = packf2(vp0[lane + 64], vp1[lane + 64]);
        unsigned long long vv3 = packf2(vp0[lane + 96], vp1[lane + 96]);
#pragma unroll
        for (int ii = 0; ii < 8; ii++) {
            unsigned long long pp =
                *(const unsigned long long*)(s_p + (w + 8 * ii) * 132 + j);
            fma2(acc[ii][0], pp, vv0);
            fma2(acc[ii][1], pp, vv1);
            fma2(acc[ii][2], pp, vv2);
            fma2(acc[ii][3], pp, vv3);
        }
    }
#pragma unroll
    for (int ii = 0; ii < 8; ii++) {
        size_t base = ((size_t)bh * (NHSH * TT) + c * 64 + w + 8 * ii) * 128;
        so[base + lane] = sumf2(acc[ii][0]);
        so[base + lane + 32] = sumf2(acc[ii][1]);
        so[base + lane + 64] = sumf2(acc[ii][2]);
        so[base + lane + 96] = sumf2(acc[ii][3]);
    }
}

// ------------------------- combine hash rounds + fused split ---------------
// FP16=0: write 3-term bf16 A' (K=DIMC). FP16=1: write 2-term fp16 A'.
template <int FP16>
__global__ void combine_split(const float* __restrict__ so, const float* __restrict__ slog,
                              const int* __restrict__ undo, void* __restrict__ Aout) {
    int warp = threadIdx.x >> 5, lane = threadIdx.x & 31;
    int rid = blockIdx.x * 8 + warp;
    int bh = rid >> 12, t = rid & 4095;
    int b = bh >> 3, h = bh & 7;
    int u[4];
    float lg[4];
#pragma unroll
    for (int r = 0; r < 4; r++) {
        u[r] = undo[((size_t)bh * 4 + r) * TT + t];
        lg[r] = slog[(size_t)bh * (NHSH * TT) + r * TT + u[r]];
    }
    float m = fmaxf(fmaxf(lg[0], lg[1]), fmaxf(lg[2], lg[3]));
    float e[4];
    float s = 0.f;
#pragma unroll
    for (int r = 0; r < 4; r++) {
        e[r] = expf(lg[r] - m);
        s += e[r];
    }
    float is = 1.0f / s;
    float a[4] = {0, 0, 0, 0};
#pragma unroll
    for (int r = 0; r < 4; r++) {
        const float* op = so + ((size_t)bh * (NHSH * TT) + r * TT + u[r]) * 128;
        float pr = e[r] * is;
        a[0] = fmaf(pr, op[lane], a[0]);
        a[1] = fmaf(pr, op[lane + 32], a[1]);
        a[2] = fmaf(pr, op[lane + 64], a[2]);
        a[3] = fmaf(pr, op[lane + 96], a[3]);
    }
    size_t mrow = (size_t)(b * TT + t);
#pragma unroll
    for (int q = 0; q < 4; q++) {
        int col = h * DHH + lane + 32 * q;
        if (!FP16) {
            __nv_bfloat16* A3 = (__nv_bfloat16*)Aout;
            size_t rb = mrow * 3 * DIMC;
            __nv_bfloat16 hh = __float2bfloat16(a[q]);
            __nv_bfloat16 ll = __float2bfloat16(a[q] - __bfloat162float(hh));
            A3[rb + col] = hh;
            A3[rb + DIMC + col] = hh;
            A3[rb + 2 * DIMC + col] = ll;
        } else {
            __half* A2 = (__half*)Aout;
            size_t rb = mrow * 2 * DIMC;
            __half hh = __float2half(a[q]);
            __half ll = __float2half(a[q] - __half2float(hh));
            A2[rb + col] = hh;
            A2[rb + DIMC + col] = ll;
        }
    }
}

// ------------------------- final y1 + y2 ----------------------------------
__global__ void add_out(float* __restrict__ out) {
    int i = blockIdx.x * blockDim.x + threadIdx.x;
    float4 a = ((float4*)g_x1)[i];
    float4 b = ((float4*)g_x2)[i];
    float4 o;
    o.x = a.x + b.x; o.y = a.y + b.y; o.z = a.z + b.z; o.w = a.w + b.w;
    ((float4*)out)[i] = o;
}

// ------------------------- launch -----------------------------------------
extern "C" void kernel_launch(void* const* d_in, const int* in_sizes, int n_in,
                              void* d_out, int out_size) {
    const float* x = (const float*)d_in[0];
    const float* ln1g = (const float*)d_in[1];
    const float* ln1b = (const float*)d_in[2];
    const float* Wqk = (const float*)d_in[3];
    const float* Wv = (const float*)d_in[4];
    const float* Wo = (const float*)d_in[5];
    const float* bo = (const float*)d_in[6];
    const float* ln2g = (const float*)d_in[7];
    const float* ln2b = (const float*)d_in[8];
    const float* W1 = (const float*)d_in[9];
    const float* b1 = (const float*)d_in[10];
    const float* W2 = (const float*)d_in[11];
    const float* b2 = (const float*)d_in[12];
    const float* rot = (const float*)d_in[13];

    float *px1, *px2, *pqk, *pv, *pso, *pslog;
    int *pst, *pundo;
    unsigned char* pbkt;
    void *pA1, *pA2, *pB;
    cudaGetSymbolAddress((void**)&px1, g_x1);
    cudaGetSymbolAddress((void**)&px2, g_x2);
    cudaGetSymbolAddress((void**)&pqk, g_qk);
    cudaGetSymbolAddress((void**)&pv, g_v);
    cudaGetSymbolAddress((void**)&pso, g_so);
    cudaGetSymbolAddress((void**)&pslog, g_slog);
    cudaGetSymbolAddress((void**)&pst, g_st);
    cudaGetSymbolAddress((void**)&pundo, g_undo);
    cudaGetSymbolAddress((void**)&pbkt, g_bucket);
    cudaGetSymbolAddress(&pA1, g_Abuf1);
    cudaGetSymbolAddress(&pA2, g_Abuf2);
    cudaGetSymbolAddress(&pB, g_B3);
    __nv_bfloat16* pB3 = (__nv_bfloat16*)pB;
    __half* pB2h = (__half*)pB;

    cudaFuncSetAttribute(attn_kernel, cudaFuncAttributeMaxDynamicSharedMemorySize, ATTN_SMEM);
    cudaFuncSetAttribute(tgemm<0, 0>, cudaFuncAttributeMaxDynamicSharedMemorySize, TG_DSMEM);
    cudaFuncSetAttribute(tgemm<3, 0>, cudaFuncAttributeMaxDynamicSharedMemorySize, TG_DSMEM);
    cudaFuncSetAttribute(tgemm<13, 0>, cudaFuncAttributeMaxDynamicSharedMemorySize, TG_DSMEM);
    cudaFuncSetAttribute(tgemm<0, 1>, cudaFuncAttributeMaxDynamicSharedMemorySize, TG_DSMEM);
    cudaFuncSetAttribute(tgemm<3, 1>, cudaFuncAttributeMaxDynamicSharedMemorySize, TG_DSMEM);
    cudaFuncSetAttribute(tgemm<13, 1>, cudaFuncAttributeMaxDynamicSharedMemorySize, TG_DSMEM);

    init_xx<<<TOK * DIMC / 4 / 256, 256>>>(x);

    for (int L = 0; L < 2; L++) {
        const float* wqk = Wqk + (size_t)L * DIMC * DIMC;
        const float* wv = Wv + (size_t)L * DIMC * DIMC;
        const float* wo = Wo + (size_t)L * DIMC * DIMC;
        const float* w1 = W1 + (size_t)L * DIMC * FFD;
        const float* w2 = W2 + (size_t)L * FFD * DIMC;
        const float* rl = rot + (size_t)L * DHH * NHSH * (NBKT / 2);

        if (L == 0) {
            // layer-1: all 3-term bf16 (everything feeds layer-2 hashing)
            ln_split<1, 0><<<TOK, 256>>>(px2, ln1g, ln1b,
                                         (__nv_bfloat16*)pA1, nullptr);
            convB_kernel<<<dim3(DIMC / 32, DIMC / 32), 256>>>(wqk, pB3, DIMC, DIMC);
            tgemm<0, 0><<<dim3(4, 64), 256, TG_DSMEM>>>(pA1, pB, pqk, nullptr, nullptr, 1024, 3072);
            convB_kernel<<<dim3(DIMC / 32, DIMC / 32), 256>>>(wv, pB3, DIMC, DIMC);
            tgemm<0, 0><<<dim3(4, 64), 256, TG_DSMEM>>>(pA1, pB, pv, nullptr, nullptr, 1024, 3072);

            hash_kernel<<<TOK, 256>>>(pqk, rl, pbkt);
            sort_kernel<<<64, 256>>>(pbkt, pst, pundo);
            attn_kernel<<<BHC * NCHK, 256, ATTN_SMEM>>>(pqk, pv, pst, pso, pslog);
            combine_split<0><<<TOK, 256>>>(pso, pslog, pundo, pA1);

            convB_kernel<<<dim3(DIMC / 32, DIMC / 32), 256>>>(wo, pB3, DIMC, DIMC);
            tgemm<3, 0><<<dim3(4, 64), 256, TG_DSMEM>>>(pA1, pB, px1, bo, px1, 1024, 3072);

            ln_split<1, 0><<<TOK, 256>>>(px1, ln2g, ln2b,
                                         (__nv_bfloat16*)pA1, nullptr);
            convB_kernel<<<dim3(FFD / 32, DIMC / 32), 256>>>(w1, pB3, DIMC, FFD);
            tgemm<13, 0><<<dim3(16, 64), 256, TG_DSMEM>>>(pA1, pB, (float*)pA2, b1, nullptr, 4096, 3072);
            convB_kernel<<<dim3(DIMC / 32, FFD / 32), 256>>>(w2, pB3, FFD, DIMC);
            tgemm<3, 0><<<dim3(4, 64), 256, TG_DSMEM>>>(pA2, pB, px2, b2, px2, 1024, 12288);
        } else {
            // layer-2: qk 3-term bf16; V/Wo/W1/W2 2-term fp16 (no hash downstream)
            ln_split<1, 1><<<TOK, 256>>>(px2, ln1g + DIMC, ln1b + DIMC,
                                         (__nv_bfloat16*)pA1, (__half*)pA2);
            convB_kernel<<<dim3(DIMC / 32, DIMC / 32), 256>>>(wqk, pB3, DIMC, DIMC);
            tgemm<0, 0><<<dim3(4, 64), 256, TG_DSMEM>>>(pA1, pB, pqk, nullptr, nullptr, 1024, 3072);
            convB2h_kernel<<<dim3(DIMC / 32, DIMC / 32), 256>>>(wv, pB2h, DIMC, DIMC);
            tgemm<0, 1><<<dim3(4, 64), 256, TG_DSMEM>>>(pA2, pB, pv, nullptr, nullptr, 1024, 2048);

            hash_kernel<<<TOK, 256>>>(pqk, rl, pbkt);
            sort_kernel<<<64, 256>>>(pbkt, pst, pundo);
            attn_kernel<<<BHC * NCHK, 256, ATTN_SMEM>>>(pqk, pv, pst, pso, pslog);
            combine_split<1><<<TOK, 256>>>(pso, pslog, pundo, pA1);

            convB2h_kernel<<<dim3(DIMC / 32, DIMC / 32), 256>>>(wo, pB2h, DIMC, DIMC);
            tgemm<3, 1><<<dim3(4, 64), 256, TG_DSMEM>>>(pA1, pB, px1, bo + DIMC, px1, 1024, 2048);

            ln_split<0, 1><<<TOK, 256>>>(px1, ln2g + DIMC, ln2b + DIMC,
                                         nullptr, (__half*)pA1);
            convB2h_kernel<<<dim3(FFD / 32, DIMC / 32), 256>>>(w1, pB2h, DIMC, FFD);
            tgemm<13, 1><<<dim3(16, 64), 256, TG_DSMEM>>>(pA1, pB, (float*)pA2, b1 + FFD, nullptr, 4096, 2048);
            convB2h_kernel<<<dim3(DIMC / 32, FFD / 32), 256>>>(w2, pB2h, FFD, DIMC);
            tgemm<3, 1><<<dim3(4, 64), 256, TG_DSMEM>>>(pA2, pB, px2, b2 + DIMC, px2, 1024, 8192);
        }
    }

    add_out<<<TOK * DIMC / 4 / 256, 256>>>((float*)d_out);
}

// round 13
// speedup vs baseline: 2.3684x; 1.0455x over previous
#include <cuda_runtime.h>
#include <cuda_bf16.h>
#include <cuda_fp16.h>
#include <math.h>
#include <stdint.h>

#define DIMC 1024
#define TT   4096
#define BBAT 2
#define HH   8
#define DHH  128
#define BHC  16
#define TOK  8192
#define NHSH 4
#define NBKT 64
#define NCHK 256
#define FFD  4096

// ------------------------- scratch (device globals, no allocs) -------------
__device__ float g_x1[TOK * DIMC];
__device__ float g_x2[TOK * DIMC];
__device__ float g_qk[TOK * DIMC];
__device__ float g_v[TOK * DIMC];
__device__ float g_so[BHC * NHSH * TT * DHH];
__device__ float g_slog[BHC * NHSH * TT];
__device__ int g_st[BHC * NHSH * TT];
__device__ int g_undo[BHC * NHSH * TT];
__device__ unsigned char g_bucket[BHC * NHSH * TT];
__device__ uint4 g_Abuf1[(size_t)TOK * 3 * FFD * 2 / 16];
__device__ uint4 g_Abuf2[(size_t)TOK * 3 * FFD * 2 / 16];
__device__ uint4 g_B3[(size_t)FFD * 3 * DIMC * 2 / 16];

// ------------------------- helpers ----------------------------------------
__device__ __forceinline__ uint32_t smem_u32(const void* p) {
    uint32_t a;
    asm("{ .reg .u64 t; cvta.to.shared.u64 t, %1; cvt.u32.u64 %0, t; }" : "=r"(a) : "l"(p));
    return a;
}
__device__ __forceinline__ uint32_t swz128(uint32_t off) { return off ^ ((off >> 3) & 0x70); }

__device__ __forceinline__ void cp_async16(uint32_t so, const void* g) {
    asm volatile("cp.async.cg.shared.global [%0], [%1], 16;" :: "r"(so), "l"(g));
}
__device__ __forceinline__ void ldm_x4(uint32_t& r0, uint32_t& r1, uint32_t& r2, uint32_t& r3,
                                       uint32_t a) {
    asm volatile("ldmatrix.sync.aligned.m8n8.x4.shared.b16 {%0,%1,%2,%3}, [%4];"
                 : "=r"(r0), "=r"(r1), "=r"(r2), "=r"(r3) : "r"(a));
}
__device__ __forceinline__ void mma_bf16(float* c, uint32_t a0, uint32_t a1, uint32_t a2,
                                         uint32_t a3, uint32_t b0, uint32_t b1) {
    asm volatile(
        "mma.sync.aligned.m16n8k16.row.col.f32.bf16.bf16.f32 "
        "{%0,%1,%2,%3}, {%4,%5,%6,%7}, {%8,%9}, {%0,%1,%2,%3};"
        : "+f"(c[0]), "+f"(c[1]), "+f"(c[2]), "+f"(c[3])
        : "r"(a0), "r"(a1), "r"(a2), "r"(a3), "r"(b0), "r"(b1));
}
__device__ __forceinline__ void mma_fp16(float* c, uint32_t a0, uint32_t a1, uint32_t a2,
                                         uint32_t a3, uint32_t b0, uint32_t b1) {
    asm volatile(
        "mma.sync.aligned.m16n8k16.row.col.f32.f16.f16.f32 "
        "{%0,%1,%2,%3}, {%4,%5,%6,%7}, {%8,%9}, {%0,%1,%2,%3};"
        : "+f"(c[0]), "+f"(c[1]), "+f"(c[2]), "+f"(c[3])
        : "r"(a0), "r"(a1), "r"(a2), "r"(a3), "r"(b0), "r"(b1));
}
__device__ __forceinline__ void fma2(unsigned long long& d, unsigned long long a,
                                     unsigned long long b) {
    asm("fma.rn.f32x2 %0, %1, %2, %0;" : "+l"(d) : "l"(a), "l"(b));
}
__device__ __forceinline__ unsigned long long packf2(float lo, float hi) {
    unsigned long long r;
    asm("mov.b64 %0, {%1, %2};" : "=l"(r) : "f"(lo), "f"(hi));
    return r;
}
__device__ __forceinline__ float sumf2(unsigned long long v) {
    float lo, hi;
    asm("mov.b64 {%0, %1}, %2;" : "=f"(lo), "=f"(hi) : "l"(v));
    return lo + hi;
}

// ------------------------- init: x1 = x2 = x ------------------------------
__global__ void init_xx(const float* __restrict__ x) {
    int i = blockIdx.x * blockDim.x + threadIdx.x;
    float4 v = ((const float4*)x)[i];
    ((float4*)g_x1)[i] = v;
    ((float4*)g_x2)[i] = v;
}

// ------------------------- layernorm with fused split output ---------------
template <int W3, int WH>
__global__ void ln_split(const float* __restrict__ in, const float* __restrict__ g,
                         const float* __restrict__ b, __nv_bfloat16* __restrict__ A3,
                         __half* __restrict__ A2) {
    int row = blockIdx.x;
    int tid = threadIdx.x;
    const float* p = in + (size_t)row * DIMC;
    float v[4];
    float s = 0.f, sq = 0.f;
#pragma unroll
    for (int j = 0; j < 4; j++) {
        float x = p[tid + j * 256];
        v[j] = x;
        s += x;
        sq += x * x;
    }
#pragma unroll
    for (int o = 16; o; o >>= 1) {
        s += __shfl_xor_sync(~0u, s, o);
        sq += __shfl_xor_sync(~0u, sq, o);
    }
    __shared__ float rs[8], rq[8];
    if ((tid & 31) == 0) { rs[tid >> 5] = s; rq[tid >> 5] = sq; }
    __syncthreads();
    float S = 0.f, Q = 0.f;
#pragma unroll
    for (int w = 0; w < 8; w++) { S += rs[w]; Q += rq[w]; }
    float mean = S * (1.0f / DIMC);
    float var = Q * (1.0f / DIMC) - mean * mean;
    float inv = rsqrtf(var + 1e-5f);
    size_t rb3 = (size_t)row * 3 * DIMC;
    size_t rb2 = (size_t)row * 2 * DIMC;
#pragma unroll
    for (int j = 0; j < 4; j++) {
        int c = tid + j * 256;
        float y = (v[j] - mean) * inv * g[c] + b[c];
        if (W3) {
            __nv_bfloat16 h = __float2bfloat16(y);
            __nv_bfloat16 l = __float2bfloat16(y - __bfloat162float(h));
            A3[rb3 + c] = h;
            A3[rb3 + DIMC + c] = h;
            A3[rb3 + 2 * DIMC + c] = l;
        }
        if (WH) {
            __half h = __float2half(y);
            __half l = __float2half(y - __half2float(h));
            A2[rb2 + c] = h;
            A2[rb2 + DIMC + c] = l;
        }
    }
}

// ------------------------- weight conversions ------------------------------
__global__ void convB_kernel(const float* __restrict__ W, __nv_bfloat16* __restrict__ B3,
                             int K, int N) {
    __shared__ float s[32][33];
    int tx = threadIdx.x & 31, ty = threadIdx.x >> 5;
    int n0 = blockIdx.x * 32, k0 = blockIdx.y * 32;
#pragma unroll
    for (int j = 0; j < 4; j++)
        s[ty + 8 * j][tx] = W[(size_t)(k0 + ty + 8 * j) * N + n0 + tx];
    __syncthreads();
#pragma unroll
    for (int j = 0; j < 4; j++) {
        int r = ty + 8 * j;
        int n = n0 + r;
        int k = k0 + tx;
        float x = s[tx][r];
        __nv_bfloat16 h = __float2bfloat16(x);
        __nv_bfloat16 l = __float2bfloat16(x - __bfloat162float(h));
        size_t rb = (size_t)n * 3 * K;
        B3[rb + k] = h;
        B3[rb + K + k] = l;
        B3[rb + 2 * K + k] = h;
    }
}

__global__ void convB2h_kernel(const float* __restrict__ W, __half* __restrict__ B2,
                               int K, int N) {
    __shared__ float s[32][33];
    int tx = threadIdx.x & 31, ty = threadIdx.x >> 5;
    int n0 = blockIdx.x * 32, k0 = blockIdx.y * 32;
#pragma unroll
    for (int j = 0; j < 4; j++)
        s[ty + 8 * j][tx] = W[(size_t)(k0 + ty + 8 * j) * N + n0 + tx];
    __syncthreads();
#pragma unroll
    for (int j = 0; j < 4; j++) {
        int r = ty + 8 * j;
        int n = n0 + r;
        int k = k0 + tx;
        __half h = __float2half(s[tx][r]);
        size_t rb = (size_t)n * 2 * K;
        B2[rb + k] = h;
        B2[rb + K + k] = h;
    }
}

// ------------------------- HMMA GEMM (mma.sync) ----------------------------
// Tile 128x256, BK=128, 2-stage cp.async (96KB/stage). Rows stored as two
// SW128-swizzled 128B half-tiles (A halves 16KB apart, B halves 32KB apart).
// FLAGS: 1=+bias, 2=+res, 4=exact gelu, 8=write split operand.
#define TG_STAGE 98304
#define TG_DSMEM (2 * TG_STAGE)

template <int FLAGS, int FP16>
__global__ void __launch_bounds__(256) tgemm(const void* __restrict__ Av,
                                             const void* __restrict__ Bv,
                                             float* __restrict__ C,
                                             const float* __restrict__ bias,
                                             const float* __restrict__ res,
                                             int N, int K3) {
    extern __shared__ char sm_[];
    int tid = threadIdx.x, lane = tid & 31, wid = tid >> 5;
    int wm = wid >> 2, wn = wid & 3;
    int bx = blockIdx.x, by = blockIdx.y;
    const char* Ag = (const char*)Av + (size_t)(by * 128) * K3 * 2;
    const char* Bg = (const char*)Bv + (size_t)(bx * 256) * K3 * 2;
    size_t rs = (size_t)K3 * 2;
    int nk = K3 >> 7;                // 128-col chunks
    uint32_t sbase = smem_u32(sm_);

    auto load_stage = [&](int kc, int s) {
        uint32_t sb = sbase + s * TG_STAGE;
#pragma unroll
        for (int j = 0; j < 24; j++) {
            int idx = tid + j * 256;           // 0..6143
            if (idx < 2048) {                  // A: 128 rows x 16 segs
                int r = idx >> 4, seg = idx & 15;
                const char* g = Ag + (size_t)r * rs + (size_t)kc * 256 + seg * 16;
                cp_async16(sb + (seg >> 3) * 16384 + swz128(r * 128 + (seg & 7) * 16), g);
            } else {                           // B: 256 rows x 16 segs
                int t = idx - 2048;
                int r = t >> 4, seg = t & 15;
                const char* g = Bg + (size_t)r * rs + (size_t)kc * 256 + seg * 16;
                cp_async16(sb + 32768 + (seg >> 3) * 32768 + swz128(r * 128 + (seg & 7) * 16), g);
            }
        }
        asm volatile("cp.async.commit_group;");
    };

    float acc[4][8][4];
#pragma unroll
    for (int a = 0; a < 4; a++)
#pragma unroll
        for (int b = 0; b < 8; b++)
#pragma unroll
            for (int c = 0; c < 4; c++) acc[a][b][c] = 0.f;

    load_stage(0, 0);

    int mat = lane >> 3, rin = lane & 7;
    for (int i = 0; i < nk; i++) {
        __syncthreads();                       // all warps done with stage (i+1)&1
        if (i + 1 < nk) load_stage(i + 1, (i + 1) & 1);
        if (i + 1 < nk) asm volatile("cp.async.wait_group 1;");
        else            asm volatile("cp.async.wait_group 0;");
        __syncthreads();

        uint32_t sa = sbase + (i & 1) * TG_STAGE;
        uint32_t sbB = sa + 32768;
#pragma unroll
        for (int ks = 0; ks < 8; ks++) {
            uint32_t af[4][4], bf[8][2];
#pragma unroll
            for (int mt = 0; mt < 4; mt++) {
                int row = wm * 64 + mt * 16 + (mat & 1) * 8 + rin;
                int kb = 2 * ks + (mat >> 1);
                ldm_x4(af[mt][0], af[mt][1], af[mt][2], af[mt][3],
                       sa + (kb >> 3) * 16384 + swz128(row * 128 + (kb & 7) * 16));
            }
#pragma unroll
            for (int g = 0; g < 4; g++) {
                int nt = 2 * g + (mat >> 1);
                int n = wn * 64 + nt * 8 + rin;
                int kb = 2 * ks + (mat & 1);
                uint32_t b0, b1, b2, b3;
                ldm_x4(b0, b1, b2, b3,
                       sbB + (kb >> 3) * 32768 + swz128(n * 128 + (kb & 7) * 16));
                bf[2 * g][0] = b0; bf[2 * g][1] = b1;
                bf[2 * g + 1][0] = b2; bf[2 * g + 1][1] = b3;
            }
#pragma unroll
            for (int mt = 0; mt < 4; mt++)
#pragma unroll
                for (int nt = 0; nt < 8; nt++) {
                    if (FP16)
                        mma_fp16(acc[mt][nt], af[mt][0], af[mt][1], af[mt][2], af[mt][3],
                                 bf[nt][0], bf[nt][1]);
                    else
                        mma_bf16(acc[mt][nt], af[mt][0], af[mt][1], af[mt][2], af[mt][3],
                                 bf[nt][0], bf[nt][1]);
                }
        }
    }

    // epilogue
#pragma unroll
    for (int mt = 0; mt < 4; mt++) {
        int gr0 = by * 128 + wm * 64 + mt * 16 + (lane >> 2);
#pragma unroll
        for (int nt = 0; nt < 8; nt++) {
            int gc = bx * 256 + wn * 64 + nt * 8 + (lane & 3) * 2;
            float v0 = acc[mt][nt][0], v1 = acc[mt][nt][1];
            float v2 = acc[mt][nt][2], v3 = acc[mt][nt][3];
            if (FLAGS & 1) {
                float b0 = bias[gc], b1 = bias[gc + 1];
                v0 += b0; v1 += b1; v2 += b0; v3 += b1;
            }
            if (FLAGS & 4) {
                v0 = 0.5f * v0 * (1.0f + erff(v0 * 0.70710678118654752f));
                v1 = 0.5f * v1 * (1.0f + erff(v1 * 0.70710678118654752f));
                v2 = 0.5f * v2 * (1.0f + erff(v2 * 0.70710678118654752f));
                v3 = 0.5f * v3 * (1.0f + erff(v3 * 0.70710678118654752f));
            }
            if (FLAGS & 8) {
                if (!FP16) {
                    __nv_bfloat16* O = (__nv_bfloat16*)C;
                    size_t r0 = (size_t)gr0 * 3 * N, r1 = (size_t)(gr0 + 8) * 3 * N;
                    __nv_bfloat16 h0 = __float2bfloat16(v0);
                    __nv_bfloat16 h1 = __float2bfloat16(v1);
                    __nv_bfloat16 h2 = __float2bfloat16(v2);
                    __nv_bfloat16 h3 = __float2bfloat16(v3);
                    __nv_bfloat162 hp0 = {h0, h1}, hp1 = {h2, h3};
                    __nv_bfloat162 lp0 = {__float2bfloat16(v0 - __bfloat162float(h0)),
                                          __float2bfloat16(v1 - __bfloat162float(h1))};
                    __nv_bfloat162 lp1 = {__float2bfloat16(v2 - __bfloat162float(h2)),
                                          __float2bfloat16(v3 - __bfloat162float(h3))};
                    *(__nv_bfloat162*)(O + r0 + gc) = hp0;
                    *(__nv_bfloat162*)(O + r0 + N + gc) = hp0;
                    *(__nv_bfloat162*)(O + r0 + 2 * N + gc) = lp0;
                    *(__nv_bfloat162*)(O + r1 + gc) = hp1;
                    *(__nv_bfloat162*)(O + r1 + N + gc) = hp1;
                    *(__nv_bfloat162*)(O + r1 + 2 * N + gc) = lp1;
                } else {
                    __half* O = (__half*)C;
                    size_t r0 = (size_t)gr0 * 2 * N, r1 = (size_t)(gr0 + 8) * 2 * N;
                    __half h0 = __float2half(v0), h1 = __float2half(v1);
                    __half h2 = __float2half(v2), h3 = __float2half(v3);
                    __half2 hp0 = {h0, h1}, hp1 = {h2, h3};
                    __half2 lp0 = {__float2half(v0 - __half2float(h0)),
                                   __float2half(v1 - __half2float(h1))};
                    __half2 lp1 = {__float2half(v2 - __half2float(h2)),
                                   __float2half(v3 - __half2float(h3))};
                    *(__half2*)(O + r0 + gc) = hp0;
                    *(__half2*)(O + r0 + N + gc) = lp0;
                    *(__half2*)(O + r1 + gc) = hp1;
                    *(__half2*)(O + r1 + N + gc) = lp1;
                }
            } else {
                if (FLAGS & 2) {
                    const float* r0p = res + (size_t)gr0 * N + gc;
                    const float* r1p = res + (size_t)(gr0 + 8) * N + gc;
                    v0 += r0p[0]; v1 += r0p[1]; v2 += r1p[0]; v3 += r1p[1];
                }
                float2 o0 = {v0, v1}, o1 = {v2, v3};
                *(float2*)(C + (size_t)gr0 * N + gc) = o0;
                *(float2*)(C + (size_t)(gr0 + 8) * N + gc) = o1;
            }
        }
    }
}

// ------------------------- LSH hashing ------------------------------------
__global__ void hash_kernel(const float* __restrict__ qk, const float* __restrict__ rot,
                            unsigned char* __restrict__ bucket) {
    __shared__ float srow[8][128];
    int warp = threadIdx.x >> 5, lane = threadIdx.x & 31;
    int rid = blockIdx.x * 8 + warp;
    int bh = rid >> 12, t = rid & 4095;
    int b = bh >> 3, h = bh & 7;
    const float* qp = qk + ((size_t)(b * TT + t)) * DIMC + h * DHH;
#pragma unroll
    for (int j = 0; j < 4; j++) srow[warp][lane + j * 32] = qp[lane + j * 32];
    __syncwarp();
#pragma unroll
    for (int hh = 0; hh < 4; hh++) {
        float acc = 0.f;
#pragma unroll 8
        for (int f = 0; f < 128; f++)
            acc = fmaf(srow[warp][f], rot[f * 128 + hh * 32 + lane], acc);
        float val = fmaxf(acc, -acc);
        int idx = (acc >= -acc) ? lane : 32 + lane;
#pragma unroll
        for (int o = 16; o; o >>= 1) {
            float ov = __shfl_down_sync(~0u, val, o);
            int oi = __shfl_down_sync(~0u, idx, o);
            if (ov > val || (ov == val && oi < idx)) { val = ov; idx = oi; }
        }
        if (lane == 0) bucket[((size_t)bh * 4 + hh) * TT + t] = (unsigned char)idx;
    }
}

// ------------------------- stable counting sort per (bh, hash) ------------
__global__ void sort_kernel(const unsigned char* __restrict__ bucket,
                            int* __restrict__ st, int* __restrict__ undo) {
    __shared__ unsigned char sb[4096];
    __shared__ unsigned short hist[64 * 257];
    __shared__ int base[65];
    __shared__ int tot[64];
    int blk = blockIdx.x;
    int tid = threadIdx.x;
    const unsigned char* bp = bucket + (size_t)blk * TT;
    for (int i = tid; i < 4096; i += 256) sb[i] = bp[i];
    for (int i = tid; i < 64 * 257; i += 256) hist[i] = 0;
    __syncthreads();
#pragma unroll
    for (int j = 0; j < 16; j++) {
        int t = tid * 16 + j;
        int b = sb[t];
        hist[b * 257 + tid]++;
    }
    __syncthreads();
    if (tid < 64) {
        unsigned int run = 0;
        int b = tid;
        for (int th = 0; th < 256; th++) {
            unsigned short tmp = hist[b * 257 + th];
            hist[b * 257 + th] = (unsigned short)run;
            run += tmp;
        }
        tot[b] = (int)run;
    }
    __syncthreads();
    if (tid == 0) {
        base[0] = 0;
        for (int b = 0; b < 64; b++) base[b + 1] = base[b] + tot[b];
    }
    __syncthreads();
#pragma unroll
    for (int j = 0; j < 16; j++) {
        int t = tid * 16 + j;
        int b = sb[t];
        int pos = base[b] + hist[b * 257 + tid];
        hist[b * 257 + tid]++;
        st[(size_t)blk * TT + pos] = t;
        undo[(size_t)blk * TT + t] = pos;
    }
}

// ------------------------- chunked LSH attention (f32x2) -------------------
#define SKW 134
#define ATTN_SMEM ((128 * SKW + 64 * 132 + 128) * 4 + 128 * 4)
__global__ void __launch_bounds__(256) attn_kernel(const float* __restrict__ qk,
                                                   const float* __restrict__ v,
                                                   const int* __restrict__ st,
                                                   float* __restrict__ so,
                                                   float* __restrict__ slog) {
    extern __shared__ float sm[];
    float* s_k = sm;
    float* s_p = s_k + 128 * SKW;
    float* s_rn = s_p + 64 * 132;
    int* s_pk = (int*)(s_rn + 128);
    int tid = threadIdx.x;
    int bh = blockIdx.x >> 8;
    int c = blockIdx.x & 255;
    int prev = (c + 255) & 255;
    int b = bh >> 3, h = bh & 7;
    const int* stb = st + (size_t)bh * (NHSH * TT);
    if (tid < 64) s_pk[tid] = stb[c * 64 + tid];
    else if (tid < 128) s_pk[tid] = stb[prev * 64 + (tid - 64)];
    __syncthreads();
#pragma unroll
    for (int rep = 0; rep < 16; rep++) {
        int idx = tid + rep * 256;
        int j = idx >> 5, d4 = idx & 31;
        const float* kp = qk + ((size_t)(b * TT + s_pk[j])) * DIMC + h * DHH + d4 * 4;
        float4 kv = *(const float4*)kp;
        float* dst = s_k + j * SKW + d4 * 4;
        *(float2*)(dst) = make_float2(kv.x, kv.y);
        *(float2*)(dst + 2) = make_float2(kv.z, kv.w);
    }
    __syncthreads();
    if (tid < 128) {
        float sq = 0.f;
        const float* kr = s_k + tid * SKW;
#pragma unroll 8
        for (int d = 0; d < 128; d += 2) {
            float2 x = *(const float2*)(kr + d);
            sq += x.x * x.x + x.y * x.y;
        }
        s_rn[tid] = 1.0f / fmaxf(sqrtf(sq), 1e-12f);
    }
    __syncthreads();
    int lane = tid & 31, w = tid >> 5;
    const float SC = 0.08838834764831845f;
    for (int p2 = 0; p2 < 4; p2++) {
        int i0 = w * 8 + p2 * 2;
        unsigned long long a0[4] = {0, 0, 0, 0}, a1[4] = {0, 0, 0, 0};
        const float* k0 = s_k + i0 * SKW;
        const float* k1 = k0 + SKW;
        const float* kvb = s_k + lane * SKW;
#pragma unroll 4
        for (int d = 0; d < 128; d += 2) {
            unsigned long long q0 = *(const unsigned long long*)(k0 + d);
            unsigned long long q1 = *(const unsigned long long*)(k1 + d);
#pragma unroll
            for (int cc = 0; cc < 4; cc++) {
                unsigned long long kv =
                    *(const unsigned long long*)(kvb + cc * 32 * SKW + d);
                fma2(a0[cc], q0, kv);
                fma2(a1[cc], q1, kv);
            }
        }
        int pq0 = s_pk[i0], pq1 = s_pk[i0 + 1];
#pragma unroll
        for (int cc = 0; cc < 4; cc++) {
            int j = lane + 32 * cc;
            float rn = s_rn[j];
            int pkj = s_pk[j];
            float d0 = sumf2(a0[cc]);
            float d1 = sumf2(a1[cc]);
            s_p[i0 * 132 + j] = (pq0 == pkj) ? -5e4f : d0 * rn * SC;
            s_p[(i0 + 1) * 132 + j] = (pq1 == pkj) ? -5e4f : d1 * rn * SC;
        }
    }
    __syncthreads();
    for (int rr = 0; rr < 8; rr++) {
        int i = w * 8 + rr;
        float vv[4];
#pragma unroll
        for (int cc = 0; cc < 4; cc++) vv[cc] = s_p[i * 132 + lane + 32 * cc];
        float m = fmaxf(fmaxf(vv[0], vv[1]), fmaxf(vv[2], vv[3]));
#pragma unroll
        for (int o = 16; o; o >>= 1) m = fmaxf(m, __shfl_xor_sync(~0u, m, o));
        float sum = 0.f;
#pragma unroll
        for (int cc = 0; cc < 4; cc++) {
            vv[cc] = expf(vv[cc] - m);
            sum += vv[cc];
        }
#pragma unroll
        for (int o = 16; o; o >>= 1) sum += __shfl_xor_sync(~0u, sum, o);
        float lse = m + logf(sum);
        float isum = 1.0f / sum;
#pragma unroll
        for (int cc = 0; cc < 4; cc++) s_p[i * 132 + lane + 32 * cc] = vv[cc] * isum;
        if (lane == 0) slog[(size_t)bh * (NHSH * TT) + c * 64 + i] = lse;
    }
    __syncthreads();
    unsigned long long acc[8][4];
#pragma unroll
    for (int ii = 0; ii < 8; ii++)
#pragma unroll
        for (int dd = 0; dd < 4; dd++) acc[ii][dd] = 0ull;
    for (int j = 0; j < 128; j += 2) {
        const float* vp0 = v + ((size_t)(b * TT + s_pk[j])) * DIMC + h * DHH;
        const float* vp1 = v + ((size_t)(b * TT + s_pk[j + 1])) * DIMC + h * DHH;
        unsigned long long vv0 = packf2(vp0[lane], vp1[lane]);
        unsigned long long vv1 = packf2(vp0[lane + 32], vp1[lane + 32]);
        unsigned long long vv2 = packf2(vp0[lane + 64], vp1[lane + 64]);
        unsigned long long vv3 = packf2(vp0[lane + 96], vp1[lane + 96]);
#pragma unroll
        for (int ii = 0; ii < 8; ii++) {
            unsigned long long pp =
                *(const unsigned long long*)(s_p + (w + 8 * ii) * 132 + j);
            fma2(acc[ii][0], pp, vv0);
            fma2(acc[ii][1], pp, vv1);
            fma2(acc[ii][2], pp, vv2);
            fma2(acc[ii][3], pp, vv3);
        }
    }
#pragma unroll
    for (int ii = 0; ii < 8; ii++) {
        size_t base = ((size_t)bh * (NHSH * TT) + c * 64 + w + 8 * ii) * 128;
        so[base + lane] = sumf2(acc[ii][0]);
        so[base + lane + 32] = sumf2(acc[ii][1]);
        so[base + lane + 64] = sumf2(acc[ii][2]);
        so[base + lane + 96] = sumf2(acc[ii][3]);
    }
}

// ------------------------- combine hash rounds + fused split ---------------
template <int FP16>
__global__ void combine_split(const float* __restrict__ so, const float* __restrict__ slog,
                              const int* __restrict__ undo, void* __restrict__ Aout) {
    int warp = threadIdx.x >> 5, lane = threadIdx.x & 31;
    int rid = blockIdx.x * 8 + warp;
    int bh = rid >> 12, t = rid & 4095;
    int b = bh >> 3, h = bh & 7;
    int u[4];
    float lg[4];
#pragma unroll
    for (int r = 0; r < 4; r++) {
        u[r] = undo[((size_t)bh * 4 + r) * TT + t];
        lg[r] = slog[(size_t)bh * (NHSH * TT) + r * TT + u[r]];
    }
    float m = fmaxf(fmaxf(lg[0], lg[1]), fmaxf(lg[2], lg[3]));
    float e[4];
    float s = 0.f;
#pragma unroll
    for (int r = 0; r < 4; r++) {
        e[r] = expf(lg[r] - m);
        s += e[r];
    }
    float is = 1.0f / s;
    float a[4] = {0, 0, 0, 0};
#pragma unroll
    for (int r = 0; r < 4; r++) {
        const float* op = so + ((size_t)bh * (NHSH * TT) + r * TT + u[r]) * 128;
        float pr = e[r] * is;
        a[0] = fmaf(pr, op[lane], a[0]);
        a[1] = fmaf(pr, op[lane + 32], a[1]);
        a[2] = fmaf(pr, op[lane + 64], a[2]);
        a[3] = fmaf(pr, op[lane + 96], a[3]);
    }
    size_t mrow = (size_t)(b * TT + t);
#pragma unroll
    for (int q = 0; q < 4; q++) {
        int col = h * DHH + lane + 32 * q;
        if (!FP16) {
            __nv_bfloat16* A3 = (__nv_bfloat16*)Aout;
            size_t rb = mrow * 3 * DIMC;
            __nv_bfloat16 hh = __float2bfloat16(a[q]);
            __nv_bfloat16 ll = __float2bfloat16(a[q] - __bfloat162float(hh));
            A3[rb + col] = hh;
            A3[rb + DIMC + col] = hh;
            A3[rb + 2 * DIMC + col] = ll;
        } else {
            __half* A2 = (__half*)Aout;
            size_t rb = mrow * 2 * DIMC;
            __half hh = __float2half(a[q]);
            __half ll = __float2half(a[q] - __half2float(hh));
            A2[rb + col] = hh;
            A2[rb + DIMC + col] = ll;
        }
    }
}

// ------------------------- final y1 + y2 ----------------------------------
__global__ void add_out(float* __restrict__ out) {
    int i = blockIdx.x * blockDim.x + threadIdx.x;
    float4 a = ((float4*)g_x1)[i];
    float4 b = ((float4*)g_x2)[i];
    float4 o;
    o.x = a.x + b.x; o.y = a.y + b.y; o.z = a.z + b.z; o.w = a.w + b.w;
    ((float4*)out)[i] = o;
}

// ------------------------- launch -----------------------------------------
extern "C" void kernel_launch(void* const* d_in, const int* in_sizes, int n_in,
                              void* d_out, int out_size) {
    const float* x = (const float*)d_in[0];
    const float* ln1g = (const float*)d_in[1];
    const float* ln1b = (const float*)d_in[2];
    const float* Wqk = (const float*)d_in[3];
    const float* Wv = (const float*)d_in[4];
    const float* Wo = (const float*)d_in[5];
    const float* bo = (const float*)d_in[6];
    const float* ln2g = (const float*)d_in[7];
    const float* ln2b = (const float*)d_in[8];
    const float* W1 = (const float*)d_in[9];
    const float* b1 = (const float*)d_in[10];
    const float* W2 = (const float*)d_in[11];
    const float* b2 = (const float*)d_in[12];
    const float* rot = (const float*)d_in[13];

    float *px1, *px2, *pqk, *pv, *pso, *pslog;
    int *pst, *pundo;
    unsigned char* pbkt;
    void *pA1, *pA2, *pB;
    cudaGetSymbolAddress((void**)&px1, g_x1);
    cudaGetSymbolAddress((void**)&px2, g_x2);
    cudaGetSymbolAddress((void**)&pqk, g_qk);
    cudaGetSymbolAddress((void**)&pv, g_v);
    cudaGetSymbolAddress((void**)&pso, g_so);
    cudaGetSymbolAddress((void**)&pslog, g_slog);
    cudaGetSymbolAddress((void**)&pst, g_st);
    cudaGetSymbolAddress((void**)&pundo, g_undo);
    cudaGetSymbolAddress((void**)&pbkt, g_bucket);
    cudaGetSymbolAddress(&pA1, g_Abuf1);
    cudaGetSymbolAddress(&pA2, g_Abuf2);
    cudaGetSymbolAddress(&pB, g_B3);
    __nv_bfloat16* pB3 = (__nv_bfloat16*)pB;
    __half* pB2h = (__half*)pB;

    cudaFuncSetAttribute(attn_kernel, cudaFuncAttributeMaxDynamicSharedMemorySize, ATTN_SMEM);
    cudaFuncSetAttribute(tgemm<0, 0>, cudaFuncAttributeMaxDynamicSharedMemorySize, TG_DSMEM);
    cudaFuncSetAttribute(tgemm<3, 0>, cudaFuncAttributeMaxDynamicSharedMemorySize, TG_DSMEM);
    cudaFuncSetAttribute(tgemm<13, 0>, cudaFuncAttributeMaxDynamicSharedMemorySize, TG_DSMEM);
    cudaFuncSetAttribute(tgemm<0, 1>, cudaFuncAttributeMaxDynamicSharedMemorySize, TG_DSMEM);
    cudaFuncSetAttribute(tgemm<3, 1>, cudaFuncAttributeMaxDynamicSharedMemorySize, TG_DSMEM);
    cudaFuncSetAttribute(tgemm<13, 1>, cudaFuncAttributeMaxDynamicSharedMemorySize, TG_DSMEM);

    init_xx<<<TOK * DIMC / 4 / 256, 256>>>(x);

    for (int L = 0; L < 2; L++) {
        const float* wqk = Wqk + (size_t)L * DIMC * DIMC;
        const float* wv = Wv + (size_t)L * DIMC * DIMC;
        const float* wo = Wo + (size_t)L * DIMC * DIMC;
        const float* w1 = W1 + (size_t)L * DIMC * FFD;
        const float* w2 = W2 + (size_t)L * FFD * DIMC;
        const float* rl = rot + (size_t)L * DHH * NHSH * (NBKT / 2);

        if (L == 0) {
            ln_split<1, 0><<<TOK, 256>>>(px2, ln1g, ln1b,
                                         (__nv_bfloat16*)pA1, nullptr);
            convB_kernel<<<dim3(DIMC / 32, DIMC / 32), 256>>>(wqk, pB3, DIMC, DIMC);
            tgemm<0, 0><<<dim3(4, 64), 256, TG_DSMEM>>>(pA1, pB, pqk, nullptr, nullptr, 1024, 3072);
            convB_kernel<<<dim3(DIMC / 32, DIMC / 32), 256>>>(wv, pB3, DIMC, DIMC);
            tgemm<0, 0><<<dim3(4, 64), 256, TG_DSMEM>>>(pA1, pB, pv, nullptr, nullptr, 1024, 3072);

            hash_kernel<<<TOK, 256>>>(pqk, rl, pbkt);
            sort_kernel<<<64, 256>>>(pbkt, pst, pundo);
            attn_kernel<<<BHC * NCHK, 256, ATTN_SMEM>>>(pqk, pv, pst, pso, pslog);
            combine_split<0><<<TOK, 256>>>(pso, pslog, pundo, pA1);

            convB_kernel<<<dim3(DIMC / 32, DIMC / 32), 256>>>(wo, pB3, DIMC, DIMC);
            tgemm<3, 0><<<dim3(4, 64), 256, TG_DSMEM>>>(pA1, pB, px1, bo, px1, 1024, 3072);

            ln_split<1, 0><<<TOK, 256>>>(px1, ln2g, ln2b,
                                         (__nv_bfloat16*)pA1, nullptr);
            convB_kernel<<<dim3(FFD / 32, DIMC / 32), 256>>>(w1, pB3, DIMC, FFD);
            tgemm<13, 0><<<dim3(16, 64), 256, TG_DSMEM>>>(pA1, pB, (float*)pA2, b1, nullptr, 4096, 3072);
            convB_kernel<<<dim3(DIMC / 32, FFD / 32), 256>>>(w2, pB3, FFD, DIMC);
            tgemm<3, 0><<<dim3(4, 64), 256, TG_DSMEM>>>(pA2, pB, px2, b2, px2, 1024, 12288);
        } else {
            ln_split<1, 1><<<TOK, 256>>>(px2, ln1g + DIMC, ln1b + DIMC,
                                         (__nv_bfloat16*)pA1, (__half*)pA2);
            convB_kernel<<<dim3(DIMC / 32, DIMC / 32), 256>>>(wqk, pB3, DIMC, DIMC);
            tgemm<0, 0><<<dim3(4, 64), 256, TG_DSMEM>>>(pA1, pB, pqk, nullptr, nullptr, 1024, 3072);
            convB2h_kernel<<<dim3(DIMC / 32, DIMC / 32), 256>>>(wv, pB2h, DIMC, DIMC);
            tgemm<0, 1><<<dim3(4, 64), 256, TG_DSMEM>>>(pA2, pB, pv, nullptr, nullptr, 1024, 2048);

            hash_kernel<<<TOK, 256>>>(pqk, rl, pbkt);
            sort_kernel<<<64, 256>>>(pbkt, pst, pundo);
            attn_kernel<<<BHC * NCHK, 256, ATTN_SMEM>>>(pqk, pv, pst, pso, pslog);
            combine_split<1><<<TOK, 256>>>(pso, pslog, pundo, pA1);

            convB2h_kernel<<<dim3(DIMC / 32, DIMC / 32), 256>>>(wo, pB2h, DIMC, DIMC);
            tgemm<3, 1><<<dim3(4, 64), 256, TG_DSMEM>>>(pA1, pB, px1, bo + DIMC, px1, 1024, 2048);

            ln_split<0, 1><<<TOK, 256>>>(px1, ln2g + DIMC, ln2b + DIMC,
                                         nullptr, (__half*)pA1);
            convB2h_kernel<<<dim3(FFD / 32, DIMC / 32), 256>>>(w1, pB2h, DIMC, FFD);
            tgemm<13, 1><<<dim3(16, 64), 256, TG_DSMEM>>>(pA1, pB, (float*)pA2, b1 + FFD, nullptr, 4096, 2048);
            convB2h_kernel<<<dim3(DIMC / 32, FFD / 32), 256>>>(w2, pB2h, FFD, DIMC);
            tgemm<3, 1><<<dim3(4, 64), 256, TG_DSMEM>>>(pA2, pB, px2, b2 + DIMC, px2, 1024, 8192);
        }
    }

    add_out<<<TOK * DIMC / 4 / 256, 256>>>((float*)d_out);
}

// round 14
// speedup vs baseline: 2.4966x; 1.0541x over previous
#include <cuda_runtime.h>
#include <cuda_bf16.h>
#include <cuda_fp16.h>
#include <math.h>
#include <stdint.h>

#define DIMC 1024
#define TT   4096
#define BBAT 2
#define HH   8
#define DHH  128
#define BHC  16
#define TOK  8192
#define NHSH 4
#define NBKT 64
#define NCHK 256
#define FFD  4096

// ------------------------- scratch (device globals, no allocs) -------------
__device__ float g_x1[TOK * DIMC];
__device__ float g_x2[TOK * DIMC];
__device__ float g_qkv[TOK * 2048];
__device__ float g_v[TOK * DIMC];
__device__ float g_so[BHC * NHSH * TT * DHH];
__device__ float g_slog[BHC * NHSH * TT];
__device__ int g_st[BHC * NHSH * TT];
__device__ int g_undo[BHC * NHSH * TT];
__device__ unsigned char g_bucket[BHC * NHSH * TT];
__device__ uint4 g_Abuf1[(size_t)TOK * 3 * FFD * 2 / 16];
__device__ uint4 g_Abuf2[(size_t)TOK * 3 * FFD * 2 / 16];
__device__ uint4 g_B3[(size_t)FFD * 3 * DIMC * 2 / 16];

// ------------------------- helpers ----------------------------------------
__device__ __forceinline__ uint32_t smem_u32(const void* p) {
    uint32_t a;
    asm("{ .reg .u64 t; cvta.to.shared.u64 t, %1; cvt.u32.u64 %0, t; }" : "=r"(a) : "l"(p));
    return a;
}
__device__ __forceinline__ uint32_t swz128(uint32_t off) { return off ^ ((off >> 3) & 0x70); }

__device__ __forceinline__ void cp_async16(uint32_t so, const void* g) {
    asm volatile("cp.async.cg.shared.global [%0], [%1], 16;" :: "r"(so), "l"(g));
}
__device__ __forceinline__ void ldm_x4(uint32_t& r0, uint32_t& r1, uint32_t& r2, uint32_t& r3,
                                       uint32_t a) {
    asm volatile("ldmatrix.sync.aligned.m8n8.x4.shared.b16 {%0,%1,%2,%3}, [%4];"
                 : "=r"(r0), "=r"(r1), "=r"(r2), "=r"(r3) : "r"(a));
}
__device__ __forceinline__ void mma_bf16(float* c, uint32_t a0, uint32_t a1, uint32_t a2,
                                         uint32_t a3, uint32_t b0, uint32_t b1) {
    asm volatile(
        "mma.sync.aligned.m16n8k16.row.col.f32.bf16.bf16.f32 "
        "{%0,%1,%2,%3}, {%4,%5,%6,%7}, {%8,%9}, {%0,%1,%2,%3};"
        : "+f"(c[0]), "+f"(c[1]), "+f"(c[2]), "+f"(c[3])
        : "r"(a0), "r"(a1), "r"(a2), "r"(a3), "r"(b0), "r"(b1));
}
__device__ __forceinline__ void mma_fp16(float* c, uint32_t a0, uint32_t a1, uint32_t a2,
                                         uint32_t a3, uint32_t b0, uint32_t b1) {
    asm volatile(
        "mma.sync.aligned.m16n8k16.row.col.f32.f16.f16.f32 "
        "{%0,%1,%2,%3}, {%4,%5,%6,%7}, {%8,%9}, {%0,%1,%2,%3};"
        : "+f"(c[0]), "+f"(c[1]), "+f"(c[2]), "+f"(c[3])
        : "r"(a0), "r"(a1), "r"(a2), "r"(a3), "r"(b0), "r"(b1));
}
__device__ __forceinline__ void fma2(unsigned long long& d, unsigned long long a,
                                     unsigned long long b) {
    asm("fma.rn.f32x2 %0, %1, %2, %0;" : "+l"(d) : "l"(a), "l"(b));
}
__device__ __forceinline__ float sumf2(unsigned long long v) {
    float lo, hi;
    asm("mov.b64 {%0, %1}, %2;" : "=f"(lo), "=f"(hi) : "l"(v));
    return lo + hi;
}

// ------------------------- init: x1 = x2 = x ------------------------------
__global__ void init_xx(const float* __restrict__ x) {
    int i = blockIdx.x * blockDim.x + threadIdx.x;
    float4 v = ((const float4*)x)[i];
    ((float4*)g_x1)[i] = v;
    ((float4*)g_x2)[i] = v;
}

// ------------------------- layernorm with fused split output ---------------
template <int W3, int WH>
__global__ void ln_split(const float* __restrict__ in, const float* __restrict__ g,
                         const float* __restrict__ b, __nv_bfloat16* __restrict__ A3,
                         __half* __restrict__ A2) {
    int row = blockIdx.x;
    int tid = threadIdx.x;
    const float* p = in + (size_t)row * DIMC;
    float v[4];
    float s = 0.f, sq = 0.f;
#pragma unroll
    for (int j = 0; j < 4; j++) {
        float x = p[tid + j * 256];
        v[j] = x;
        s += x;
        sq += x * x;
    }
#pragma unroll
    for (int o = 16; o; o >>= 1) {
        s += __shfl_xor_sync(~0u, s, o);
        sq += __shfl_xor_sync(~0u, sq, o);
    }
    __shared__ float rs[8], rq[8];
    if ((tid & 31) == 0) { rs[tid >> 5] = s; rq[tid >> 5] = sq; }
    __syncthreads();
    float S = 0.f, Q = 0.f;
#pragma unroll
    for (int w = 0; w < 8; w++) { S += rs[w]; Q += rq[w]; }
    float mean = S * (1.0f / DIMC);
    float var = Q * (1.0f / DIMC) - mean * mean;
    float inv = rsqrtf(var + 1e-5f);
    size_t rb3 = (size_t)row * 3 * DIMC;
    size_t rb2 = (size_t)row * 2 * DIMC;
#pragma unroll
    for (int j = 0; j < 4; j++) {
        int c = tid + j * 256;
        float y = (v[j] - mean) * inv * g[c] + b[c];
        if (W3) {
            __nv_bfloat16 h = __float2bfloat16(y);
            __nv_bfloat16 l = __float2bfloat16(y - __bfloat162float(h));
            A3[rb3 + c] = h;
            A3[rb3 + DIMC + c] = h;
            A3[rb3 + 2 * DIMC + c] = l;
        }
        if (WH) {
            __half h = __float2half(y);
            __half l = __float2half(y - __half2float(h));
            A2[rb2 + c] = h;
            A2[rb2 + DIMC + c] = l;
        }
    }
}

// ------------------------- weight conversions ------------------------------
__global__ void convB_kernel(const float* __restrict__ W, __nv_bfloat16* __restrict__ B3,
                             int K, int N) {
    __shared__ float s[32][33];
    int tx = threadIdx.x & 31, ty = threadIdx.x >> 5;
    int n0 = blockIdx.x * 32, k0 = blockIdx.y * 32;
#pragma unroll
    for (int j = 0; j < 4; j++)
        s[ty + 8 * j][tx] = W[(size_t)(k0 + ty + 8 * j) * N + n0 + tx];
    __syncthreads();
#pragma unroll
    for (int j = 0; j < 4; j++) {
        int r = ty + 8 * j;
        int n = n0 + r;
        int k = k0 + tx;
        float x = s[tx][r];
        __nv_bfloat16 h = __float2bfloat16(x);
        __nv_bfloat16 l = __float2bfloat16(x - __bfloat162float(h));
        size_t rb = (size_t)n * 3 * K;
        B3[rb + k] = h;
        B3[rb + K + k] = l;
        B3[rb + 2 * K + k] = h;
    }
}

__global__ void convB2h_kernel(const float* __restrict__ W, __half* __restrict__ B2,
                               int K, int N) {
    __shared__ float s[32][33];
    int tx = threadIdx.x & 31, ty = threadIdx.x >> 5;
    int n0 = blockIdx.x * 32, k0 = blockIdx.y * 32;
#pragma unroll
    for (int j = 0; j < 4; j++)
        s[ty + 8 * j][tx] = W[(size_t)(k0 + ty + 8 * j) * N + n0 + tx];
    __syncthreads();
#pragma unroll
    for (int j = 0; j < 4; j++) {
        int r = ty + 8 * j;
        int n = n0 + r;
        int k = k0 + tx;
        __half h = __float2half(s[tx][r]);
        size_t rb = (size_t)n * 2 * K;
        B2[rb + k] = h;
        B2[rb + K + k] = h;
    }
}

// ------------------------- HMMA GEMM (mma.sync) ----------------------------
#define TG_STAGE 98304
#define TG_DSMEM (2 * TG_STAGE)

template <int FLAGS, int FP16>
__global__ void __launch_bounds__(256) tgemm(const void* __restrict__ Av,
                                             const void* __restrict__ Bv,
                                             float* __restrict__ C,
                                             const float* __restrict__ bias,
                                             const float* __restrict__ res,
                                             int N, int K3) {
    extern __shared__ char sm_[];
    int tid = threadIdx.x, lane = tid & 31, wid = tid >> 5;
    int wm = wid >> 2, wn = wid & 3;
    int bx = blockIdx.x, by = blockIdx.y;
    const char* Ag = (const char*)Av + (size_t)(by * 128) * K3 * 2;
    const char* Bg = (const char*)Bv + (size_t)(bx * 256) * K3 * 2;
    size_t rs = (size_t)K3 * 2;
    int nk = K3 >> 7;
    uint32_t sbase = smem_u32(sm_);

    auto load_stage = [&](int kc, int s) {
        uint32_t sb = sbase + s * TG_STAGE;
#pragma unroll
        for (int j = 0; j < 24; j++) {
            int idx = tid + j * 256;
            if (idx < 2048) {
                int r = idx >> 4, seg = idx & 15;
                const char* g = Ag + (size_t)r * rs + (size_t)kc * 256 + seg * 16;
                cp_async16(sb + (seg >> 3) * 16384 + swz128(r * 128 + (seg & 7) * 16), g);
            } else {
                int t = idx - 2048;
                int r = t >> 4, seg = t & 15;
                const char* g = Bg + (size_t)r * rs + (size_t)kc * 256 + seg * 16;
                cp_async16(sb + 32768 + (seg >> 3) * 32768 + swz128(r * 128 + (seg & 7) * 16), g);
            }
        }
        asm volatile("cp.async.commit_group;");
    };

    float acc[4][8][4];
#pragma unroll
    for (int a = 0; a < 4; a++)
#pragma unroll
        for (int b = 0; b < 8; b++)
#pragma unroll
            for (int c = 0; c < 4; c++) acc[a][b][c] = 0.f;

    load_stage(0, 0);

    int mat = lane >> 3, rin = lane & 7;
    for (int i = 0; i < nk; i++) {
        __syncthreads();
        if (i + 1 < nk) load_stage(i + 1, (i + 1) & 1);
        if (i + 1 < nk) asm volatile("cp.async.wait_group 1;");
        else            asm volatile("cp.async.wait_group 0;");
        __syncthreads();

        uint32_t sa = sbase + (i & 1) * TG_STAGE;
        uint32_t sbB = sa + 32768;
#pragma unroll
        for (int ks = 0; ks < 8; ks++) {
            uint32_t af[4][4], bf[8][2];
#pragma unroll
            for (int mt = 0; mt < 4; mt++) {
                int row = wm * 64 + mt * 16 + (mat & 1) * 8 + rin;
                int kb = 2 * ks + (mat >> 1);
                ldm_x4(af[mt][0], af[mt][1], af[mt][2], af[mt][3],
                       sa + (kb >> 3) * 16384 + swz128(row * 128 + (kb & 7) * 16));
            }
#pragma unroll
            for (int g = 0; g < 4; g++) {
                int nt = 2 * g + (mat >> 1);
                int n = wn * 64 + nt * 8 + rin;
                int kb = 2 * ks + (mat & 1);
                uint32_t b0, b1, b2, b3;
                ldm_x4(b0, b1, b2, b3,
                       sbB + (kb >> 3) * 32768 + swz128(n * 128 + (kb & 7) * 16));
                bf[2 * g][0] = b0; bf[2 * g][1] = b1;
                bf[2 * g + 1][0] = b2; bf[2 * g + 1][1] = b3;
            }
#pragma unroll
            for (int mt = 0; mt < 4; mt++)
#pragma unroll
                for (int nt = 0; nt < 8; nt++) {
                    if (FP16)
                        mma_fp16(acc[mt][nt], af[mt][0], af[mt][1], af[mt][2], af[mt][3],
                                 bf[nt][0], bf[nt][1]);
                    else
                        mma_bf16(acc[mt][nt], af[mt][0], af[mt][1], af[mt][2], af[mt][3],
                                 bf[nt][0], bf[nt][1]);
                }
        }
    }

#pragma unroll
    for (int mt = 0; mt < 4; mt++) {
        int gr0 = by * 128 + wm * 64 + mt * 16 + (lane >> 2);
#pragma unroll
        for (int nt = 0; nt < 8; nt++) {
            int gc = bx * 256 + wn * 64 + nt * 8 + (lane & 3) * 2;
            float v0 = acc[mt][nt][0], v1 = acc[mt][nt][1];
            float v2 = acc[mt][nt][2], v3 = acc[mt][nt][3];
            if (FLAGS & 1) {
                float b0 = bias[gc], b1 = bias[gc + 1];
                v0 += b0; v1 += b1; v2 += b0; v3 += b1;
            }
            if (FLAGS & 4) {
                v0 = 0.5f * v0 * (1.0f + erff(v0 * 0.70710678118654752f));
                v1 = 0.5f * v1 * (1.0f + erff(v1 * 0.70710678118654752f));
                v2 = 0.5f * v2 * (1.0f + erff(v2 * 0.70710678118654752f));
                v3 = 0.5f * v3 * (1.0f + erff(v3 * 0.70710678118654752f));
            }
            if (FLAGS & 8) {
                if (!FP16) {
                    __nv_bfloat16* O = (__nv_bfloat16*)C;
                    size_t r0 = (size_t)gr0 * 3 * N, r1 = (size_t)(gr0 + 8) * 3 * N;
                    __nv_bfloat16 h0 = __float2bfloat16(v0);
                    __nv_bfloat16 h1 = __float2bfloat16(v1);
                    __nv_bfloat16 h2 = __float2bfloat16(v2);
                    __nv_bfloat16 h3 = __float2bfloat16(v3);
                    __nv_bfloat162 hp0 = {h0, h1}, hp1 = {h2, h3};
                    __nv_bfloat162 lp0 = {__float2bfloat16(v0 - __bfloat162float(h0)),
                                          __float2bfloat16(v1 - __bfloat162float(h1))};
                    __nv_bfloat162 lp1 = {__float2bfloat16(v2 - __bfloat162float(h2)),
                                          __float2bfloat16(v3 - __bfloat162float(h3))};
                    *(__nv_bfloat162*)(O + r0 + gc) = hp0;
                    *(__nv_bfloat162*)(O + r0 + N + gc) = hp0;
                    *(__nv_bfloat162*)(O + r0 + 2 * N + gc) = lp0;
                    *(__nv_bfloat162*)(O + r1 + gc) = hp1;
                    *(__nv_bfloat162*)(O + r1 + N + gc) = hp1;
                    *(__nv_bfloat162*)(O + r1 + 2 * N + gc) = lp1;
                } else {
                    __half* O = (__half*)C;
                    size_t r0 = (size_t)gr0 * 2 * N, r1 = (size_t)(gr0 + 8) * 2 * N;
                    __half h0 = __float2half(v0), h1 = __float2half(v1);
                    __half h2 = __float2half(v2), h3 = __float2half(v3);
                    __half2 hp0 = {h0, h1}, hp1 = {h2, h3};
                    __half2 lp0 = {__float2half(v0 - __half2float(h0)),
                                   __float2half(v1 - __half2float(h1))};
                    __half2 lp1 = {__float2half(v2 - __half2float(h2)),
                                   __float2half(v3 - __half2float(h3))};
                    *(__half2*)(O + r0 + gc) = hp0;
                    *(__half2*)(O + r0 + N + gc) = lp0;
                    *(__half2*)(O + r1 + gc) = hp1;
                    *(__half2*)(O + r1 + N + gc) = lp1;
                }
            } else {
                if (FLAGS & 2) {
                    const float* r0p = res + (size_t)gr0 * N + gc;
                    const float* r1p = res + (size_t)(gr0 + 8) * N + gc;
                    v0 += r0p[0]; v1 += r0p[1]; v2 += r1p[0]; v3 += r1p[1];
                }
                float2 o0 = {v0, v1}, o1 = {v2, v3};
                *(float2*)(C + (size_t)gr0 * N + gc) = o0;
                *(float2*)(C + (size_t)(gr0 + 8) * N + gc) = o1;
            }
        }
    }
}

// ------------------------- LSH hashing (strided qk) ------------------------
__global__ void hash_kernel(const float* __restrict__ qk, int qstride,
                            const float* __restrict__ rot,
                            unsigned char* __restrict__ bucket) {
    __shared__ float srow[8][128];
    int warp = threadIdx.x >> 5, lane = threadIdx.x & 31;
    int rid = blockIdx.x * 8 + warp;
    int bh = rid >> 12, t = rid & 4095;
    int b = bh >> 3, h = bh & 7;
    const float* qp = qk + (size_t)(b * TT + t) * qstride + h * DHH;
#pragma unroll
    for (int j = 0; j < 4; j++) srow[warp][lane + j * 32] = qp[lane + j * 32];
    __syncwarp();
#pragma unroll
    for (int hh = 0; hh < 4; hh++) {
        float acc = 0.f;
#pragma unroll 8
        for (int f = 0; f < 128; f++)
            acc = fmaf(srow[warp][f], rot[f * 128 + hh * 32 + lane], acc);
        float val = fmaxf(acc, -acc);
        int idx = (acc >= -acc) ? lane : 32 + lane;
#pragma unroll
        for (int o = 16; o; o >>= 1) {
            float ov = __shfl_down_sync(~0u, val, o);
            int oi = __shfl_down_sync(~0u, idx, o);
            if (ov > val || (ov == val && oi < idx)) { val = ov; idx = oi; }
        }
        if (lane == 0) bucket[((size_t)bh * 4 + hh) * TT + t] = (unsigned char)idx;
    }
}

// ------------------------- stable counting sort per (bh, hash) ------------
__global__ void sort_kernel(const unsigned char* __restrict__ bucket,
                            int* __restrict__ st, int* __restrict__ undo) {
    __shared__ unsigned char sb[4096];
    __shared__ unsigned short hist[64 * 257];
    __shared__ int base[65];
    __shared__ int tot[64];
    int blk = blockIdx.x;
    int tid = threadIdx.x;
    const unsigned char* bp = bucket + (size_t)blk * TT;
    for (int i = tid; i < 4096; i += 256) sb[i] = bp[i];
    for (int i = tid; i < 64 * 257; i += 256) hist[i] = 0;
    __syncthreads();
#pragma unroll
    for (int j = 0; j < 16; j++) {
        int t = tid * 16 + j;
        int b = sb[t];
        hist[b * 257 + tid]++;
    }
    __syncthreads();
    if (tid < 64) {
        unsigned int run = 0;
        int b = tid;
        for (int th = 0; th < 256; th++) {
            unsigned short tmp = hist[b * 257 + th];
            hist[b * 257 + th] = (unsigned short)run;
            run += tmp;
        }
        tot[b] = (int)run;
    }
    __syncthreads();
    if (tid == 0) {
        base[0] = 0;
        for (int b = 0; b < 64; b++) base[b + 1] = base[b] + tot[b];
    }
    __syncthreads();
#pragma unroll
    for (int j = 0; j < 16; j++) {
        int t = tid * 16 + j;
        int b = sb[t];
        int pos = base[b] + hist[b * 257 + tid];
        hist[b * 257 + tid]++;
        st[(size_t)blk * TT + pos] = t;
        undo[(size_t)blk * TT + t] = pos;
    }
}

// ------------------------- chunked LSH attention (512 thr, smem V) --------
#define SKW 134
#define ATTN_SMEM ((128 * SKW + 64 * 132 + 128) * 4 + 128 * 4)
__global__ void __launch_bounds__(512) attn_kernel(const float* __restrict__ qkb, int qstride,
                                                   const float* __restrict__ vb, int vstride,
                                                   const int* __restrict__ st,
                                                   float* __restrict__ so,
                                                   float* __restrict__ slog) {
    extern __shared__ float sm[];
    float* s_k = sm;                     // 128 x SKW; reused (transposed) for V
    float* s_p = s_k + 128 * SKW;
    float* s_rn = s_p + 64 * 132;
    int* s_pk = (int*)(s_rn + 128);
    int tid = threadIdx.x;
    int bh = blockIdx.x >> 8;
    int c = blockIdx.x & 255;
    int prev = (c + 255) & 255;
    int b = bh >> 3, h = bh & 7;
    const int* stb = st + (size_t)bh * (NHSH * TT);
    if (tid < 64) s_pk[tid] = stb[c * 64 + tid];
    else if (tid < 128) s_pk[tid] = stb[prev * 64 + (tid - 64)];
    __syncthreads();
#pragma unroll
    for (int rep = 0; rep < 8; rep++) {
        int idx = tid + rep * 512;
        int j = idx >> 5, d4 = idx & 31;
        const float* kp = qkb + (size_t)(b * TT + s_pk[j]) * qstride + h * DHH + d4 * 4;
        float4 kv = *(const float4*)kp;
        float* dst = s_k + j * SKW + d4 * 4;
        *(float2*)(dst) = make_float2(kv.x, kv.y);
        *(float2*)(dst + 2) = make_float2(kv.z, kv.w);
    }
    __syncthreads();
    if (tid < 128) {
        float sq = 0.f;
        const float* kr = s_k + tid * SKW;
#pragma unroll 8
        for (int d = 0; d < 128; d += 2) {
            float2 x = *(const float2*)(kr + d);
            sq += x.x * x.x + x.y * x.y;
        }
        s_rn[tid] = 1.0f / fmaxf(sqrtf(sq), 1e-12f);
    }
    __syncthreads();
    int lane = tid & 31, w = tid >> 5;        // 16 warps
    const float SC = 0.08838834764831845f;
    for (int p2 = 0; p2 < 2; p2++) {
        int i0 = w * 4 + p2 * 2;
        unsigned long long a0[4] = {0, 0, 0, 0}, a1[4] = {0, 0, 0, 0};
        const float* k0 = s_k + i0 * SKW;
        const float* k1 = k0 + SKW;
        const float* kvb = s_k + lane * SKW;
#pragma unroll 4
        for (int d = 0; d < 128; d += 2) {
            unsigned long long q0 = *(const unsigned long long*)(k0 + d);
            unsigned long long q1 = *(const unsigned long long*)(k1 + d);
#pragma unroll
            for (int cc = 0; cc < 4; cc++) {
                unsigned long long kv =
                    *(const unsigned long long*)(kvb + cc * 32 * SKW + d);
                fma2(a0[cc], q0, kv);
                fma2(a1[cc], q1, kv);
            }
        }
        int pq0 = s_pk[i0], pq1 = s_pk[i0 + 1];
#pragma unroll
        for (int cc = 0; cc < 4; cc++) {
            int j = lane + 32 * cc;
            float rn = s_rn[j];
            int pkj = s_pk[j];
            float d0 = sumf2(a0[cc]);
            float d1 = sumf2(a1[cc]);
            s_p[i0 * 132 + j] = (pq0 == pkj) ? -5e4f : d0 * rn * SC;
            s_p[(i0 + 1) * 132 + j] = (pq1 == pkj) ? -5e4f : d1 * rn * SC;
        }
    }
    __syncthreads();   // dots done: s_k dead, s_p complete
    // load V transposed into s_k: sV[d * SKW + j] = V[j][d]
#pragma unroll
    for (int rep = 0; rep < 8; rep++) {
        int idx = tid + rep * 512;
        int j = idx >> 5, d4 = idx & 31;
        const float* vp = vb + (size_t)(b * TT + s_pk[j]) * vstride + h * DHH + d4 * 4;
        float4 vv = *(const float4*)vp;
        s_k[(d4 * 4 + 0) * SKW + j] = vv.x;
        s_k[(d4 * 4 + 1) * SKW + j] = vv.y;
        s_k[(d4 * 4 + 2) * SKW + j] = vv.z;
        s_k[(d4 * 4 + 3) * SKW + j] = vv.w;
    }
    // softmax (s_p only) — overlapped with V staging
    for (int rr = 0; rr < 4; rr++) {
        int i = w * 4 + rr;
        float vv[4];
#pragma unroll
        for (int cc = 0; cc < 4; cc++) vv[cc] = s_p[i * 132 + lane + 32 * cc];
        float m = fmaxf(fmaxf(vv[0], vv[1]), fmaxf(vv[2], vv[3]));
#pragma unroll
        for (int o = 16; o; o >>= 1) m = fmaxf(m, __shfl_xor_sync(~0u, m, o));
        float sum = 0.f;
#pragma unroll
        for (int cc = 0; cc < 4; cc++) {
            vv[cc] = expf(vv[cc] - m);
            sum += vv[cc];
        }
#pragma unroll
        for (int o = 16; o; o >>= 1) sum += __shfl_xor_sync(~0u, sum, o);
        float lse = m + logf(sum);
        float isum = 1.0f / sum;
#pragma unroll
        for (int cc = 0; cc < 4; cc++) s_p[i * 132 + lane + 32 * cc] = vv[cc] * isum;
        if (lane == 0) slog[(size_t)bh * (NHSH * TT) + c * 64 + i] = lse;
    }
    __syncthreads();
    // PV: warp w owns queries w*4..w*4+3; V pairs from smem (conflict-free LDS.64)
    unsigned long long acc[4][4];
#pragma unroll
    for (int ii = 0; ii < 4; ii++)
#pragma unroll
        for (int dd = 0; dd < 4; dd++) acc[ii][dd] = 0ull;
    for (int j = 0; j < 128; j += 2) {
        unsigned long long vv0 = *(const unsigned long long*)(s_k + (size_t)lane * SKW + j);
        unsigned long long vv1 = *(const unsigned long long*)(s_k + (size_t)(lane + 32) * SKW + j);
        unsigned long long vv2 = *(const unsigned long long*)(s_k + (size_t)(lane + 64) * SKW + j);
        unsigned long long vv3 = *(const unsigned long long*)(s_k + (size_t)(lane + 96) * SKW + j);
#pragma unroll
        for (int ii = 0; ii < 4; ii++) {
            unsigned long long pp =
                *(const unsigned long long*)(s_p + (w * 4 + ii) * 132 + j);
            fma2(acc[ii][0], pp, vv0);
            fma2(acc[ii][1], pp, vv1);
            fma2(acc[ii][2], pp, vv2);
            fma2(acc[ii][3], pp, vv3);
        }
    }
#pragma unroll
    for (int ii = 0; ii < 4; ii++) {
        size_t base = ((size_t)bh * (NHSH * TT) + c * 64 + w * 4 + ii) * 128;
        so[base + lane] = sumf2(acc[ii][0]);
        so[base + lane + 32] = sumf2(acc[ii][1]);
        so[base + lane + 64] = sumf2(acc[ii][2]);
        so[base + lane + 96] = sumf2(acc[ii][3]);
    }
}

// ------------------------- combine hash rounds + fused split ---------------
template <int FP16>
__global__ void combine_split(const float* __restrict__ so, const float* __restrict__ slog,
                              const int* __restrict__ undo, void* __restrict__ Aout) {
    int warp = threadIdx.x >> 5, lane = threadIdx.x & 31;
    int rid = blockIdx.x * 8 + warp;
    int bh = rid >> 12, t = rid & 4095;
    int b = bh >> 3, h = bh & 7;
    int u[4];
    float lg[4];
#pragma unroll
    for (int r = 0; r < 4; r++) {
        u[r] = undo[((size_t)bh * 4 + r) * TT + t];
        lg[r] = slog[(size_t)bh * (NHSH * TT) + r * TT + u[r]];
    }
    float m = fmaxf(fmaxf(lg[0], lg[1]), fmaxf(lg[2], lg[3]));
    float e[4];
    float s = 0.f;
#pragma unroll
    for (int r = 0; r < 4; r++) {
        e[r] = expf(lg[r] - m);
        s += e[r];
    }
    float is = 1.0f / s;
    float a[4] = {0, 0, 0, 0};
#pragma unroll
    for (int r = 0; r < 4; r++) {
        const float* op = so + ((size_t)bh * (NHSH * TT) + r * TT + u[r]) * 128;
        float pr = e[r] * is;
        a[0] = fmaf(pr, op[lane], a[0]);
        a[1] = fmaf(pr, op[lane + 32], a[1]);
        a[2] = fmaf(pr, op[lane + 64], a[2]);
        a[3] = fmaf(pr, op[lane + 96], a[3]);
    }
    size_t mrow = (size_t)(b * TT + t);
#pragma unroll
    for (int q = 0; q < 4; q++) {
        int col = h * DHH + lane + 32 * q;
        if (!FP16) {
            __nv_bfloat16* A3 = (__nv_bfloat16*)Aout;
            size_t rb = mrow * 3 * DIMC;
            __nv_bfloat16 hh = __float2bfloat16(a[q]);
            __nv_bfloat16 ll = __float2bfloat16(a[q] - __bfloat162float(hh));
            A3[rb + col] = hh;
            A3[rb + DIMC + col] = hh;
            A3[rb + 2 * DIMC + col] = ll;
        } else {
            __half* A2 = (__half*)Aout;
            size_t rb = mrow * 2 * DIMC;
            __half hh = __float2half(a[q]);
            __half ll = __float2half(a[q] - __half2float(hh));
            A2[rb + col] = hh;
            A2[rb + DIMC + col] = ll;
        }
    }
}

// ------------------------- final y1 + y2 ----------------------------------
__global__ void add_out(float* __restrict__ out) {
    int i = blockIdx.x * blockDim.x + threadIdx.x;
    float4 a = ((float4*)g_x1)[i];
    float4 b = ((float4*)g_x2)[i];
    float4 o;
    o.x = a.x + b.x; o.y = a.y + b.y; o.z = a.z + b.z; o.w = a.w + b.w;
    ((float4*)out)[i] = o;
}

// ------------------------- launch -----------------------------------------
extern "C" void kernel_launch(void* const* d_in, const int* in_sizes, int n_in,
                              void* d_out, int out_size) {
    const float* x = (const float*)d_in[0];
    const float* ln1g = (const float*)d_in[1];
    const float* ln1b = (const float*)d_in[2];
    const float* Wqk = (const float*)d_in[3];
    const float* Wv = (const float*)d_in[4];
    const float* Wo = (const float*)d_in[5];
    const float* bo = (const float*)d_in[6];
    const float* ln2g = (const float*)d_in[7];
    const float* ln2b = (const float*)d_in[8];
    const float* W1 = (const float*)d_in[9];
    const float* b1 = (const float*)d_in[10];
    const float* W2 = (const float*)d_in[11];
    const float* b2 = (const float*)d_in[12];
    const float* rot = (const float*)d_in[13];

    float *px1, *px2, *pqkv, *pv, *pso, *pslog;
    int *pst, *pundo;
    unsigned char* pbkt;
    void *pA1, *pA2, *pB;
    cudaGetSymbolAddress((void**)&px1, g_x1);
    cudaGetSymbolAddress((void**)&px2, g_x2);
    cudaGetSymbolAddress((void**)&pqkv, g_qkv);
    cudaGetSymbolAddress((void**)&pv, g_v);
    cudaGetSymbolAddress((void**)&pso, g_so);
    cudaGetSymbolAddress((void**)&pslog, g_slog);
    cudaGetSymbolAddress((void**)&pst, g_st);
    cudaGetSymbolAddress((void**)&pundo, g_undo);
    cudaGetSymbolAddress((void**)&pbkt, g_bucket);
    cudaGetSymbolAddress(&pA1, g_Abuf1);
    cudaGetSymbolAddress(&pA2, g_Abuf2);
    cudaGetSymbolAddress(&pB, g_B3);
    __nv_bfloat16* pB3 = (__nv_bfloat16*)pB;
    __half* pB2h = (__half*)pB;

    cudaFuncSetAttribute(attn_kernel, cudaFuncAttributeMaxDynamicSharedMemorySize, ATTN_SMEM);
    cudaFuncSetAttribute(tgemm<0, 0>, cudaFuncAttributeMaxDynamicSharedMemorySize, TG_DSMEM);
    cudaFuncSetAttribute(tgemm<3, 0>, cudaFuncAttributeMaxDynamicSharedMemorySize, TG_DSMEM);
    cudaFuncSetAttribute(tgemm<13, 0>, cudaFuncAttributeMaxDynamicSharedMemorySize, TG_DSMEM);
    cudaFuncSetAttribute(tgemm<0, 1>, cudaFuncAttributeMaxDynamicSharedMemorySize, TG_DSMEM);
    cudaFuncSetAttribute(tgemm<3, 1>, cudaFuncAttributeMaxDynamicSharedMemorySize, TG_DSMEM);
    cudaFuncSetAttribute(tgemm<13, 1>, cudaFuncAttributeMaxDynamicSharedMemorySize, TG_DSMEM);

    init_xx<<<TOK * DIMC / 4 / 256, 256>>>(x);

    for (int L = 0; L < 2; L++) {
        const float* wqk = Wqk + (size_t)L * DIMC * DIMC;
        const float* wv = Wv + (size_t)L * DIMC * DIMC;
        const float* wo = Wo + (size_t)L * DIMC * DIMC;
        const float* w1 = W1 + (size_t)L * DIMC * FFD;
        const float* w2 = W2 + (size_t)L * FFD * DIMC;
        const float* rl = rot + (size_t)L * DHH * NHSH * (NBKT / 2);

        if (L == 0) {
            ln_split<1, 0><<<TOK, 256>>>(px2, ln1g, ln1b,
                                         (__nv_bfloat16*)pA1, nullptr);
            // merged qk|v: B' rows 0..1023 = Wqk, 1024..2047 = Wv
            convB_kernel<<<dim3(DIMC / 32, DIMC / 32), 256>>>(wqk, pB3, DIMC, DIMC);
            convB_kernel<<<dim3(DIMC / 32, DIMC / 32), 256>>>(
                wv, pB3 + (size_t)1024 * 3 * DIMC, DIMC, DIMC);
            tgemm<0, 0><<<dim3(8, 64), 256, TG_DSMEM>>>(pA1, pB, pqkv, nullptr, nullptr, 2048, 3072);

            hash_kernel<<<TOK, 256>>>(pqkv, 2048, rl, pbkt);
            sort_kernel<<<64, 256>>>(pbkt, pst, pundo);
            attn_kernel<<<BHC * NCHK, 512, ATTN_SMEM>>>(pqkv, 2048, pqkv + 1024, 2048,
                                                        pst, pso, pslog);
            combine_split<0><<<TOK, 256>>>(pso, pslog, pundo, pA1);

            convB_kernel<<<dim3(DIMC / 32, DIMC / 32), 256>>>(wo, pB3, DIMC, DIMC);
            tgemm<3, 0><<<dim3(4, 64), 256, TG_DSMEM>>>(pA1, pB, px1, bo, px1, 1024, 3072);

            ln_split<1, 0><<<TOK, 256>>>(px1, ln2g, ln2b,
                                         (__nv_bfloat16*)pA1, nullptr);
            convB_kernel<<<dim3(FFD / 32, DIMC / 32), 256>>>(w1, pB3, DIMC, FFD);
            tgemm<13, 0><<<dim3(16, 64), 256, TG_DSMEM>>>(pA1, pB, (float*)pA2, b1, nullptr, 4096, 3072);
            convB_kernel<<<dim3(DIMC / 32, FFD / 32), 256>>>(w2, pB3, FFD, DIMC);
            tgemm<3, 0><<<dim3(4, 64), 256, TG_DSMEM>>>(pA2, pB, px2, b2, px2, 1024, 12288);
        } else {
            ln_split<1, 1><<<TOK, 256>>>(px2, ln1g + DIMC, ln1b + DIMC,
                                         (__nv_bfloat16*)pA1, (__half*)pA2);
            convB_kernel<<<dim3(DIMC / 32, DIMC / 32), 256>>>(wqk, pB3, DIMC, DIMC);
            tgemm<0, 0><<<dim3(4, 64), 256, TG_DSMEM>>>(pA1, pB, pqkv, nullptr, nullptr, 1024, 3072);
            convB2h_kernel<<<dim3(DIMC / 32, DIMC / 32), 256>>>(wv, pB2h, DIMC, DIMC);
            tgemm<0, 1><<<dim3(4, 64), 256, TG_DSMEM>>>(pA2, pB, pv, nullptr, nullptr, 1024, 2048);

            hash_kernel<<<TOK, 256>>>(pqkv, 1024, rl, pbkt);
            sort_kernel<<<64, 256>>>(pbkt, pst, pundo);
            attn_kernel<<<BHC * NCHK, 512, ATTN_SMEM>>>(pqkv, 1024, pv, 1024,
                                                        pst, pso, pslog);
            combine_split<1><<<TOK, 256>>>(pso, pslog, pundo, pA1);

            convB2h_kernel<<<dim3(DIMC / 32, DIMC / 32), 256>>>(wo, pB2h, DIMC, DIMC);
            tgemm<3, 1><<<dim3(4, 64), 256, TG_DSMEM>>>(pA1, pB, px1, bo + DIMC, px1, 1024, 2048);

            ln_split<0, 1><<<TOK, 256>>>(px1, ln2g + DIMC, ln2b + DIMC,
                                         nullptr, (__half*)pA1);
            convB2h_kernel<<<dim3(FFD / 32, DIMC / 32), 256>>>(w1, pB2h, DIMC, FFD);
            tgemm<13, 1><<<dim3(16, 64), 256, TG_DSMEM>>>(pA1, pB, (float*)pA2, b1 + FFD, nullptr, 4096, 2048);
            convB2h_kernel<<<dim3(DIMC / 32, FFD / 32), 256>>>(w2, pB2h, FFD, DIMC);
            tgemm<3, 1><<<dim3(4, 64), 256, TG_DSMEM>>>(pA2, pB, px2, b2 + DIMC, px2, 1024, 8192);
        }
    }

    add_out<<<TOK * DIMC / 4 / 256, 256>>>((float*)d_out);
}

// round 16
// speedup vs baseline: 2.5955x; 1.0396x over previous
#include <cuda_runtime.h>
#include <cuda_bf16.h>
#include <cuda_fp16.h>
#include <math.h>
#include <stdint.h>

#define DIMC 1024
#define TT   4096
#define BBAT 2
#define HH   8
#define DHH  128
#define BHC  16
#define TOK  8192
#define NHSH 4
#define NBKT 64
#define NCHK 256
#define FFD  4096

// ------------------------- scratch (device globals, no allocs) -------------
__device__ float g_x1[TOK * DIMC];
__device__ float g_x2[TOK * DIMC];
__device__ float g_qkv[TOK * 2048];
__device__ float g_v[TOK * DIMC];
__device__ float g_so[BHC * NHSH * TT * DHH];
__device__ float g_slog[BHC * NHSH * TT];
__device__ int g_st[BHC * NHSH * TT];
__device__ int g_undo[BHC * NHSH * TT];
__device__ unsigned char g_bucket[BHC * NHSH * TT];
__device__ uint4 g_Abuf1[(size_t)TOK * 3 * FFD * 2 / 16];
__device__ uint4 g_Abuf2[(size_t)TOK * 3 * FFD * 2 / 16];
__device__ uint4 g_B3[(size_t)FFD * 3 * DIMC * 2 / 16];

// ------------------------- helpers ----------------------------------------
__device__ __forceinline__ uint32_t smem_u32(const void* p) {
    uint32_t a;
    asm("{ .reg .u64 t; cvta.to.shared.u64 t, %1; cvt.u32.u64 %0, t; }" : "=r"(a) : "l"(p));
    return a;
}
__device__ __forceinline__ uint32_t swz128(uint32_t off) { return off ^ ((off >> 3) & 0x70); }

__device__ __forceinline__ void cp_async16(uint32_t so, const void* g) {
    asm volatile("cp.async.cg.shared.global [%0], [%1], 16;" :: "r"(so), "l"(g));
}
__device__ __forceinline__ void ldm_x4(uint32_t& r0, uint32_t& r1, uint32_t& r2, uint32_t& r3,
                                       uint32_t a) {
    asm volatile("ldmatrix.sync.aligned.m8n8.x4.shared.b16 {%0,%1,%2,%3}, [%4];"
                 : "=r"(r0), "=r"(r1), "=r"(r2), "=r"(r3) : "r"(a));
}
__device__ __forceinline__ void mma_bf16(float* c, uint32_t a0, uint32_t a1, uint32_t a2,
                                         uint32_t a3, uint32_t b0, uint32_t b1) {
    asm volatile(
        "mma.sync.aligned.m16n8k16.row.col.f32.bf16.bf16.f32 "
        "{%0,%1,%2,%3}, {%4,%5,%6,%7}, {%8,%9}, {%0,%1,%2,%3};"
        : "+f"(c[0]), "+f"(c[1]), "+f"(c[2]), "+f"(c[3])
        : "r"(a0), "r"(a1), "r"(a2), "r"(a3), "r"(b0), "r"(b1));
}
__device__ __forceinline__ void mma_fp16(float* c, uint32_t a0, uint32_t a1, uint32_t a2,
                                         uint32_t a3, uint32_t b0, uint32_t b1) {
    asm volatile(
        "mma.sync.aligned.m16n8k16.row.col.f32.f16.f16.f32 "
        "{%0,%1,%2,%3}, {%4,%5,%6,%7}, {%8,%9}, {%0,%1,%2,%3};"
        : "+f"(c[0]), "+f"(c[1]), "+f"(c[2]), "+f"(c[3])
        : "r"(a0), "r"(a1), "r"(a2), "r"(a3), "r"(b0), "r"(b1));
}
__device__ __forceinline__ void fma2(unsigned long long& d, unsigned long long a,
                                     unsigned long long b) {
    asm("fma.rn.f32x2 %0, %1, %2, %0;" : "+l"(d) : "l"(a), "l"(b));
}
__device__ __forceinline__ float sumf2(unsigned long long v) {
    float lo, hi;
    asm("mov.b64 {%0, %1}, %2;" : "=f"(lo), "=f"(hi) : "l"(v));
    return lo + hi;
}

// ------------------------- init: x1 = x2 = x ------------------------------
__global__ void init_xx(const float* __restrict__ x) {
    int i = blockIdx.x * blockDim.x + threadIdx.x;
    float4 v = ((const float4*)x)[i];
    ((float4*)g_x1)[i] = v;
    ((float4*)g_x2)[i] = v;
}

// ------------------------- layernorm with fused split output ---------------
template <int W3, int WH>
__global__ void ln_split(const float* __restrict__ in, const float* __restrict__ g,
                         const float* __restrict__ b, __nv_bfloat16* __restrict__ A3,
                         __half* __restrict__ A2) {
    int row = blockIdx.x;
    int tid = threadIdx.x;
    const float* p = in + (size_t)row * DIMC;
    float v[4];
    float s = 0.f, sq = 0.f;
#pragma unroll
    for (int j = 0; j < 4; j++) {
        float x = p[tid + j * 256];
        v[j] = x;
        s += x;
        sq += x * x;
    }
#pragma unroll
    for (int o = 16; o; o >>= 1) {
        s += __shfl_xor_sync(~0u, s, o);
        sq += __shfl_xor_sync(~0u, sq, o);
    }
    __shared__ float rs[8], rq[8];
    if ((tid & 31) == 0) { rs[tid >> 5] = s; rq[tid >> 5] = sq; }
    __syncthreads();
    float S = 0.f, Q = 0.f;
#pragma unroll
    for (int w = 0; w < 8; w++) { S += rs[w]; Q += rq[w]; }
    float mean = S * (1.0f / DIMC);
    float var = Q * (1.0f / DIMC) - mean * mean;
    float inv = rsqrtf(var + 1e-5f);
    size_t rb3 = (size_t)row * 3 * DIMC;
    size_t rb2 = (size_t)row * 2 * DIMC;
#pragma unroll
    for (int j = 0; j < 4; j++) {
        int c = tid + j * 256;
        float y = (v[j] - mean) * inv * g[c] + b[c];
        if (W3) {
            __nv_bfloat16 h = __float2bfloat16(y);
            __nv_bfloat16 l = __float2bfloat16(y - __bfloat162float(h));
            A3[rb3 + c] = h;
            A3[rb3 + DIMC + c] = h;
            A3[rb3 + 2 * DIMC + c] = l;
        }
        if (WH) {
            __half h = __float2half(y);
            __half l = __float2half(y - __half2float(h));
            A2[rb2 + c] = h;
            A2[rb2 + DIMC + c] = l;
        }
    }
}

// ------------------------- weight conversions ------------------------------
__global__ void convB_kernel(const float* __restrict__ W, __nv_bfloat16* __restrict__ B3,
                             int K, int N) {
    __shared__ float s[32][33];
    int tx = threadIdx.x & 31, ty = threadIdx.x >> 5;
    int n0 = blockIdx.x * 32, k0 = blockIdx.y * 32;
#pragma unroll
    for (int j = 0; j < 4; j++)
        s[ty + 8 * j][tx] = W[(size_t)(k0 + ty + 8 * j) * N + n0 + tx];
    __syncthreads();
#pragma unroll
    for (int j = 0; j < 4; j++) {
        int r = ty + 8 * j;
        int n = n0 + r;
        int k = k0 + tx;
        float x = s[tx][r];
        __nv_bfloat16 h = __float2bfloat16(x);
        __nv_bfloat16 l = __float2bfloat16(x - __bfloat162float(h));
        size_t rb = (size_t)n * 3 * K;
        B3[rb + k] = h;
        B3[rb + K + k] = l;
        B3[rb + 2 * K + k] = h;
    }
}

__global__ void convB2h_kernel(const float* __restrict__ W, __half* __restrict__ B2,
                               int K, int N) {
    __shared__ float s[32][33];
    int tx = threadIdx.x & 31, ty = threadIdx.x >> 5;
    int n0 = blockIdx.x * 32, k0 = blockIdx.y * 32;
#pragma unroll
    for (int j = 0; j < 4; j++)
        s[ty + 8 * j][tx] = W[(size_t)(k0 + ty + 8 * j) * N + n0 + tx];
    __syncthreads();
#pragma unroll
    for (int j = 0; j < 4; j++) {
        int r = ty + 8 * j;
        int n = n0 + r;
        int k = k0 + tx;
        __half h = __float2half(s[tx][r]);
        size_t rb = (size_t)n * 2 * K;
        B2[rb + k] = h;
        B2[rb + K + k] = h;
    }
}

// ------------------------- HMMA GEMM (mma.sync) ----------------------------
// Tile 128x128, BK=64, 2-stage cp.async (32KB/stage, 64KB/CTA), 2 CTAs/SM.
// Warp layout 2x4, warp tile 64x32 (acc 64 regs). FLAGS: 1=+bias, 2=+res,
// 4=exact gelu, 8=write split operand.
#define TG_STAGE 32768
#define TG_DSMEM (2 * TG_STAGE)

template <int FLAGS, int FP16>
__global__ void __launch_bounds__(256, 2) tgemm(const void* __restrict__ Av,
                                                const void* __restrict__ Bv,
                                                float* __restrict__ C,
                                                const float* __restrict__ bias,
                                                const float* __restrict__ res,
                                                int N, int K3) {
    extern __shared__ char sm_[];
    int tid = threadIdx.x, lane = tid & 31, wid = tid >> 5;
    int wm = wid >> 2, wn = wid & 3;
    int bx = blockIdx.x, by = blockIdx.y;
    const char* Ag = (const char*)Av + (size_t)(by * 128) * K3 * 2;
    const char* Bg = (const char*)Bv + (size_t)(bx * 128) * K3 * 2;
    size_t rs = (size_t)K3 * 2;
    int nk = K3 >> 6;
    uint32_t sbase = smem_u32(sm_);

    auto load_stage = [&](int kc, int s) {
        uint32_t sb = sbase + s * TG_STAGE;
#pragma unroll
        for (int j = 0; j < 8; j++) {
            int idx = tid + j * 256;           // 0..2047
            int half = idx >> 10;              // 0:A 1:B
            int r = (idx >> 3) & 127, seg = idx & 7;
            const char* g = (half ? Bg : Ag) + (size_t)r * rs + (size_t)kc * 128 + seg * 16;
            cp_async16(sb + half * 16384 + swz128(r * 128 + seg * 16), g);
        }
        asm volatile("cp.async.commit_group;");
    };

    float acc[4][4][4];
#pragma unroll
    for (int a = 0; a < 4; a++)
#pragma unroll
        for (int b = 0; b < 4; b++)
#pragma unroll
            for (int c = 0; c < 4; c++) acc[a][b][c] = 0.f;

    load_stage(0, 0);

    int mat = lane >> 3, rin = lane & 7;
    for (int i = 0; i < nk; i++) {
        __syncthreads();
        if (i + 1 < nk) load_stage(i + 1, (i + 1) & 1);
        if (i + 1 < nk) asm volatile("cp.async.wait_group 1;");
        else            asm volatile("cp.async.wait_group 0;");
        __syncthreads();

        uint32_t sa = sbase + (i & 1) * TG_STAGE;
        uint32_t sbB = sa + 16384;
#pragma unroll
        for (int ks = 0; ks < 4; ks++) {
            uint32_t af[4][4], bf[4][2];
#pragma unroll
            for (int mt = 0; mt < 4; mt++) {
                int row = wm * 64 + mt * 16 + (mat & 1) * 8 + rin;
                int kb = 2 * ks + (mat >> 1);
                ldm_x4(af[mt][0], af[mt][1], af[mt][2], af[mt][3],
                       sa + swz128(row * 128 + kb * 16));
            }
#pragma unroll
            for (int g = 0; g < 2; g++) {
                int nt = 2 * g + (mat >> 1);
                int n = wn * 32 + nt * 8 + rin;
                int kb = 2 * ks + (mat & 1);
                uint32_t b0, b1, b2, b3;
                ldm_x4(b0, b1, b2, b3, sbB + swz128(n * 128 + kb * 16));
                bf[2 * g][0] = b0; bf[2 * g][1] = b1;
                bf[2 * g + 1][0] = b2; bf[2 * g + 1][1] = b3;
            }
#pragma unroll
            for (int mt = 0; mt < 4; mt++)
#pragma unroll
                for (int nt = 0; nt < 4; nt++) {
                    if (FP16)
                        mma_fp16(acc[mt][nt], af[mt][0], af[mt][1], af[mt][2], af[mt][3],
                                 bf[nt][0], bf[nt][1]);
                    else
                        mma_bf16(acc[mt][nt], af[mt][0], af[mt][1], af[mt][2], af[mt][3],
                                 bf[nt][0], bf[nt][1]);
                }
        }
    }

#pragma unroll
    for (int mt = 0; mt < 4; mt++) {
        int gr0 = by * 128 + wm * 64 + mt * 16 + (lane >> 2);
#pragma unroll
        for (int nt = 0; nt < 4; nt++) {
            int gc = bx * 128 + wn * 32 + nt * 8 + (lane & 3) * 2;
            float v0 = acc[mt][nt][0], v1 = acc[mt][nt][1];
            float v2 = acc[mt][nt][2], v3 = acc[mt][nt][3];
            if (FLAGS & 1) {
                float b0 = bias[gc], b1 = bias[gc + 1];
                v0 += b0; v1 += b1; v2 += b0; v3 += b1;
            }
            if (FLAGS & 4) {
                v0 = 0.5f * v0 * (1.0f + erff(v0 * 0.70710678118654752f));
                v1 = 0.5f * v1 * (1.0f + erff(v1 * 0.70710678118654752f));
                v2 = 0.5f * v2 * (1.0f + erff(v2 * 0.70710678118654752f));
                v3 = 0.5f * v3 * (1.0f + erff(v3 * 0.70710678118654752f));
            }
            if (FLAGS & 8) {
                if (!FP16) {
                    __nv_bfloat16* O = (__nv_bfloat16*)C;
                    size_t r0 = (size_t)gr0 * 3 * N, r1 = (size_t)(gr0 + 8) * 3 * N;
                    __nv_bfloat16 h0 = __float2bfloat16(v0);
                    __nv_bfloat16 h1 = __float2bfloat16(v1);
                    __nv_bfloat16 h2 = __float2bfloat16(v2);
                    __nv_bfloat16 h3 = __float2bfloat16(v3);
                    __nv_bfloat162 hp0 = {h0, h1}, hp1 = {h2, h3};
                    __nv_bfloat162 lp0 = {__float2bfloat16(v0 - __bfloat162float(h0)),
                                          __float2bfloat16(v1 - __bfloat162float(h1))};
                    __nv_bfloat162 lp1 = {__float2bfloat16(v2 - __bfloat162float(h2)),
                                          __float2bfloat16(v3 - __bfloat162float(h3))};
                    *(__nv_bfloat162*)(O + r0 + gc) = hp0;
                    *(__nv_bfloat162*)(O + r0 + N + gc) = hp0;
                    *(__nv_bfloat162*)(O + r0 + 2 * N + gc) = lp0;
                    *(__nv_bfloat162*)(O + r1 + gc) = hp1;
                    *(__nv_bfloat162*)(O + r1 + N + gc) = hp1;
                    *(__nv_bfloat162*)(O + r1 + 2 * N + gc) = lp1;
                } else {
                    __half* O = (__half*)C;
                    size_t r0 = (size_t)gr0 * 2 * N, r1 = (size_t)(gr0 + 8) * 2 * N;
                    __half h0 = __float2half(v0), h1 = __float2half(v1);
                    __half h2 = __float2half(v2), h3 = __float2half(v3);
                    __half2 hp0 = {h0, h1}, hp1 = {h2, h3};
                    __half2 lp0 = {__float2half(v0 - __half2float(h0)),
                                   __float2half(v1 - __half2float(h1))};
                    __half2 lp1 = {__float2half(v2 - __half2float(h2)),
                                   __float2half(v3 - __half2float(h3))};
                    *(__half2*)(O + r0 + gc) = hp0;
                    *(__half2*)(O + r0 + N + gc) = lp0;
                    *(__half2*)(O + r1 + gc) = hp1;
                    *(__half2*)(O + r1 + N + gc) = lp1;
                }
            } else {
                if (FLAGS & 2) {
                    const float* r0p = res + (size_t)gr0 * N + gc;
                    const float* r1p = res + (size_t)(gr0 + 8) * N + gc;
                    v0 += r0p[0]; v1 += r0p[1]; v2 += r1p[0]; v3 += r1p[1];
                }
                float2 o0 = {v0, v1}, o1 = {v2, v3};
                *(float2*)(C + (size_t)gr0 * N + gc) = o0;
                *(float2*)(C + (size_t)(gr0 + 8) * N + gc) = o1;
            }
        }
    }
}

// ------------------------- LSH hashing (strided qk) ------------------------
__global__ void hash_kernel(const float* __restrict__ qk, int qstride,
                            const float* __restrict__ rot,
                            unsigned char* __restrict__ bucket) {
    __shared__ float srow[8][128];
    int warp = threadIdx.x >> 5, lane = threadIdx.x & 31;
    int rid = blockIdx.x * 8 + warp;
    int bh = rid >> 12, t = rid & 4095;
    int b = bh >> 3, h = bh & 7;
    const float* qp = qk + (size_t)(b * TT + t) * qstride + h * DHH;
#pragma unroll
    for (int j = 0; j < 4; j++) srow[warp][lane + j * 32] = qp[lane + j * 32];
    __syncwarp();
#pragma unroll
    for (int hh = 0; hh < 4; hh++) {
        float acc = 0.f;
#pragma unroll 8
        for (int f = 0; f < 128; f++)
            acc = fmaf(srow[warp][f], rot[f * 128 + hh * 32 + lane], acc);
        float val = fmaxf(acc, -acc);
        int idx = (acc >= -acc) ? lane : 32 + lane;
#pragma unroll
        for (int o = 16; o; o >>= 1) {
            float ov = __shfl_down_sync(~0u, val, o);
            int oi = __shfl_down_sync(~0u, idx, o);
            if (ov > val || (ov == val && oi < idx)) { val = ov; idx = oi; }
        }
        if (lane == 0) bucket[((size_t)bh * 4 + hh) * TT + t] = (unsigned char)idx;
    }
}

// ------------------------- stable counting sort per (bh, hash) ------------
__global__ void sort_kernel(const unsigned char* __restrict__ bucket,
                            int* __restrict__ st, int* __restrict__ undo) {
    __shared__ unsigned char sb[4096];
    __shared__ unsigned short hist[64 * 257];
    __shared__ int base[65];
    __shared__ int tot[64];
    int blk = blockIdx.x;
    int tid = threadIdx.x;
    const unsigned char* bp = bucket + (size_t)blk * TT;
    for (int i = tid; i < 4096; i += 256) sb[i] = bp[i];
    for (int i = tid; i < 64 * 257; i += 256) hist[i] = 0;
    __syncthreads();
#pragma unroll
    for (int j = 0; j < 16; j++) {
        int t = tid * 16 + j;
        int b = sb[t];
        hist[b * 257 + tid]++;
    }
    __syncthreads();
    if (tid < 64) {
        unsigned int run = 0;
        int b = tid;
        for (int th = 0; th < 256; th++) {
            unsigned short tmp = hist[b * 257 + th];
            hist[b * 257 + th] = (unsigned short)run;
            run += tmp;
        }
        tot[b] = (int)run;
    }
    __syncthreads();
    if (tid == 0) {
        base[0] = 0;
        for (int b = 0; b < 64; b++) base[b + 1] = base[b] + tot[b];
    }
    __syncthreads();
#pragma unroll
    for (int j = 0; j < 16; j++) {
        int t = tid * 16 + j;
        int b = sb[t];
        int pos = base[b] + hist[b * 257 + tid];
        hist[b * 257 + tid]++;
        st[(size_t)blk * TT + pos] = t;
        undo[(size_t)blk * TT + t] = pos;
    }
}

// ------------------------- chunked LSH attention (512 thr, smem V) --------
#define SKW 134
#define ATTN_SMEM ((128 * SKW + 64 * 132 + 128) * 4 + 128 * 4)
__global__ void __launch_bounds__(512) attn_kernel(const float* __restrict__ qkb, int qstride,
                                                   const float* __restrict__ vb, int vstride,
                                                   const int* __restrict__ st,
                                                   float* __restrict__ so,
                                                   float* __restrict__ slog) {
    extern __shared__ float sm[];
    float* s_k = sm;
    float* s_p = s_k + 128 * SKW;
    float* s_rn = s_p + 64 * 132;
    int* s_pk = (int*)(s_rn + 128);
    int tid = threadIdx.x;
    int bh = blockIdx.x >> 8;
    int c = blockIdx.x & 255;
    int prev = (c + 255) & 255;
    int b = bh >> 3, h = bh & 7;
    const int* stb = st + (size_t)bh * (NHSH * TT);
    if (tid < 64) s_pk[tid] = stb[c * 64 + tid];
    else if (tid < 128) s_pk[tid] = stb[prev * 64 + (tid - 64)];
    __syncthreads();
#pragma unroll
    for (int rep = 0; rep < 8; rep++) {
        int idx = tid + rep * 512;
        int j = idx >> 5, d4 = idx & 31;
        const float* kp = qkb + (size_t)(b * TT + s_pk[j]) * qstride + h * DHH + d4 * 4;
        float4 kv = *(const float4*)kp;
        float* dst = s_k + j * SKW + d4 * 4;
        *(float2*)(dst) = make_float2(kv.x, kv.y);
        *(float2*)(dst + 2) = make_float2(kv.z, kv.w);
    }
    __syncthreads();
    if (tid < 128) {
        float sq = 0.f;
        const float* kr = s_k + tid * SKW;
#pragma unroll 8
        for (int d = 0; d < 128; d += 2) {
            float2 x = *(const float2*)(kr + d);
            sq += x.x * x.x + x.y * x.y;
        }
        s_rn[tid] = 1.0f / fmaxf(sqrtf(sq), 1e-12f);
    }
    __syncthreads();
    int lane = tid & 31, w = tid >> 5;
    const float SC = 0.08838834764831845f;
    for (int p2 = 0; p2 < 2; p2++) {
        int i0 = w * 4 + p2 * 2;
        unsigned long long a0[4] = {0, 0, 0, 0}, a1[4] = {0, 0, 0, 0};
        const float* k0 = s_k + i0 * SKW;
        const float* k1 = k0 + SKW;
        const float* kvb = s_k + lane * SKW;
#pragma unroll 4
        for (int d = 0; d < 128; d += 2) {
            unsigned long long q0 = *(const unsigned long long*)(k0 + d);
            unsigned long long q1 = *(const unsigned long long*)(k1 + d);
#pragma unroll
            for (int cc = 0; cc < 4; cc++) {
                unsigned long long kv =
                    *(const unsigned long long*)(kvb + cc * 32 * SKW + d);
                fma2(a0[cc], q0, kv);
                fma2(a1[cc], q1, kv);
            }
        }
        int pq0 = s_pk[i0], pq1 = s_pk[i0 + 1];
#pragma unroll
        for (int cc = 0; cc < 4; cc++) {
            int j = lane + 32 * cc;
            float rn = s_rn[j];
            int pkj = s_pk[j];
            float d0 = sumf2(a0[cc]);
            float d1 = sumf2(a1[cc]);
            s_p[i0 * 132 + j] = (pq0 == pkj) ? -5e4f : d0 * rn * SC;
            s_p[(i0 + 1) * 132 + j] = (pq1 == pkj) ? -5e4f : d1 * rn * SC;
        }
    }
    __syncthreads();
#pragma unroll
    for (int rep = 0; rep < 8; rep++) {
        int idx = tid + rep * 512;
        int j = idx >> 5, d4 = idx & 31;
        const float* vp = vb + (size_t)(b * TT + s_pk[j]) * vstride + h * DHH + d4 * 4;
        float4 vv = *(const float4*)vp;
        s_k[(d4 * 4 + 0) * SKW + j] = vv.x;
        s_k[(d4 * 4 + 1) * SKW + j] = vv.y;
        s_k[(d4 * 4 + 2) * SKW + j] = vv.z;
        s_k[(d4 * 4 + 3) * SKW + j] = vv.w;
    }
    for (int rr = 0; rr < 4; rr++) {
        int i = w * 4 + rr;
        float vv[4];
#pragma unroll
        for (int cc = 0; cc < 4; cc++) vv[cc] = s_p[i * 132 + lane + 32 * cc];
        float m = fmaxf(fmaxf(vv[0], vv[1]), fmaxf(vv[2], vv[3]));
#pragma unroll
        for (int o = 16; o; o >>= 1) m = fmaxf(m, __shfl_xor_sync(~0u, m, o));
        float sum = 0.f;
#pragma unroll
        for (int cc = 0; cc < 4; cc++) {
            vv[cc] = expf(vv[cc] - m);
            sum += vv[cc];
        }
#pragma unroll
        for (int o = 16; o; o >>= 1) sum += __shfl_xor_sync(~0u, sum, o);
        float lse = m + logf(sum);
        float isum = 1.0f / sum;
#pragma unroll
        for (int cc = 0; cc < 4; cc++) s_p[i * 132 + lane + 32 * cc] = vv[cc] * isum;
        if (lane == 0) slog[(size_t)bh * (NHSH * TT) + c * 64 + i] = lse;
    }
    __syncthreads();
    unsigned long long acc[4][4];
#pragma unroll
    for (int ii = 0; ii < 4; ii++)
#pragma unroll
        for (int dd = 0; dd < 4; dd++) acc[ii][dd] = 0ull;
    for (int j = 0; j < 128; j += 2) {
        unsigned long long vv0 = *(const unsigned long long*)(s_k + (size_t)lane * SKW + j);
        unsigned long long vv1 = *(const unsigned long long*)(s_k + (size_t)(lane + 32) * SKW + j);
        unsigned long long vv2 = *(const unsigned long long*)(s_k + (size_t)(lane + 64) * SKW + j);
        unsigned long long vv3 = *(const unsigned long long*)(s_k + (size_t)(lane + 96) * SKW + j);
#pragma unroll
        for (int ii = 0; ii < 4; ii++) {
            unsigned long long pp =
                *(const unsigned long long*)(s_p + (w * 4 + ii) * 132 + j);
            fma2(acc[ii][0], pp, vv0);
            fma2(acc[ii][1], pp, vv1);
            fma2(acc[ii][2], pp, vv2);
            fma2(acc[ii][3], pp, vv3);
        }
    }
#pragma unroll
    for (int ii = 0; ii < 4; ii++) {
        size_t base = ((size_t)bh * (NHSH * TT) + c * 64 + w * 4 + ii) * 128;
        so[base + lane] = sumf2(acc[ii][0]);
        so[base + lane + 32] = sumf2(acc[ii][1]);
        so[base + lane + 64] = sumf2(acc[ii][2]);
        so[base + lane + 96] = sumf2(acc[ii][3]);
    }
}

// ------------------------- combine hash rounds + fused split ---------------
template <int FP16>
__global__ void combine_split(const float* __restrict__ so, const float* __restrict__ slog,
                              const int* __restrict__ undo, void* __restrict__ Aout) {
    int warp = threadIdx.x >> 5, lane = threadIdx.x & 31;
    int rid = blockIdx.x * 8 + warp;
    int bh = rid >> 12, t = rid & 4095;
    int b = bh >> 3, h = bh & 7;
    int u[4];
    float lg[4];
#pragma unroll
    for (int r = 0; r < 4; r++) {
        u[r] = undo[((size_t)bh * 4 + r) * TT + t];
        lg[r] = slog[(size_t)bh * (NHSH * TT) + r * TT + u[r]];
    }
    float m = fmaxf(fmaxf(lg[0], lg[1]), fmaxf(lg[2], lg[3]));
    float e[4];
    float s = 0.f;
#pragma unroll
    for (int r = 0; r < 4; r++) {
        e[r] = expf(lg[r] - m);
        s += e[r];
    }
    float is = 1.0f / s;
    float a[4] = {0, 0, 0, 0};
#pragma unroll
    for (int r = 0; r < 4; r++) {
        const float* op = so + ((size_t)bh * (NHSH * TT) + r * TT + u[r]) * 128;
        float pr = e[r] * is;
        a[0] = fmaf(pr, op[lane], a[0]);
        a[1] = fmaf(pr, op[lane + 32], a[1]);
        a[2] = fmaf(pr, op[lane + 64], a[2]);
        a[3] = fmaf(pr, op[lane + 96], a[3]);
    }
    size_t mrow = (size_t)(b * TT + t);
#pragma unroll
    for (int q = 0; q < 4; q++) {
        int col = h * DHH + lane + 32 * q;
        if (!FP16) {
            __nv_bfloat16* A3 = (__nv_bfloat16*)Aout;
            size_t rb = mrow * 3 * DIMC;
            __nv_bfloat16 hh = __float2bfloat16(a[q]);
            __nv_bfloat16 ll = __float2bfloat16(a[q] - __bfloat162float(hh));
            A3[rb + col] = hh;
            A3[rb + DIMC + col] = hh;
            A3[rb + 2 * DIMC + col] = ll;
        } else {
            __half* A2 = (__half*)Aout;
            size_t rb = mrow * 2 * DIMC;
            __half hh = __float2half(a[q]);
            __half ll = __float2half(a[q] - __half2float(hh));
            A2[rb + col] = hh;
            A2[rb + DIMC + col] = ll;
        }
    }
}

// ------------------------- final y1 + y2 ----------------------------------
__global__ void add_out(float* __restrict__ out) {
    int i = blockIdx.x * blockDim.x + threadIdx.x;
    float4 a = ((float4*)g_x1)[i];
    float4 b = ((float4*)g_x2)[i];
    float4 o;
    o.x = a.x + b.x; o.y = a.y + b.y; o.z = a.z + b.z; o.w = a.w + b.w;
    ((float4*)out)[i] = o;
}

// ------------------------- launch -----------------------------------------
extern "C" void kernel_launch(void* const* d_in, const int* in_sizes, int n_in,
                              void* d_out, int out_size) {
    const float* x = (const float*)d_in[0];
    const float* ln1g = (const float*)d_in[1];
    const float* ln1b = (const float*)d_in[2];
    const float* Wqk = (const float*)d_in[3];
    const float* Wv = (const float*)d_in[4];
    const float* Wo = (const float*)d_in[5];
    const float* bo = (const float*)d_in[6];
    const float* ln2g = (const float*)d_in[7];
    const float* ln2b = (const float*)d_in[8];
    const float* W1 = (const float*)d_in[9];
    const float* b1 = (const float*)d_in[10];
    const float* W2 = (const float*)d_in[11];
    const float* b2 = (const float*)d_in[12];
    const float* rot = (const float*)d_in[13];

    float *px1, *px2, *pqkv, *pv, *pso, *pslog;
    int *pst, *pundo;
    unsigned char* pbkt;
    void *pA1, *pA2, *pB;
    cudaGetSymbolAddress((void**)&px1, g_x1);
    cudaGetSymbolAddress((void**)&px2, g_x2);
    cudaGetSymbolAddress((void**)&pqkv, g_qkv);
    cudaGetSymbolAddress((void**)&pv, g_v);
    cudaGetSymbolAddress((void**)&pso, g_so);
    cudaGetSymbolAddress((void**)&pslog, g_slog);
    cudaGetSymbolAddress((void**)&pst, g_st);
    cudaGetSymbolAddress((void**)&pundo, g_undo);
    cudaGetSymbolAddress((void**)&pbkt, g_bucket);
    cudaGetSymbolAddress(&pA1, g_Abuf1);
    cudaGetSymbolAddress(&pA2, g_Abuf2);
    cudaGetSymbolAddress(&pB, g_B3);
    __nv_bfloat16* pB3 = (__nv_bfloat16*)pB;
    __half* pB2h = (__half*)pB;

    cudaFuncSetAttribute(attn_kernel, cudaFuncAttributeMaxDynamicSharedMemorySize, ATTN_SMEM);
    cudaFuncSetAttribute(tgemm<0, 0>, cudaFuncAttributeMaxDynamicSharedMemorySize, TG_DSMEM);
    cudaFuncSetAttribute(tgemm<3, 0>, cudaFuncAttributeMaxDynamicSharedMemorySize, TG_DSMEM);
    cudaFuncSetAttribute(tgemm<13, 0>, cudaFuncAttributeMaxDynamicSharedMemorySize, TG_DSMEM);
    cudaFuncSetAttribute(tgemm<0, 1>, cudaFuncAttributeMaxDynamicSharedMemorySize, TG_DSMEM);
    cudaFuncSetAttribute(tgemm<3, 1>, cudaFuncAttributeMaxDynamicSharedMemorySize, TG_DSMEM);
    cudaFuncSetAttribute(tgemm<13, 1>, cudaFuncAttributeMaxDynamicSharedMemorySize, TG_DSMEM);

    init_xx<<<TOK * DIMC / 4 / 256, 256>>>(x);

    for (int L = 0; L < 2; L++) {
        const float* wqk = Wqk + (size_t)L * DIMC * DIMC;
        const float* wv = Wv + (size_t)L * DIMC * DIMC;
        const float* wo = Wo + (size_t)L * DIMC * DIMC;
        const float* w1 = W1 + (size_t)L * DIMC * FFD;
        const float* w2 = W2 + (size_t)L * FFD * DIMC;
        const float* rl = rot + (size_t)L * DHH * NHSH * (NBKT / 2);

        if (L == 0) {
            ln_split<1, 0><<<TOK, 256>>>(px2, ln1g, ln1b,
                                         (__nv_bfloat16*)pA1, nullptr);
            convB_kernel<<<dim3(DIMC / 32, DIMC / 32), 256>>>(wqk, pB3, DIMC, DIMC);
            convB_kernel<<<dim3(DIMC / 32, DIMC / 32), 256>>>(
                wv, pB3 + (size_t)1024 * 3 * DIMC, DIMC, DIMC);
            tgemm<0, 0><<<dim3(16, 64), 256, TG_DSMEM>>>(pA1, pB, pqkv, nullptr, nullptr, 2048, 3072);

            hash_kernel<<<TOK, 256>>>(pqkv, 2048, rl, pbkt);
            sort_kernel<<<64, 256>>>(pbkt, pst, pundo);
            attn_kernel<<<BHC * NCHK, 512, ATTN_SMEM>>>(pqkv, 2048, pqkv + 1024, 2048,
                                                        pst, pso, pslog);
            combine_split<0><<<TOK, 256>>>(pso, pslog, pundo, pA1);

            convB_kernel<<<dim3(DIMC / 32, DIMC / 32), 256>>>(wo, pB3, DIMC, DIMC);
            tgemm<3, 0><<<dim3(8, 64), 256, TG_DSMEM>>>(pA1, pB, px1, bo, px1, 1024, 3072);

            ln_split<1, 0><<<TOK, 256>>>(px1, ln2g, ln2b,
                                         (__nv_bfloat16*)pA1, nullptr);
            convB_kernel<<<dim3(FFD / 32, DIMC / 32), 256>>>(w1, pB3, DIMC, FFD);
            tgemm<13, 0><<<dim3(32, 64), 256, TG_DSMEM>>>(pA1, pB, (float*)pA2, b1, nullptr, 4096, 3072);
            convB_kernel<<<dim3(DIMC / 32, FFD / 32), 256>>>(w2, pB3, FFD, DIMC);
            tgemm<3, 0><<<dim3(8, 64), 256, TG_DSMEM>>>(pA2, pB, px2, b2, px2, 1024, 12288);
        } else {
            ln_split<1, 1><<<TOK, 256>>>(px2, ln1g + DIMC, ln1b + DIMC,
                                         (__nv_bfloat16*)pA1, (__half*)pA2);
            convB_kernel<<<dim3(DIMC / 32, DIMC / 32), 256>>>(wqk, pB3, DIMC, DIMC);
            tgemm<0, 0><<<dim3(8, 64), 256, TG_DSMEM>>>(pA1, pB, pqkv, nullptr, nullptr, 1024, 3072);
            convB2h_kernel<<<dim3(DIMC / 32, DIMC / 32), 256>>>(wv, pB2h, DIMC, DIMC);
            tgemm<0, 1><<<dim3(8, 64), 256, TG_DSMEM>>>(pA2, pB, pv, nullptr, nullptr, 1024, 2048);

            hash_kernel<<<TOK, 256>>>(pqkv, 1024, rl, pbkt);
            sort_kernel<<<64, 256>>>(pbkt, pst, pundo);
            attn_kernel<<<BHC * NCHK, 512, ATTN_SMEM>>>(pqkv, 1024, pv, 1024,
                                                        pst, pso, pslog);
            combine_split<1><<<TOK, 256>>>(pso, pslog, pundo, pA1);

            convB2h_kernel<<<dim3(DIMC / 32, DIMC / 32), 256>>>(wo, pB2h, DIMC, DIMC);
            tgemm<3, 1><<<dim3(8, 64), 256, TG_DSMEM>>>(pA1, pB, px1, bo + DIMC, px1, 1024, 2048);

            ln_split<0, 1><<<TOK, 256>>>(px1, ln2g + DIMC, ln2b + DIMC,
                                         nullptr, (__half*)pA1);
            convB2h_kernel<<<dim3(FFD / 32, DIMC / 32), 256>>>(w1, pB2h, DIMC, FFD);
            tgemm<13, 1><<<dim3(32, 64), 256, TG_DSMEM>>>(pA1, pB, (float*)pA2, b1 + FFD, nullptr, 4096, 2048);
            convB2h_kernel<<<dim3(DIMC / 32, FFD / 32), 256>>>(w2, pB2h, FFD, DIMC);
            tgemm<3, 1><<<dim3(8, 64), 256, TG_DSMEM>>>(pA2, pB, px2, b2 + DIMC, px2, 1024, 8192);
        }
    }

    add_out<<<TOK * DIMC / 4 / 256, 256>>>((float*)d_out);
}